// round 4
// baseline (speedup 1.0000x reference)
#include <cuda_runtime.h>
#include <math_constants.h>

#define BATCH 2
#define CH    128
#define NSP   4096
#define GROUPS 8
#define TN    64
#define TM    128
#define EPSV  1e-5f

// ---------------- scratch (static __device__, allocation-free) ----------------
__device__ float g_Q [BATCH*CH*NSP];     // [b][c][n]
__device__ float g_K [BATCH*CH*NSP];     // [b][c][n]
__device__ float g_Vt[BATCH*NSP*CH];     // [b][m][c]  (pre-transposed V)
__device__ float g_H [BATCH*NSP*CH];     // [b][n][c]
__device__ float g_Y [BATCH*CH*NSP];     // [b][c][n]  (pre-norm residual sum)
__device__ float g_part [BATCH*64*GROUPS*2];
__device__ float g_stats[BATCH*GROUPS*2];

// ---------------- f32x2 helpers (Blackwell packed fp32) ----------------
__device__ __forceinline__ unsigned long long pk2(float x, float y){
    unsigned long long r; asm("mov.b64 %0, {%1,%2};" : "=l"(r) : "f"(x), "f"(y)); return r;
}
__device__ __forceinline__ void upk2(unsigned long long v, float& x, float& y){
    asm("mov.b64 {%0,%1}, %2;" : "=f"(x), "=f"(y) : "l"(v));
}
__device__ __forceinline__ void ffma2(unsigned long long& d, unsigned long long a, unsigned long long b){
    asm("fma.rn.f32x2 %0, %1, %2, %0;" : "+l"(d) : "l"(a), "l"(b));
}
__device__ __forceinline__ unsigned long long fmul2(unsigned long long a, unsigned long long b){
    unsigned long long d; asm("mul.rn.f32x2 %0, %1, %2;" : "=l"(d) : "l"(a), "l"(b)); return d;
}

// ============================================================================
// K1: Q/K/V projections.  out[o][n] = sum_c W[o][c] * x[b][c][n]
// grid (64 n-tiles, B, 3 mats). V is written transposed [m][c].
// smem: Wt [128][130] + Xs/stage region (8320 floats)
// ============================================================================
__global__ __launch_bounds__(256) void k_qkv(const float* __restrict__ x,
                                             const float* __restrict__ Wq,
                                             const float* __restrict__ Wk,
                                             const float* __restrict__ Wv)
{
    extern __shared__ float sm[];
    float* Wt = sm;               // [c][130]
    float* Xs = sm + 128*130;     // [c][64] during compute; [o][65] staging after

    const int n0  = blockIdx.x * TN;
    const int b   = blockIdx.y;
    const int z   = blockIdx.z;
    const float* W = (z == 0) ? Wq : ((z == 1) ? Wk : Wv);

    const int tid = threadIdx.x;
    const int tx  = tid & 15;
    const int ty  = tid >> 4;

    // W transposed into smem: Wt[c][o]
    for (int idx = tid; idx < 128*64; idx += 256){
        int o  = idx >> 6;
        int cq = (idx & 63) << 1;
        float2 w = *(const float2*)(W + o*128 + cq);
        Wt[ cq   *130 + o] = w.x;
        Wt[(cq+1)*130 + o] = w.y;
    }
    // X tile [c][64]
    const float* xb = x + (size_t)b*CH*NSP + n0;
    for (int idx = tid; idx < 128*16; idx += 256){
        int c = idx >> 4, u = (idx & 15) << 2;
        *(float4*)(Xs + c*64 + u) = *(const float4*)(xb + c*NSP + u);
    }
    __syncthreads();

    unsigned long long acc[4][4];
    #pragma unroll
    for (int i = 0; i < 4; i++)
        #pragma unroll
        for (int j = 0; j < 4; j++) acc[i][j] = 0ull;

    #pragma unroll 4
    for (int c = 0; c < 128; c++){
        unsigned long long wv[4]; float xn[4];
        #pragma unroll
        for (int j = 0; j < 4; j++)
            wv[j] = *(const unsigned long long*)(Wt + c*130 + 2*tx + 32*j);
        #pragma unroll
        for (int i = 0; i < 4; i++) xn[i] = Xs[c*64 + ty + 16*i];
        #pragma unroll
        for (int i = 0; i < 4; i++){
            unsigned long long xd = pk2(xn[i], xn[i]);
            #pragma unroll
            for (int j = 0; j < 4; j++) ffma2(acc[i][j], wv[j], xd);
        }
    }
    __syncthreads();

    // stage [o][65]
    float* St = Xs;
    #pragma unroll
    for (int i = 0; i < 4; i++)
        #pragma unroll
        for (int j = 0; j < 4; j++){
            float a, bv; upk2(acc[i][j], a, bv);
            int o = 2*tx + 32*j, n = ty + 16*i;
            St[ o   *65 + n] = a;
            St[(o+1)*65 + n] = bv;
        }
    __syncthreads();

    if (z < 2){
        float* out = (z == 0 ? g_Q : g_K) + (size_t)b*CH*NSP + n0;
        for (int k = 0; k < 32; k++){
            int e = k*256 + tid; int o = e >> 6, n = e & 63;
            out[o*NSP + n] = St[o*65 + n];
        }
    } else {
        float* out = g_Vt + (size_t)b*NSP*CH + (size_t)n0*CH;
        for (int k = 0; k < 32; k++){
            int e = k*256 + tid; int n = e >> 7, o = e & 127;
            out[n*CH + o] = St[o*65 + n];
        }
    }
}

// ============================================================================
// K2: flash attention.  CTA = (64 queries, b). Online softmax over 32 key
// tiles of 128.  S[n][m] = sum_c Q[c][n]K[c][m];  O[n][c] += P[n][m]Vt[m][c].
// smem: QS[128][64] KS[128][128] VT[128][132] PS[64][130]
// ============================================================================
__global__ __launch_bounds__(256) void k_attn()
{
    extern __shared__ float sm[];
    float* QS = sm;                 // 8192
    float* KS = QS + 128*64;        // 16384
    float* VT = KS + 128*128;       // 16896
    float* PS = VT + 128*132;       // 8320 (also staging for H)

    const int n0 = blockIdx.x * TN;
    const int b  = blockIdx.y;
    const int tid = threadIdx.x;
    const int tx  = tid & 15;
    const int ty  = tid >> 4;

    const float* Qb = g_Q  + (size_t)b*CH*NSP + n0;
    const float* Kb = g_K  + (size_t)b*CH*NSP;
    const float* Vb = g_Vt + (size_t)b*NSP*CH;

    for (int idx = tid; idx < 128*16; idx += 256){
        int c = idx >> 4, u = (idx & 15) << 2;
        *(float4*)(QS + c*64 + u) = *(const float4*)(Qb + c*NSP + u);
    }

    unsigned long long oacc[4][4];
    #pragma unroll
    for (int i = 0; i < 4; i++)
        #pragma unroll
        for (int j = 0; j < 4; j++) oacc[i][j] = 0ull;
    float mrow[4] = {-CUDART_INF_F, -CUDART_INF_F, -CUDART_INF_F, -CUDART_INF_F};
    float lrow[4] = {0.f, 0.f, 0.f, 0.f};

    for (int m0 = 0; m0 < NSP; m0 += TM){
        __syncthreads();   // covers QS fill (1st iter) and prior O-accum reads of KS/VT
        for (int idx = tid; idx < 128*32; idx += 256){
            int c = idx >> 5, u = (idx & 31) << 2;
            *(float4*)(KS + c*128 + u) = *(const float4*)(Kb + c*NSP + m0 + u);
        }
        for (int idx = tid; idx < 128*32; idx += 256){
            int m = idx >> 5, u = (idx & 31) << 2;
            *(float4*)(VT + m*132 + u) = *(const float4*)(Vb + (size_t)(m0+m)*CH + u);
        }
        __syncthreads();

        // ---- S = Q^T K (f32x2 over m-pairs) ----
        unsigned long long s[4][4];
        #pragma unroll
        for (int i = 0; i < 4; i++)
            #pragma unroll
            for (int j = 0; j < 4; j++) s[i][j] = 0ull;

        #pragma unroll 2
        for (int c = 0; c < 128; c++){
            unsigned long long kv[4]; float qv[4];
            #pragma unroll
            for (int j = 0; j < 4; j++)
                kv[j] = *(const unsigned long long*)(KS + c*128 + 2*tx + 32*j);
            #pragma unroll
            for (int i = 0; i < 4; i++) qv[i] = QS[c*64 + ty + 16*i];
            #pragma unroll
            for (int i = 0; i < 4; i++){
                unsigned long long qd = pk2(qv[i], qv[i]);
                #pragma unroll
                for (int j = 0; j < 4; j++) ffma2(s[i][j], kv[j], qd);
            }
        }

        // ---- online softmax per row ----
        #pragma unroll
        for (int i = 0; i < 4; i++){
            float p[8];
            #pragma unroll
            for (int j = 0; j < 4; j++) upk2(s[i][j], p[2*j], p[2*j+1]);
            float mx = p[0];
            #pragma unroll
            for (int j = 1; j < 8; j++) mx = fmaxf(mx, p[j]);
            #pragma unroll
            for (int d = 1; d < 16; d <<= 1) mx = fmaxf(mx, __shfl_xor_sync(0xffffffffu, mx, d));
            float mnew = fmaxf(mrow[i], mx);
            float al   = __expf(mrow[i] - mnew);
            mrow[i]    = mnew;
            float sum = 0.f;
            #pragma unroll
            for (int j = 0; j < 8; j++){ p[j] = __expf(p[j] - mnew); sum += p[j]; }
            int nrow = ty + 16*i;
            #pragma unroll
            for (int j = 0; j < 4; j++)
                *(float2*)(PS + nrow*130 + 2*tx + 32*j) = make_float2(p[2*j], p[2*j+1]);
            #pragma unroll
            for (int d = 1; d < 16; d <<= 1) sum += __shfl_xor_sync(0xffffffffu, sum, d);
            lrow[i] = lrow[i]*al + sum;
            unsigned long long ad = pk2(al, al);
            #pragma unroll
            for (int j = 0; j < 4; j++) oacc[i][j] = fmul2(oacc[i][j], ad);
        }
        __syncthreads();

        // ---- O += P Vt (f32x2 over c-pairs) ----
        #pragma unroll 2
        for (int m = 0; m < 128; m++){
            unsigned long long vv[4]; float pv[4];
            #pragma unroll
            for (int j = 0; j < 4; j++)
                vv[j] = *(const unsigned long long*)(VT + m*132 + 2*tx + 32*j);
            #pragma unroll
            for (int i = 0; i < 4; i++) pv[i] = PS[(ty + 16*i)*130 + m];
            #pragma unroll
            for (int i = 0; i < 4; i++){
                unsigned long long pd = pk2(pv[i], pv[i]);
                #pragma unroll
                for (int j = 0; j < 4; j++) ffma2(oacc[i][j], vv[j], pd);
            }
        }
    }
    __syncthreads();

    // normalize + stage [n][c] into PS, then coalesced write to g_H
    #pragma unroll
    for (int i = 0; i < 4; i++){
        float inv = 1.0f / lrow[i];
        unsigned long long id = pk2(inv, inv);
        int nrow = ty + 16*i;
        #pragma unroll
        for (int j = 0; j < 4; j++){
            unsigned long long o2 = fmul2(oacc[i][j], id);
            float a, bv; upk2(o2, a, bv);
            *(float2*)(PS + nrow*130 + 2*tx + 32*j) = make_float2(a, bv);
        }
    }
    __syncthreads();
    float* Hb = g_H + (size_t)b*NSP*CH + (size_t)n0*CH;
    for (int k = 0; k < 32; k++){
        int e = k*256 + tid; int n = e >> 7, c = e & 127;
        Hb[n*CH + c] = PS[n*130 + c];
    }
}

// ============================================================================
// K3: y = x + Wo @ h, plus deterministic per-(b,group) partial sums.
// smem: Wot[128][130] + HS region (8320 floats; [n][129] then [o][65] staging)
// ============================================================================
__global__ __launch_bounds__(256) void k_proj(const float* __restrict__ x,
                                              const float* __restrict__ Wo)
{
    extern __shared__ float sm[];
    float* Wt = sm;               // [c][130]
    float* HS = sm + 128*130;     // [n][129] compute; [o][65] staging

    const int n0 = blockIdx.x * TN;
    const int b  = blockIdx.y;
    const int tid = threadIdx.x;
    const int tx  = tid & 15;
    const int ty  = tid >> 4;

    for (int idx = tid; idx < 128*64; idx += 256){
        int o  = idx >> 6;
        int cq = (idx & 63) << 1;
        float2 w = *(const float2*)(Wo + o*128 + cq);
        Wt[ cq   *130 + o] = w.x;
        Wt[(cq+1)*130 + o] = w.y;
    }
    const float* Hb = g_H + (size_t)b*NSP*CH + (size_t)n0*CH;
    for (int idx = tid; idx < 64*128; idx += 256){
        int n = idx >> 7, c = idx & 127;
        HS[n*129 + c] = Hb[idx];
    }
    __syncthreads();

    unsigned long long acc[4][4];
    #pragma unroll
    for (int i = 0; i < 4; i++)
        #pragma unroll
        for (int j = 0; j < 4; j++) acc[i][j] = 0ull;

    #pragma unroll 4
    for (int c = 0; c < 128; c++){
        unsigned long long wv[4]; float hv[4];
        #pragma unroll
        for (int j = 0; j < 4; j++)
            wv[j] = *(const unsigned long long*)(Wt + c*130 + 2*tx + 32*j);
        #pragma unroll
        for (int i = 0; i < 4; i++) hv[i] = HS[(ty + 16*i)*129 + c];
        #pragma unroll
        for (int i = 0; i < 4; i++){
            unsigned long long hd = pk2(hv[i], hv[i]);
            #pragma unroll
            for (int j = 0; j < 4; j++) ffma2(acc[i][j], wv[j], hd);
        }
    }
    __syncthreads();

    float* St = HS;  // [o][65]
    #pragma unroll
    for (int i = 0; i < 4; i++)
        #pragma unroll
        for (int j = 0; j < 4; j++){
            float a, bv; upk2(acc[i][j], a, bv);
            int o = 2*tx + 32*j, n = ty + 16*i;
            St[ o   *65 + n] = a;
            St[(o+1)*65 + n] = bv;
        }
    __syncthreads();

    const float* xb = x   + (size_t)b*CH*NSP + n0;
    float*       yb = g_Y + (size_t)b*CH*NSP + n0;
    const int w = tid >> 5, lane = tid & 31;
    float s1 = 0.f, s2 = 0.f;
    for (int k = 0; k < 32; k++){
        int e = w*1024 + k*32 + lane;       // warp w covers channels [16w,16w+16) = group w
        int o = e >> 6, n = e & 63;
        float val = xb[o*NSP + n] + St[o*65 + n];
        yb[o*NSP + n] = val;
        s1 += val; s2 += val*val;
    }
    #pragma unroll
    for (int d = 16; d >= 1; d >>= 1){
        s1 += __shfl_xor_sync(0xffffffffu, s1, d);
        s2 += __shfl_xor_sync(0xffffffffu, s2, d);
    }
    if (lane == 0){
        float* p = g_part + ((size_t)(b*64 + blockIdx.x)*GROUPS + w)*2;
        p[0] = s1; p[1] = s2;
    }
}

// K3b: deterministic reduction of partials. 1 block, 512 threads (warp per (b,g)).
__global__ void k_red()
{
    int w = threadIdx.x >> 5, lane = threadIdx.x & 31;
    int b = w >> 3, g = w & 7;
    float s1 = 0.f, s2 = 0.f;
    for (int t = lane; t < 64; t += 32){
        const float* p = g_part + ((size_t)(b*64 + t)*GROUPS + g)*2;
        s1 += p[0]; s2 += p[1];
    }
    #pragma unroll
    for (int d = 16; d >= 1; d >>= 1){
        s1 += __shfl_xor_sync(0xffffffffu, s1, d);
        s2 += __shfl_xor_sync(0xffffffffu, s2, d);
    }
    if (lane == 0){
        g_stats[(b*GROUPS + g)*2 + 0] = s1;
        g_stats[(b*GROUPS + g)*2 + 1] = s2;
    }
}

// K4: GroupNorm + affine + SiLU, elementwise (float4).
__global__ __launch_bounds__(256) void k_norm(const float* __restrict__ gamma,
                                              const float* __restrict__ beta,
                                              float* __restrict__ out)
{
    int gid = blockIdx.x * blockDim.x + threadIdx.x;
    int e = gid << 2;
    int b = e >> 19;               // CH*NSP = 2^19
    int c = (e >> 12) & 127;       // NSP = 2^12
    int g = c >> 4;
    float s  = g_stats[(b*GROUPS + g)*2 + 0];
    float ss = g_stats[(b*GROUPS + g)*2 + 1];
    const float icnt = 1.0f / 65536.0f;   // (CH/GROUPS)*NSP
    float mean = s * icnt;
    float var  = ss * icnt - mean*mean;
    float inv  = rsqrtf(var + EPSV);
    float ga = gamma[c], be = beta[c];

    float4 y = *(const float4*)(g_Y + e);
    float4 r;
    {
        float t = (y.x - mean)*inv*ga + be; r.x = t / (1.0f + __expf(-t));
        t = (y.y - mean)*inv*ga + be;       r.y = t / (1.0f + __expf(-t));
        t = (y.z - mean)*inv*ga + be;       r.z = t / (1.0f + __expf(-t));
        t = (y.w - mean)*inv*ga + be;       r.w = t / (1.0f + __expf(-t));
    }
    *(float4*)(out + e) = r;
}

// ============================================================================
extern "C" void kernel_launch(void* const* d_in, const int* in_sizes, int n_in,
                              void* d_out, int out_size)
{
    const float* x     = (const float*)d_in[0];
    const float* Wq    = (const float*)d_in[1];
    const float* Wk    = (const float*)d_in[2];
    const float* Wv    = (const float*)d_in[3];
    const float* Wo    = (const float*)d_in[4];
    const float* gamma = (const float*)d_in[5];
    const float* beta  = (const float*)d_in[6];
    float* out = (float*)d_out;

    const int SM1 = (128*130 + 128*65) * 4;                       // 99840 B
    const int SM2 = (128*64 + 128*128 + 128*132 + 64*130) * 4;    // 199168 B
    const int SM3 = (128*130 + 128*65) * 4;                       // 99840 B

    cudaFuncSetAttribute(k_qkv,  cudaFuncAttributeMaxDynamicSharedMemorySize, SM1);
    cudaFuncSetAttribute(k_attn, cudaFuncAttributeMaxDynamicSharedMemorySize, SM2);
    cudaFuncSetAttribute(k_proj, cudaFuncAttributeMaxDynamicSharedMemorySize, SM3);

    k_qkv <<<dim3(NSP/TN, BATCH, 3), 256, SM1>>>(x, Wq, Wk, Wv);
    k_attn<<<dim3(NSP/TN, BATCH),    256, SM2>>>();
    k_proj<<<dim3(NSP/TN, BATCH),    256, SM3>>>(x, Wo);
    k_red <<<1, 512>>>();
    k_norm<<<(BATCH*CH*NSP)/(4*256), 256>>>(gamma, beta, out);
}

// round 6
// speedup vs baseline: 2.0744x; 2.0744x over previous
#include <cuda_runtime.h>
#include <cuda_bf16.h>
#include <math_constants.h>
#include <cstdint>

#define BATCH 2
#define CH    128
#define NSP   4096
#define GROUPS 8
#define TN    64
#define EPSV  1e-5f

// attention tiling
#define TQ     128
#define TK     128
#define KSPLIT 2
#define NTILE  (NSP/KSPLIT/TK)   // 16
#define SHIFT  40.0f

// ---------------- scratch (static __device__, allocation-free) ----------------
__device__ uint32_t g_Qh[BATCH*NSP*64], g_Ql[BATCH*NSP*64];   // [b][n][cw] bf16x2
__device__ uint32_t g_Kh[BATCH*NSP*64], g_Kl[BATCH*NSP*64];   // [b][m][cw]
__device__ uint32_t g_Vh[BATCH*CH*2048], g_Vl[BATCH*CH*2048]; // [b][c][mw] (V^T)
__device__ float g_Op[KSPLIT*BATCH*NSP*CH];   // unnormalized O  [s][b][n][c]
__device__ float g_lp[KSPLIT*BATCH*NSP];      // exp-sums        [s][b][n]
__device__ float g_Y [BATCH*CH*NSP];
__device__ float g_part [BATCH*64*GROUPS*2];
__device__ float g_stats[BATCH*GROUPS*2];

// ---------------- f32x2 helpers ----------------
__device__ __forceinline__ unsigned long long pk2(float x, float y){
    unsigned long long r; asm("mov.b64 %0, {%1,%2};" : "=l"(r) : "f"(x), "f"(y)); return r;
}
__device__ __forceinline__ void upk2(unsigned long long v, float& x, float& y){
    asm("mov.b64 {%0,%1}, %2;" : "=f"(x), "=f"(y) : "l"(v));
}
__device__ __forceinline__ void ffma2(unsigned long long& d, unsigned long long a, unsigned long long b){
    asm("fma.rn.f32x2 %0, %1, %2, %0;" : "+l"(d) : "l"(a), "l"(b));
}

// ---------------- smem / mma / ldmatrix / cp.async helpers ----------------
__device__ __forceinline__ uint32_t smem_u32(const void* p){
    uint32_t a;
    asm("{ .reg .u64 t; cvta.to.shared.u64 t, %1; cvt.u32.u64 %0, t; }" : "=r"(a) : "l"(p));
    return a;
}
__device__ __forceinline__ void cpa(uint32_t saddr, const void* g){
    asm volatile("cp.async.ca.shared.global [%0], [%1], 16;" :: "r"(saddr), "l"(g) : "memory");
}
#define CPA_COMMIT() asm volatile("cp.async.commit_group;" ::: "memory")
#define CPA_WAIT0()  asm volatile("cp.async.wait_group 0;" ::: "memory")

__device__ __forceinline__ void ldsm4(uint32_t a, uint32_t r[4]){
    asm volatile("ldmatrix.sync.aligned.m8n8.x4.shared.b16 {%0,%1,%2,%3}, [%4];"
      : "=r"(r[0]), "=r"(r[1]), "=r"(r[2]), "=r"(r[3]) : "r"(a));
}
__device__ __forceinline__ void mmabf(float c[4], const uint32_t a[4], const uint32_t b[2]){
    asm volatile("mma.sync.aligned.m16n8k16.row.col.f32.bf16.bf16.f32 "
      "{%0,%1,%2,%3}, {%4,%5,%6,%7}, {%8,%9}, {%0,%1,%2,%3};"
      : "+f"(c[0]), "+f"(c[1]), "+f"(c[2]), "+f"(c[3])
      : "r"(a[0]), "r"(a[1]), "r"(a[2]), "r"(a[3]), "r"(b[0]), "r"(b[1]));
}

// bf16 hi/lo split of a float pair, packed little-endian (even elem = low half)
__device__ __forceinline__ void split2(float a, float b, uint32_t& hw, uint32_t& lw){
    __nv_bfloat16 ah = __float2bfloat16(a), bh = __float2bfloat16(b);
    float ar = a - __bfloat162float(ah), br = b - __bfloat162float(bh);
    __nv_bfloat16 al = __float2bfloat16(ar), bl = __float2bfloat16(br);
    hw = ((uint32_t)__bfloat16_as_ushort(bh) << 16) | __bfloat16_as_ushort(ah);
    lw = ((uint32_t)__bfloat16_as_ushort(bl) << 16) | __bfloat16_as_ushort(al);
}

// smem byte offsets for k_attn (row stride 272B = 136 bf16, 128 rows per tile)
#define TILEB 34816
#define QHS  0
#define QLS  (1*TILEB)
#define KHS  (2*TILEB)
#define KLS  (3*TILEB)
#define VHS  (4*TILEB)
#define VLS  (5*TILEB)
#define SM_ATTN (6*TILEB)   // 208896 B

// ============================================================================
// K1: Q/K/V projections (fp32 scalar) -> bf16 hi/lo split words.
// Q,K -> [b][n][c];  V -> [b][c][m] (transposed).
// ============================================================================
__global__ __launch_bounds__(256) void k_qkv(const float* __restrict__ x,
                                             const float* __restrict__ Wq,
                                             const float* __restrict__ Wk,
                                             const float* __restrict__ Wv)
{
    extern __shared__ float sm[];
    float* Wt = sm;               // [c][130]
    float* Xs = sm + 128*130;     // [c][64] during compute; [o][65] staging after

    const int n0  = blockIdx.x * TN;
    const int b   = blockIdx.y;
    const int z   = blockIdx.z;
    const float* W = (z == 0) ? Wq : ((z == 1) ? Wk : Wv);

    const int tid = threadIdx.x;
    const int tx  = tid & 15;
    const int ty  = tid >> 4;

    for (int idx = tid; idx < 128*64; idx += 256){
        int o  = idx >> 6;
        int cq = (idx & 63) << 1;
        float2 w = *(const float2*)(W + o*128 + cq);
        Wt[ cq   *130 + o] = w.x;
        Wt[(cq+1)*130 + o] = w.y;
    }
    const float* xb = x + (size_t)b*CH*NSP + n0;
    for (int idx = tid; idx < 128*16; idx += 256){
        int c = idx >> 4, u = (idx & 15) << 2;
        *(float4*)(Xs + c*64 + u) = *(const float4*)(xb + c*NSP + u);
    }
    __syncthreads();

    unsigned long long acc[4][4];
    #pragma unroll
    for (int i = 0; i < 4; i++)
        #pragma unroll
        for (int j = 0; j < 4; j++) acc[i][j] = 0ull;

    #pragma unroll 4
    for (int c = 0; c < 128; c++){
        unsigned long long wv[4]; float xn[4];
        #pragma unroll
        for (int j = 0; j < 4; j++)
            wv[j] = *(const unsigned long long*)(Wt + c*130 + 2*tx + 32*j);
        #pragma unroll
        for (int i = 0; i < 4; i++) xn[i] = Xs[c*64 + ty + 16*i];
        #pragma unroll
        for (int i = 0; i < 4; i++){
            unsigned long long xd = pk2(xn[i], xn[i]);
            #pragma unroll
            for (int j = 0; j < 4; j++) ffma2(acc[i][j], wv[j], xd);
        }
    }
    __syncthreads();

    float* St = Xs;  // [o][65]
    #pragma unroll
    for (int i = 0; i < 4; i++)
        #pragma unroll
        for (int j = 0; j < 4; j++){
            float a, bv; upk2(acc[i][j], a, bv);
            int o = 2*tx + 32*j, n = ty + 16*i;
            St[ o   *65 + n] = a;
            St[(o+1)*65 + n] = bv;
        }
    __syncthreads();

    if (z < 2){
        uint32_t* oh = (z == 0 ? g_Qh : g_Kh) + ((size_t)b*NSP + n0)*64;
        uint32_t* ol = (z == 0 ? g_Ql : g_Kl) + ((size_t)b*NSP + n0)*64;
        for (int idx = tid; idx < 64*64; idx += 256){
            int n = idx >> 6, cw = idx & 63;
            uint32_t hw, lw;
            split2(St[(2*cw)*65 + n], St[(2*cw+1)*65 + n], hw, lw);
            oh[n*64 + cw] = hw;
            ol[n*64 + cw] = lw;
        }
    } else {
        uint32_t* oh = g_Vh + (size_t)b*CH*2048 + (n0 >> 1);
        uint32_t* ol = g_Vl + (size_t)b*CH*2048 + (n0 >> 1);
        for (int idx = tid; idx < 128*32; idx += 256){
            int c = idx >> 5, mw = idx & 31;
            uint32_t hw, lw;
            split2(St[c*65 + 2*mw], St[c*65 + 2*mw + 1], hw, lw);
            oh[(size_t)c*2048 + mw] = hw;
            ol[(size_t)c*2048 + mw] = lw;
        }
    }
}

// ============================================================================
// K2: HMMA flash attention, unnormalized softmax (fixed shift), split-K.
// CTA = 128 queries x 2048 keys, 8 warps; warp owns 16 query rows.
// S = Q K^T and O += P V^T via mma.sync m16n8k16 bf16, 3-pass hi/lo split.
// ============================================================================
__global__ __launch_bounds__(256) void k_attn()
{
    extern __shared__ char smc[];
    const uint32_t sb = smem_u32(smc);
    const int tid = threadIdx.x;
    const int wid = tid >> 5, lane = tid & 31;
    const int n0 = blockIdx.x * TQ;
    const int b  = blockIdx.y;
    const int sp = blockIdx.z;
    const int m_base = sp * (NSP/KSPLIT);

    const uint32_t* Qh = g_Qh + ((size_t)b*NSP + n0)*64;
    const uint32_t* Ql = g_Ql + ((size_t)b*NSP + n0)*64;
    const uint32_t* Kh = g_Kh + (size_t)b*NSP*64;
    const uint32_t* Kl = g_Kl + (size_t)b*NSP*64;
    const uint32_t* Vh = g_Vh + (size_t)b*CH*2048;
    const uint32_t* Vl = g_Vl + (size_t)b*CH*2048;

    // ---- initial loads: Q tiles + first K/V tiles ----
    for (int i = tid; i < 2048; i += 256){
        int r = i >> 4, q = i & 15;
        uint32_t so = (uint32_t)r*272 + q*16;
        cpa(sb + QHS + so, Qh + r*64 + q*4);
        cpa(sb + QLS + so, Ql + r*64 + q*4);
        cpa(sb + KHS + so, Kh + (size_t)(m_base + r)*64 + q*4);
        cpa(sb + KLS + so, Kl + (size_t)(m_base + r)*64 + q*4);
        cpa(sb + VHS + so, Vh + (size_t)r*2048 + (m_base >> 1) + q*4);
        cpa(sb + VLS + so, Vl + (size_t)r*2048 + (m_base >> 1) + q*4);
    }
    CPA_COMMIT(); CPA_WAIT0();
    __syncthreads();

    float oacc[16][4];
    #pragma unroll
    for (int i = 0; i < 16; i++)
        #pragma unroll
        for (int j = 0; j < 4; j++) oacc[i][j] = 0.f;
    float lsum0 = 0.f, lsum1 = 0.f;

    // fragment address bases (row stride 272B)
    const int arow = 16*wid + (lane & 7) + ((lane >> 3) & 1)*8;
    const uint32_t aoff = (uint32_t)arow*272 + ((lane >> 4) & 1)*16;
    const int brow = (lane & 7) + ((lane >> 4) & 1)*8;
    const uint32_t boff = ((lane >> 3) & 1)*16;

    for (int t = 0; t < NTILE; t++){
        // ---- S = Q K^T : 3 split passes ----
        float sacc[16][4];
        #pragma unroll
        for (int i = 0; i < 16; i++)
            #pragma unroll
            for (int j = 0; j < 4; j++) sacc[i][j] = 0.f;

        #pragma unroll
        for (int p = 0; p < 3; p++){
            const uint32_t Ab = sb + (p < 2 ? QHS : QLS);
            const uint32_t Bb = sb + (p == 1 ? KLS : KHS);
            #pragma unroll
            for (int k = 0; k < 8; k++){
                uint32_t af[4]; ldsm4(Ab + aoff + k*32, af);
                #pragma unroll
                for (int jj = 0; jj < 8; jj++){
                    uint32_t bf4[4];
                    ldsm4(Bb + (uint32_t)(16*jj + brow)*272 + boff + k*32, bf4);
                    mmabf(sacc[2*jj],     af, bf4);
                    mmabf(sacc[2*jj + 1], af, bf4 + 2);
                }
            }
        }
        __syncthreads();               // all warps done reading K tile

        // prefetch next K while we do exp + PV
        if (t + 1 < NTILE){
            const int m1 = m_base + (t + 1)*TK;
            for (int i = tid; i < 2048; i += 256){
                int r = i >> 4, q = i & 15;
                uint32_t so = (uint32_t)r*272 + q*16;
                cpa(sb + KHS + so, Kh + (size_t)(m1 + r)*64 + q*4);
                cpa(sb + KLS + so, Kl + (size_t)(m1 + r)*64 + q*4);
            }
            CPA_COMMIT();
        }

        // ---- P = exp(S - SHIFT); pack into A-fragments (hi/lo) ----
        uint32_t pfh[8][4], pfl[8][4];
        #pragma unroll
        for (int j = 0; j < 16; j++){
            float p0 = __expf(sacc[j][0] - SHIFT);
            float p1 = __expf(sacc[j][1] - SHIFT);
            float p2 = __expf(sacc[j][2] - SHIFT);
            float p3 = __expf(sacc[j][3] - SHIFT);
            lsum0 += p0 + p1; lsum1 += p2 + p3;
            int jk = j >> 1, hv = (j & 1) << 1;
            split2(p0, p1, pfh[jk][hv],     pfl[jk][hv]);
            split2(p2, p3, pfh[jk][hv + 1], pfl[jk][hv + 1]);
        }

        // ---- O += P V^T : 3 split passes ----
        #pragma unroll
        for (int p = 0; p < 3; p++){
            const uint32_t Bb = sb + (p == 1 ? VLS : VHS);
            #pragma unroll
            for (int k = 0; k < 8; k++){
                const uint32_t* af = (p < 2) ? pfh[k] : pfl[k];
                #pragma unroll
                for (int jj = 0; jj < 8; jj++){
                    uint32_t bf4[4];
                    ldsm4(Bb + (uint32_t)(16*jj + brow)*272 + boff + k*32, bf4);
                    mmabf(oacc[2*jj],     af, bf4);
                    mmabf(oacc[2*jj + 1], af, bf4 + 2);
                }
            }
        }
        __syncthreads();               // all warps done reading V tile

        if (t + 1 < NTILE){
            const int m1 = m_base + (t + 1)*TK;
            for (int i = tid; i < 2048; i += 256){
                int r = i >> 4, q = i & 15;
                uint32_t so = (uint32_t)r*272 + q*16;
                cpa(sb + VHS + so, Vh + (size_t)r*2048 + (m1 >> 1) + q*4);
                cpa(sb + VLS + so, Vl + (size_t)r*2048 + (m1 >> 1) + q*4);
            }
            CPA_COMMIT();
        }
        CPA_WAIT0();
        __syncthreads();
    }

    // ---- epilogue: l per row, unnormalized O out ----
    #pragma unroll
    for (int d = 1; d < 4; d <<= 1){
        lsum0 += __shfl_xor_sync(0xffffffffu, lsum0, d);
        lsum1 += __shfl_xor_sync(0xffffffffu, lsum1, d);
    }
    const int g = lane >> 2, q = lane & 3;
    const int row = 16*wid + g;
    if (q == 0){
        size_t lb = ((size_t)sp*BATCH + b)*NSP + n0;
        g_lp[lb + row]     = lsum0;
        g_lp[lb + row + 8] = lsum1;
    }
    float* Ob = g_Op + (((size_t)sp*BATCH + b)*NSP + n0)*CH;
    #pragma unroll
    for (int tt = 0; tt < 16; tt++){
        int c = 8*tt + 2*q;
        *(float2*)(Ob + (size_t)row*CH + c)       = make_float2(oacc[tt][0], oacc[tt][1]);
        *(float2*)(Ob + (size_t)(row + 8)*CH + c) = make_float2(oacc[tt][2], oacc[tt][3]);
    }
}

// ============================================================================
// K3: combine splits, y = x + Wo @ h, per-(b,group) partial sums.
// ============================================================================
__global__ __launch_bounds__(256) void k_proj(const float* __restrict__ x,
                                              const float* __restrict__ Wo)
{
    extern __shared__ float sm[];
    __shared__ float rlS[64];
    float* Wt = sm;               // [c][130]
    float* HS = sm + 128*130;     // [n][129] compute; [o][65] staging

    const int n0 = blockIdx.x * TN;
    const int b  = blockIdx.y;
    const int tid = threadIdx.x;
    const int tx  = tid & 15;
    const int ty  = tid >> 4;

    if (tid < 64){
        float l0 = g_lp[((size_t)0*BATCH + b)*NSP + n0 + tid];
        float l1 = g_lp[((size_t)1*BATCH + b)*NSP + n0 + tid];
        rlS[tid] = 1.0f / (l0 + l1);
    }
    for (int idx = tid; idx < 128*64; idx += 256){
        int o  = idx >> 6;
        int cq = (idx & 63) << 1;
        float2 w = *(const float2*)(Wo + o*128 + cq);
        Wt[ cq   *130 + o] = w.x;
        Wt[(cq+1)*130 + o] = w.y;
    }
    __syncthreads();

    const float* O0 = g_Op + (((size_t)0*BATCH + b)*NSP + n0)*CH;
    const float* O1 = g_Op + (((size_t)1*BATCH + b)*NSP + n0)*CH;
    for (int idx = tid; idx < 64*128; idx += 256){
        int n = idx >> 7, c = idx & 127;
        HS[n*129 + c] = (O0[idx] + O1[idx]) * rlS[n];
    }
    __syncthreads();

    unsigned long long acc[4][4];
    #pragma unroll
    for (int i = 0; i < 4; i++)
        #pragma unroll
        for (int j = 0; j < 4; j++) acc[i][j] = 0ull;

    #pragma unroll 4
    for (int c = 0; c < 128; c++){
        unsigned long long wv[4]; float hv[4];
        #pragma unroll
        for (int j = 0; j < 4; j++)
            wv[j] = *(const unsigned long long*)(Wt + c*130 + 2*tx + 32*j);
        #pragma unroll
        for (int i = 0; i < 4; i++) hv[i] = HS[(ty + 16*i)*129 + c];
        #pragma unroll
        for (int i = 0; i < 4; i++){
            unsigned long long hd = pk2(hv[i], hv[i]);
            #pragma unroll
            for (int j = 0; j < 4; j++) ffma2(acc[i][j], wv[j], hd);
        }
    }
    __syncthreads();

    float* St = HS;  // [o][65]
    #pragma unroll
    for (int i = 0; i < 4; i++)
        #pragma unroll
        for (int j = 0; j < 4; j++){
            float a, bv; upk2(acc[i][j], a, bv);
            int o = 2*tx + 32*j, n = ty + 16*i;
            St[ o   *65 + n] = a;
            St[(o+1)*65 + n] = bv;
        }
    __syncthreads();

    const float* xb = x   + (size_t)b*CH*NSP + n0;
    float*       yb = g_Y + (size_t)b*CH*NSP + n0;
    const int w = tid >> 5, lane = tid & 31;
    float s1 = 0.f, s2 = 0.f;
    for (int k = 0; k < 32; k++){
        int e = w*1024 + k*32 + lane;
        int o = e >> 6, n = e & 63;
        float val = xb[o*NSP + n] + St[o*65 + n];
        yb[o*NSP + n] = val;
        s1 += val; s2 += val*val;
    }
    #pragma unroll
    for (int d = 16; d >= 1; d >>= 1){
        s1 += __shfl_xor_sync(0xffffffffu, s1, d);
        s2 += __shfl_xor_sync(0xffffffffu, s2, d);
    }
    if (lane == 0){
        float* p = g_part + ((size_t)(b*64 + blockIdx.x)*GROUPS + w)*2;
        p[0] = s1; p[1] = s2;
    }
}

// K3b: deterministic reduction of partials.
__global__ void k_red()
{
    int w = threadIdx.x >> 5, lane = threadIdx.x & 31;
    int b = w >> 3, g = w & 7;
    float s1 = 0.f, s2 = 0.f;
    for (int t = lane; t < 64; t += 32){
        const float* p = g_part + ((size_t)(b*64 + t)*GROUPS + g)*2;
        s1 += p[0]; s2 += p[1];
    }
    #pragma unroll
    for (int d = 16; d >= 1; d >>= 1){
        s1 += __shfl_xor_sync(0xffffffffu, s1, d);
        s2 += __shfl_xor_sync(0xffffffffu, s2, d);
    }
    if (lane == 0){
        g_stats[(b*GROUPS + g)*2 + 0] = s1;
        g_stats[(b*GROUPS + g)*2 + 1] = s2;
    }
}

// K4: GroupNorm + affine + SiLU.
__global__ __launch_bounds__(256) void k_norm(const float* __restrict__ gamma,
                                              const float* __restrict__ beta,
                                              float* __restrict__ out)
{
    int gid = blockIdx.x * blockDim.x + threadIdx.x;
    int e = gid << 2;
    int b = e >> 19;
    int c = (e >> 12) & 127;
    int g = c >> 4;
    float s  = g_stats[(b*GROUPS + g)*2 + 0];
    float ss = g_stats[(b*GROUPS + g)*2 + 1];
    const float icnt = 1.0f / 65536.0f;
    float mean = s * icnt;
    float var  = ss * icnt - mean*mean;
    float inv  = rsqrtf(var + EPSV);
    float ga = gamma[c], be = beta[c];

    float4 y = *(const float4*)(g_Y + e);
    float4 r;
    float t = (y.x - mean)*inv*ga + be; r.x = t / (1.0f + __expf(-t));
    t = (y.y - mean)*inv*ga + be;       r.y = t / (1.0f + __expf(-t));
    t = (y.z - mean)*inv*ga + be;       r.z = t / (1.0f + __expf(-t));
    t = (y.w - mean)*inv*ga + be;       r.w = t / (1.0f + __expf(-t));
    *(float4*)(out + e) = r;
}

// ============================================================================
extern "C" void kernel_launch(void* const* d_in, const int* in_sizes, int n_in,
                              void* d_out, int out_size)
{
    const float* x     = (const float*)d_in[0];
    const float* Wq    = (const float*)d_in[1];
    const float* Wk    = (const float*)d_in[2];
    const float* Wv    = (const float*)d_in[3];
    const float* Wo    = (const float*)d_in[4];
    const float* gamma = (const float*)d_in[5];
    const float* beta  = (const float*)d_in[6];
    float* out = (float*)d_out;

    const int SM1 = (128*130 + 128*65) * 4;
    const int SM3 = (128*130 + 128*65) * 4;

    cudaFuncSetAttribute(k_qkv,  cudaFuncAttributeMaxDynamicSharedMemorySize, SM1);
    cudaFuncSetAttribute(k_attn, cudaFuncAttributeMaxDynamicSharedMemorySize, SM_ATTN);
    cudaFuncSetAttribute(k_proj, cudaFuncAttributeMaxDynamicSharedMemorySize, SM3);

    k_qkv <<<dim3(NSP/TN, BATCH, 3),      256, SM1>>>(x, Wq, Wk, Wv);
    k_attn<<<dim3(NSP/TQ, BATCH, KSPLIT), 256, SM_ATTN>>>();
    k_proj<<<dim3(NSP/TN, BATCH),         256, SM3>>>(x, Wo);
    k_red <<<1, 512>>>();
    k_norm<<<(BATCH*CH*NSP)/(4*256), 256>>>(gamma, beta, out);
}

// round 7
// speedup vs baseline: 2.8638x; 1.3806x over previous
#include <cuda_runtime.h>
#include <cuda_bf16.h>
#include <math_constants.h>
#include <cstdint>

#define BATCH 2
#define CH    128
#define NSP   4096
#define GROUPS 8
#define TN    64
#define EPSV  1e-5f

// attention tiling
#define TQ     128
#define TK     128
#define KSPLIT 2
#define NTILE  (NSP/KSPLIT/TK)   // 16
#define SHIFT  40.0f

// ---------------- scratch (static __device__, allocation-free) ----------------
__device__ uint32_t g_Qh[BATCH*NSP*64], g_Ql[BATCH*NSP*64];   // [b][n][cw] bf16x2
__device__ uint32_t g_Kh[BATCH*NSP*64], g_Kl[BATCH*NSP*64];   // [b][m][cw]
__device__ uint32_t g_Vh[BATCH*CH*2048], g_Vl[BATCH*CH*2048]; // [b][c][mw] (V^T)
__device__ float g_Op[KSPLIT*BATCH*NSP*CH];   // unnormalized O  [s][b][n][c]
__device__ float g_lp[KSPLIT*BATCH*NSP];      // exp-sums        [s][b][n]
__device__ float g_Y [BATCH*CH*NSP];
__device__ float g_part [BATCH*64*GROUPS*2];

// ---------------- f32x2 helpers ----------------
__device__ __forceinline__ unsigned long long pk2(float x, float y){
    unsigned long long r; asm("mov.b64 %0, {%1,%2};" : "=l"(r) : "f"(x), "f"(y)); return r;
}
__device__ __forceinline__ void upk2(unsigned long long v, float& x, float& y){
    asm("mov.b64 {%0,%1}, %2;" : "=f"(x), "=f"(y) : "l"(v));
}
__device__ __forceinline__ void ffma2(unsigned long long& d, unsigned long long a, unsigned long long b){
    asm("fma.rn.f32x2 %0, %1, %2, %0;" : "+l"(d) : "l"(a), "l"(b));
}

// ---------------- smem / mma / ldmatrix / cp.async helpers ----------------
__device__ __forceinline__ uint32_t smem_u32(const void* p){
    uint32_t a;
    asm("{ .reg .u64 t; cvta.to.shared.u64 t, %1; cvt.u32.u64 %0, t; }" : "=r"(a) : "l"(p));
    return a;
}
__device__ __forceinline__ void cpa(uint32_t saddr, const void* g){
    asm volatile("cp.async.ca.shared.global [%0], [%1], 16;" :: "r"(saddr), "l"(g) : "memory");
}
#define CPA_COMMIT() asm volatile("cp.async.commit_group;" ::: "memory")
#define CPA_WAIT0()  asm volatile("cp.async.wait_group 0;" ::: "memory")
#define CPA_WAIT1()  asm volatile("cp.async.wait_group 1;" ::: "memory")

__device__ __forceinline__ void ldsm4(uint32_t a, uint32_t r[4]){
    asm volatile("ldmatrix.sync.aligned.m8n8.x4.shared.b16 {%0,%1,%2,%3}, [%4];"
      : "=r"(r[0]), "=r"(r[1]), "=r"(r[2]), "=r"(r[3]) : "r"(a));
}
__device__ __forceinline__ void mmabf(float c[4], const uint32_t a[4], const uint32_t b[2]){
    asm volatile("mma.sync.aligned.m16n8k16.row.col.f32.bf16.bf16.f32 "
      "{%0,%1,%2,%3}, {%4,%5,%6,%7}, {%8,%9}, {%0,%1,%2,%3};"
      : "+f"(c[0]), "+f"(c[1]), "+f"(c[2]), "+f"(c[3])
      : "r"(a[0]), "r"(a[1]), "r"(a[2]), "r"(a[3]), "r"(b[0]), "r"(b[1]));
}

// bf16 hi/lo split of a float pair, packed little-endian (even elem = low half)
__device__ __forceinline__ void split2(float a, float b, uint32_t& hw, uint32_t& lw){
    __nv_bfloat16 ah = __float2bfloat16(a), bh = __float2bfloat16(b);
    float ar = a - __bfloat162float(ah), br = b - __bfloat162float(bh);
    __nv_bfloat16 al = __float2bfloat16(ar), bl = __float2bfloat16(br);
    hw = ((uint32_t)__bfloat16_as_ushort(bh) << 16) | __bfloat16_as_ushort(ah);
    lw = ((uint32_t)__bfloat16_as_ushort(bl) << 16) | __bfloat16_as_ushort(al);
}

// smem byte offsets for k_attn (row stride 272B = 136 bf16, 128 rows per tile)
#define TILEB 34816
#define QHS  0
#define QLS  (1*TILEB)
#define KHS  (2*TILEB)
#define KLS  (3*TILEB)
#define VHS  (4*TILEB)
#define VLS  (5*TILEB)
#define SM_ATTN (6*TILEB)   // 208896 B

// ============================================================================
// K1: Q/K/V projections (fp32 scalar) -> bf16 hi/lo split words.
// Q,K -> [b][n][c];  V -> [b][c][m] (transposed).
// ============================================================================
__global__ __launch_bounds__(256) void k_qkv(const float* __restrict__ x,
                                             const float* __restrict__ Wq,
                                             const float* __restrict__ Wk,
                                             const float* __restrict__ Wv)
{
    extern __shared__ float sm[];
    float* Wt = sm;               // [c][130]
    float* Xs = sm + 128*130;     // [c][64] during compute; [o][65] staging after

    const int n0  = blockIdx.x * TN;
    const int b   = blockIdx.y;
    const int z   = blockIdx.z;
    const float* W = (z == 0) ? Wq : ((z == 1) ? Wk : Wv);

    const int tid = threadIdx.x;
    const int tx  = tid & 15;
    const int ty  = tid >> 4;

    for (int idx = tid; idx < 128*64; idx += 256){
        int o  = idx >> 6;
        int cq = (idx & 63) << 1;
        float2 w = *(const float2*)(W + o*128 + cq);
        Wt[ cq   *130 + o] = w.x;
        Wt[(cq+1)*130 + o] = w.y;
    }
    const float* xb = x + (size_t)b*CH*NSP + n0;
    for (int idx = tid; idx < 128*16; idx += 256){
        int c = idx >> 4, u = (idx & 15) << 2;
        *(float4*)(Xs + c*64 + u) = *(const float4*)(xb + c*NSP + u);
    }
    __syncthreads();

    unsigned long long acc[4][4];
    #pragma unroll
    for (int i = 0; i < 4; i++)
        #pragma unroll
        for (int j = 0; j < 4; j++) acc[i][j] = 0ull;

    #pragma unroll 4
    for (int c = 0; c < 128; c++){
        unsigned long long wv[4]; float xn[4];
        #pragma unroll
        for (int j = 0; j < 4; j++)
            wv[j] = *(const unsigned long long*)(Wt + c*130 + 2*tx + 32*j);
        #pragma unroll
        for (int i = 0; i < 4; i++) xn[i] = Xs[c*64 + ty + 16*i];
        #pragma unroll
        for (int i = 0; i < 4; i++){
            unsigned long long xd = pk2(xn[i], xn[i]);
            #pragma unroll
            for (int j = 0; j < 4; j++) ffma2(acc[i][j], wv[j], xd);
        }
    }
    __syncthreads();

    float* St = Xs;  // [o][65]
    #pragma unroll
    for (int i = 0; i < 4; i++)
        #pragma unroll
        for (int j = 0; j < 4; j++){
            float a, bv; upk2(acc[i][j], a, bv);
            int o = 2*tx + 32*j, n = ty + 16*i;
            St[ o   *65 + n] = a;
            St[(o+1)*65 + n] = bv;
        }
    __syncthreads();

    if (z < 2){
        uint32_t* oh = (z == 0 ? g_Qh : g_Kh) + ((size_t)b*NSP + n0)*64;
        uint32_t* ol = (z == 0 ? g_Ql : g_Kl) + ((size_t)b*NSP + n0)*64;
        for (int idx = tid; idx < 64*64; idx += 256){
            int n = idx >> 6, cw = idx & 63;
            uint32_t hw, lw;
            split2(St[(2*cw)*65 + n], St[(2*cw+1)*65 + n], hw, lw);
            oh[n*64 + cw] = hw;
            ol[n*64 + cw] = lw;
        }
    } else {
        uint32_t* oh = g_Vh + (size_t)b*CH*2048 + (n0 >> 1);
        uint32_t* ol = g_Vl + (size_t)b*CH*2048 + (n0 >> 1);
        for (int idx = tid; idx < 128*32; idx += 256){
            int c = idx >> 5, mw = idx & 31;
            uint32_t hw, lw;
            split2(St[c*65 + 2*mw], St[c*65 + 2*mw + 1], hw, lw);
            oh[(size_t)c*2048 + mw] = hw;
            ol[(size_t)c*2048 + mw] = lw;
        }
    }
}

// ============================================================================
// K2: HMMA flash attention, unnormalized softmax (fixed shift), split-K.
// Fragment-cached 3-pass split: B (K/V) hi+lo loaded ONCE per (k,jj);
// Q_hi fragments cached in registers for the whole kernel.
// Split-group cp.async pipeline: QK never waits on V, PV never waits on K.
// ============================================================================
__global__ __launch_bounds__(256) void k_attn()
{
    extern __shared__ char smc[];
    const uint32_t sb = smem_u32(smc);
    const int tid = threadIdx.x;
    const int wid = tid >> 5, lane = tid & 31;
    const int n0 = blockIdx.x * TQ;
    const int b  = blockIdx.y;
    const int sp = blockIdx.z;
    const int m_base = sp * (NSP/KSPLIT);

    const uint32_t* Qh = g_Qh + ((size_t)b*NSP + n0)*64;
    const uint32_t* Ql = g_Ql + ((size_t)b*NSP + n0)*64;
    const uint32_t* Kh = g_Kh + (size_t)b*NSP*64;
    const uint32_t* Kl = g_Kl + (size_t)b*NSP*64;
    const uint32_t* Vh = g_Vh + (size_t)b*CH*2048;
    const uint32_t* Vl = g_Vl + (size_t)b*CH*2048;

    // ---- prologue: group A = Q + K(0); group B = V(0) ----
    for (int i = tid; i < 2048; i += 256){
        int r = i >> 4, q = i & 15;
        uint32_t so = (uint32_t)r*272 + q*16;
        cpa(sb + QHS + so, Qh + r*64 + q*4);
        cpa(sb + QLS + so, Ql + r*64 + q*4);
        cpa(sb + KHS + so, Kh + (size_t)(m_base + r)*64 + q*4);
        cpa(sb + KLS + so, Kl + (size_t)(m_base + r)*64 + q*4);
    }
    CPA_COMMIT();
    for (int i = tid; i < 2048; i += 256){
        int r = i >> 4, q = i & 15;
        uint32_t so = (uint32_t)r*272 + q*16;
        cpa(sb + VHS + so, Vh + (size_t)r*2048 + (m_base >> 1) + q*4);
        cpa(sb + VLS + so, Vl + (size_t)r*2048 + (m_base >> 1) + q*4);
    }
    CPA_COMMIT();
    CPA_WAIT1();            // Q + K(0) ready (V(0) may still fly)
    __syncthreads();

    // fragment address bases (row stride 272B)
    const int arow = 16*wid + (lane & 7) + ((lane >> 3) & 1)*8;
    const uint32_t aoff = (uint32_t)arow*272 + ((lane >> 4) & 1)*16;
    const int brow = (lane & 7) + ((lane >> 4) & 1)*8;
    const uint32_t boff = ((lane >> 3) & 1)*16;

    // ---- cache Q_hi A-fragments for the whole kernel ----
    uint32_t qfh[8][4];
    #pragma unroll
    for (int k = 0; k < 8; k++) ldsm4(sb + QHS + aoff + k*32, qfh[k]);

    float oacc[16][4];
    #pragma unroll
    for (int i = 0; i < 16; i++)
        #pragma unroll
        for (int j = 0; j < 4; j++) oacc[i][j] = 0.f;
    float lsum0 = 0.f, lsum1 = 0.f;

    for (int t = 0; t < NTILE; t++){
        // ---- S = Q K^T : B-fragments loaded once, 3 split passes from regs ----
        float sacc[16][4];
        #pragma unroll
        for (int i = 0; i < 16; i++)
            #pragma unroll
            for (int j = 0; j < 4; j++) sacc[i][j] = 0.f;

        #pragma unroll
        for (int k = 0; k < 8; k++){
            uint32_t al[4];
            ldsm4(sb + QLS + aoff + k*32, al);
            #pragma unroll
            for (int jj = 0; jj < 8; jj++){
                uint32_t bh[4], bl[4];
                uint32_t ro = (uint32_t)(16*jj + brow)*272 + boff + k*32;
                ldsm4(sb + KHS + ro, bh);
                ldsm4(sb + KLS + ro, bl);
                mmabf(sacc[2*jj],     qfh[k], bh);
                mmabf(sacc[2*jj + 1], qfh[k], bh + 2);
                mmabf(sacc[2*jj],     qfh[k], bl);
                mmabf(sacc[2*jj + 1], qfh[k], bl + 2);
                mmabf(sacc[2*jj],     al,     bh);
                mmabf(sacc[2*jj + 1], al,     bh + 2);
            }
        }
        __syncthreads();               // all warps done reading K tile

        // prefetch next K while we do exp + PV
        if (t + 1 < NTILE){
            const int m1 = m_base + (t + 1)*TK;
            for (int i = tid; i < 2048; i += 256){
                int r = i >> 4, q = i & 15;
                uint32_t so = (uint32_t)r*272 + q*16;
                cpa(sb + KHS + so, Kh + (size_t)(m1 + r)*64 + q*4);
                cpa(sb + KLS + so, Kl + (size_t)(m1 + r)*64 + q*4);
            }
            CPA_COMMIT();
        }

        // ---- P = exp(S - SHIFT); pack into A-fragments (hi/lo) ----
        uint32_t pfh[8][4], pfl[8][4];
        #pragma unroll
        for (int j = 0; j < 16; j++){
            float p0 = __expf(sacc[j][0] - SHIFT);
            float p1 = __expf(sacc[j][1] - SHIFT);
            float p2 = __expf(sacc[j][2] - SHIFT);
            float p3 = __expf(sacc[j][3] - SHIFT);
            lsum0 += p0 + p1; lsum1 += p2 + p3;
            int jk = j >> 1, hv = (j & 1) << 1;
            split2(p0, p1, pfh[jk][hv],     pfl[jk][hv]);
            split2(p2, p3, pfh[jk][hv + 1], pfl[jk][hv + 1]);
        }

        // V(t) ready?  (pending: V(t) [, K(t+1)])
        if (t + 1 < NTILE) { CPA_WAIT1(); } else { CPA_WAIT0(); }
        __syncthreads();

        // ---- O += P V^T : B-fragments loaded once, 3 split passes from regs ----
        #pragma unroll
        for (int k = 0; k < 8; k++){
            #pragma unroll
            for (int jj = 0; jj < 8; jj++){
                uint32_t bh[4], bl[4];
                uint32_t ro = (uint32_t)(16*jj + brow)*272 + boff + k*32;
                ldsm4(sb + VHS + ro, bh);
                ldsm4(sb + VLS + ro, bl);
                mmabf(oacc[2*jj],     pfh[k], bh);
                mmabf(oacc[2*jj + 1], pfh[k], bh + 2);
                mmabf(oacc[2*jj],     pfh[k], bl);
                mmabf(oacc[2*jj + 1], pfh[k], bl + 2);
                mmabf(oacc[2*jj],     pfl[k], bh);
                mmabf(oacc[2*jj + 1], pfl[k], bh + 2);
            }
        }
        __syncthreads();               // all warps done reading V tile

        if (t + 1 < NTILE){
            const int m1 = m_base + (t + 1)*TK;
            for (int i = tid; i < 2048; i += 256){
                int r = i >> 4, q = i & 15;
                uint32_t so = (uint32_t)r*272 + q*16;
                cpa(sb + VHS + so, Vh + (size_t)r*2048 + (m1 >> 1) + q*4);
                cpa(sb + VLS + so, Vl + (size_t)r*2048 + (m1 >> 1) + q*4);
            }
            CPA_COMMIT();
            CPA_WAIT1();               // K(t+1) ready for next QK (V(t+1) may fly)
            __syncthreads();
        }
    }

    // ---- epilogue: l per row, unnormalized O out ----
    #pragma unroll
    for (int d = 1; d < 4; d <<= 1){
        lsum0 += __shfl_xor_sync(0xffffffffu, lsum0, d);
        lsum1 += __shfl_xor_sync(0xffffffffu, lsum1, d);
    }
    const int g = lane >> 2, q = lane & 3;
    const int row = 16*wid + g;
    if (q == 0){
        size_t lb = ((size_t)sp*BATCH + b)*NSP + n0;
        g_lp[lb + row]     = lsum0;
        g_lp[lb + row + 8] = lsum1;
    }
    float* Ob = g_Op + (((size_t)sp*BATCH + b)*NSP + n0)*CH;
    #pragma unroll
    for (int tt = 0; tt < 16; tt++){
        int c = 8*tt + 2*q;
        *(float2*)(Ob + (size_t)row*CH + c)       = make_float2(oacc[tt][0], oacc[tt][1]);
        *(float2*)(Ob + (size_t)(row + 8)*CH + c) = make_float2(oacc[tt][2], oacc[tt][3]);
    }
}

// ============================================================================
// K3: combine splits, y = x + Wo @ h, per-(b,group) partial sums.
// ============================================================================
__global__ __launch_bounds__(256) void k_proj(const float* __restrict__ x,
                                              const float* __restrict__ Wo)
{
    extern __shared__ float sm[];
    __shared__ float rlS[64];
    float* Wt = sm;               // [c][130]
    float* HS = sm + 128*130;     // [n][129] compute; [o][65] staging

    const int n0 = blockIdx.x * TN;
    const int b  = blockIdx.y;
    const int tid = threadIdx.x;
    const int tx  = tid & 15;
    const int ty  = tid >> 4;

    if (tid < 64){
        float l0 = g_lp[((size_t)0*BATCH + b)*NSP + n0 + tid];
        float l1 = g_lp[((size_t)1*BATCH + b)*NSP + n0 + tid];
        rlS[tid] = 1.0f / (l0 + l1);
    }
    for (int idx = tid; idx < 128*64; idx += 256){
        int o  = idx >> 6;
        int cq = (idx & 63) << 1;
        float2 w = *(const float2*)(Wo + o*128 + cq);
        Wt[ cq   *130 + o] = w.x;
        Wt[(cq+1)*130 + o] = w.y;
    }
    __syncthreads();

    const float* O0 = g_Op + (((size_t)0*BATCH + b)*NSP + n0)*CH;
    const float* O1 = g_Op + (((size_t)1*BATCH + b)*NSP + n0)*CH;
    for (int idx = tid; idx < 64*128; idx += 256){
        int n = idx >> 7, c = idx & 127;
        HS[n*129 + c] = (O0[idx] + O1[idx]) * rlS[n];
    }
    __syncthreads();

    unsigned long long acc[4][4];
    #pragma unroll
    for (int i = 0; i < 4; i++)
        #pragma unroll
        for (int j = 0; j < 4; j++) acc[i][j] = 0ull;

    #pragma unroll 4
    for (int c = 0; c < 128; c++){
        unsigned long long wv[4]; float hv[4];
        #pragma unroll
        for (int j = 0; j < 4; j++)
            wv[j] = *(const unsigned long long*)(Wt + c*130 + 2*tx + 32*j);
        #pragma unroll
        for (int i = 0; i < 4; i++) hv[i] = HS[(ty + 16*i)*129 + c];
        #pragma unroll
        for (int i = 0; i < 4; i++){
            unsigned long long hd = pk2(hv[i], hv[i]);
            #pragma unroll
            for (int j = 0; j < 4; j++) ffma2(acc[i][j], wv[j], hd);
        }
    }
    __syncthreads();

    float* St = HS;  // [o][65]
    #pragma unroll
    for (int i = 0; i < 4; i++)
        #pragma unroll
        for (int j = 0; j < 4; j++){
            float a, bv; upk2(acc[i][j], a, bv);
            int o = 2*tx + 32*j, n = ty + 16*i;
            St[ o   *65 + n] = a;
            St[(o+1)*65 + n] = bv;
        }
    __syncthreads();

    const float* xb = x   + (size_t)b*CH*NSP + n0;
    float*       yb = g_Y + (size_t)b*CH*NSP + n0;
    const int w = tid >> 5, lane = tid & 31;
    float s1 = 0.f, s2 = 0.f;
    for (int k = 0; k < 32; k++){
        int e = w*1024 + k*32 + lane;
        int o = e >> 6, n = e & 63;
        float val = xb[o*NSP + n] + St[o*65 + n];
        yb[o*NSP + n] = val;
        s1 += val; s2 += val*val;
    }
    #pragma unroll
    for (int d = 16; d >= 1; d >>= 1){
        s1 += __shfl_xor_sync(0xffffffffu, s1, d);
        s2 += __shfl_xor_sync(0xffffffffu, s2, d);
    }
    if (lane == 0){
        float* p = g_part + ((size_t)(b*64 + blockIdx.x)*GROUPS + w)*2;
        p[0] = s1; p[1] = s2;
    }
}

// K4: GroupNorm + affine + SiLU, with fused (redundant, deterministic)
// per-block reduction of the 64 partial sums for this block's group.
__global__ __launch_bounds__(256) void k_norm(const float* __restrict__ gamma,
                                              const float* __restrict__ beta,
                                              float* __restrict__ out)
{
    __shared__ float sh_mean, sh_inv;
    const int tid = threadIdx.x;
    const int e0 = blockIdx.x << 10;        // 1024 elems per block
    const int b = e0 >> 19;
    const int c = (e0 >> 12) & 127;
    const int g = c >> 4;

    if (tid < 32){
        const float* p = g_part + ((size_t)(b*64)*GROUPS + g)*2;
        float s1 = p[(size_t)tid*GROUPS*2]     + p[(size_t)(tid+32)*GROUPS*2];
        float s2 = p[(size_t)tid*GROUPS*2 + 1] + p[(size_t)(tid+32)*GROUPS*2 + 1];
        #pragma unroll
        for (int d = 16; d >= 1; d >>= 1){
            s1 += __shfl_xor_sync(0xffffffffu, s1, d);
            s2 += __shfl_xor_sync(0xffffffffu, s2, d);
        }
        if (tid == 0){
            const float icnt = 1.0f / 65536.0f;
            float mean = s1 * icnt;
            float var  = s2 * icnt - mean*mean;
            sh_mean = mean;
            sh_inv  = rsqrtf(var + EPSV);
        }
    }
    __syncthreads();

    const float mean = sh_mean, inv = sh_inv;
    const float ga = gamma[c], be = beta[c];
    const int e = e0 + tid*4;
    float4 y = *(const float4*)(g_Y + e);
    float4 r;
    float t = (y.x - mean)*inv*ga + be; r.x = t / (1.0f + __expf(-t));
    t = (y.y - mean)*inv*ga + be;       r.y = t / (1.0f + __expf(-t));
    t = (y.z - mean)*inv*ga + be;       r.z = t / (1.0f + __expf(-t));
    t = (y.w - mean)*inv*ga + be;       r.w = t / (1.0f + __expf(-t));
    *(float4*)(out + e) = r;
}

// ============================================================================
extern "C" void kernel_launch(void* const* d_in, const int* in_sizes, int n_in,
                              void* d_out, int out_size)
{
    const float* x     = (const float*)d_in[0];
    const float* Wq    = (const float*)d_in[1];
    const float* Wk    = (const float*)d_in[2];
    const float* Wv    = (const float*)d_in[3];
    const float* Wo    = (const float*)d_in[4];
    const float* gamma = (const float*)d_in[5];
    const float* beta  = (const float*)d_in[6];
    float* out = (float*)d_out;

    const int SM1 = (128*130 + 128*65) * 4;
    const int SM3 = (128*130 + 128*65) * 4;

    cudaFuncSetAttribute(k_qkv,  cudaFuncAttributeMaxDynamicSharedMemorySize, SM1);
    cudaFuncSetAttribute(k_attn, cudaFuncAttributeMaxDynamicSharedMemorySize, SM_ATTN);
    cudaFuncSetAttribute(k_proj, cudaFuncAttributeMaxDynamicSharedMemorySize, SM3);

    k_qkv <<<dim3(NSP/TN, BATCH, 3),      256, SM1>>>(x, Wq, Wk, Wv);
    k_attn<<<dim3(NSP/TQ, BATCH, KSPLIT), 256, SM_ATTN>>>();
    k_proj<<<dim3(NSP/TN, BATCH),         256, SM3>>>(x, Wo);
    k_norm<<<(BATCH*CH*NSP)/(4*256), 256>>>(gamma, beta, out);
}

// round 9
// speedup vs baseline: 2.9024x; 1.0135x over previous
#include <cuda_runtime.h>
#include <cuda_bf16.h>
#include <math_constants.h>
#include <cstdint>

#define BATCH 2
#define CH    128
#define NSP   4096
#define GROUPS 8
#define TN    64
#define EPSV  1e-5f

// attention tiling
#define TQ     128
#define TKK    64
#define KSPLIT 2
#define NT2    (NSP/KSPLIT/TKK)   // 32
#define SHIFT  40.0f

// ---------------- scratch (static __device__, allocation-free) ----------------
__device__ uint32_t g_Qh[BATCH*NSP*64], g_Ql[BATCH*NSP*64];   // [b][n][cw] bf16x2
__device__ uint32_t g_Kh[BATCH*NSP*64], g_Kl[BATCH*NSP*64];   // [b][m][cw]
__device__ uint32_t g_Vh[BATCH*CH*2048], g_Vl[BATCH*CH*2048]; // [b][c][mw] (V^T)
__device__ float g_Op[KSPLIT*BATCH*NSP*CH];   // unnormalized O  [s][b][n][c]
__device__ float g_lp[KSPLIT*BATCH*NSP];      // exp-sums        [s][b][n]
__device__ float g_Y [BATCH*CH*NSP];
__device__ float g_part [BATCH*64*GROUPS*2];

// ---------------- f32x2 helpers ----------------
__device__ __forceinline__ unsigned long long pk2(float x, float y){
    unsigned long long r; asm("mov.b64 %0, {%1,%2};" : "=l"(r) : "f"(x), "f"(y)); return r;
}
__device__ __forceinline__ void upk2(unsigned long long v, float& x, float& y){
    asm("mov.b64 {%0,%1}, %2;" : "=f"(x), "=f"(y) : "l"(v));
}
__device__ __forceinline__ void ffma2(unsigned long long& d, unsigned long long a, unsigned long long b){
    asm("fma.rn.f32x2 %0, %1, %2, %0;" : "+l"(d) : "l"(a), "l"(b));
}

// ---------------- smem / mma / ldmatrix / cp.async helpers ----------------
__device__ __forceinline__ uint32_t smem_u32(const void* p){
    uint32_t a;
    asm("{ .reg .u64 t; cvta.to.shared.u64 t, %1; cvt.u32.u64 %0, t; }" : "=r"(a) : "l"(p));
    return a;
}
__device__ __forceinline__ void cpa(uint32_t saddr, const void* g){
    asm volatile("cp.async.ca.shared.global [%0], [%1], 16;" :: "r"(saddr), "l"(g) : "memory");
}
#define CPA_COMMIT() asm volatile("cp.async.commit_group;" ::: "memory")
#define CPA_WAIT0()  asm volatile("cp.async.wait_group 0;" ::: "memory")
#define CPA_WAIT1()  asm volatile("cp.async.wait_group 1;" ::: "memory")

__device__ __forceinline__ void ldsm4(uint32_t a, uint32_t r[4]){
    asm volatile("ldmatrix.sync.aligned.m8n8.x4.shared.b16 {%0,%1,%2,%3}, [%4];"
      : "=r"(r[0]), "=r"(r[1]), "=r"(r[2]), "=r"(r[3]) : "r"(a));
}
__device__ __forceinline__ void mmabf(float c[4], const uint32_t a[4], const uint32_t b[2]){
    asm volatile("mma.sync.aligned.m16n8k16.row.col.f32.bf16.bf16.f32 "
      "{%0,%1,%2,%3}, {%4,%5,%6,%7}, {%8,%9}, {%0,%1,%2,%3};"
      : "+f"(c[0]), "+f"(c[1]), "+f"(c[2]), "+f"(c[3])
      : "r"(a[0]), "r"(a[1]), "r"(a[2]), "r"(a[3]), "r"(b[0]), "r"(b[1]));
}

// bf16 hi/lo split of a float pair, packed little-endian (even elem = low half)
__device__ __forceinline__ void split2(float a, float b, uint32_t& hw, uint32_t& lw){
    __nv_bfloat16 ah = __float2bfloat16(a), bh = __float2bfloat16(b);
    float ar = a - __bfloat162float(ah), br = b - __bfloat162float(bh);
    __nv_bfloat16 al = __float2bfloat16(ar), bl = __float2bfloat16(br);
    hw = ((uint32_t)__bfloat16_as_ushort(bh) << 16) | __bfloat16_as_ushort(ah);
    lw = ((uint32_t)__bfloat16_as_ushort(bl) << 16) | __bfloat16_as_ushort(al);
}

// smem byte offsets for k_attn
// Q: 128 rows x 272B (hi, lo).  K bufs: 64 rows x 272B (hi, lo).  V bufs: 128 rows x 144B (hi, lo).
#define QHS  0
#define QLS  34816
#define KB0  69632
#define KBSZ 34816        /* hi 17408 + lo 17408 */
#define VB0  139264
#define VBSZ 36864        /* hi 18432 + lo 18432 */
#define SM_ATTN 212992

// ============================================================================
// K1: Q/K/V projections (fp32 scalar) -> bf16 hi/lo split words.
// Q,K -> [b][n][c];  V -> [b][c][m] (transposed).
// ============================================================================
__global__ __launch_bounds__(256) void k_qkv(const float* __restrict__ x,
                                             const float* __restrict__ Wq,
                                             const float* __restrict__ Wk,
                                             const float* __restrict__ Wv)
{
    extern __shared__ float sm[];
    float* Wt = sm;               // [c][130]
    float* Xs = sm + 128*130;     // [c][64] during compute; [o][65] staging after

    const int n0  = blockIdx.x * TN;
    const int b   = blockIdx.y;
    const int z   = blockIdx.z;
    const float* W = (z == 0) ? Wq : ((z == 1) ? Wk : Wv);

    const int tid = threadIdx.x;
    const int tx  = tid & 15;
    const int ty  = tid >> 4;

    for (int idx = tid; idx < 128*64; idx += 256){
        int o  = idx >> 6;
        int cq = (idx & 63) << 1;
        float2 w = *(const float2*)(W + o*128 + cq);
        Wt[ cq   *130 + o] = w.x;
        Wt[(cq+1)*130 + o] = w.y;
    }
    const float* xb = x + (size_t)b*CH*NSP + n0;
    for (int idx = tid; idx < 128*16; idx += 256){
        int c = idx >> 4, u = (idx & 15) << 2;
        *(float4*)(Xs + c*64 + u) = *(const float4*)(xb + c*NSP + u);
    }
    __syncthreads();

    unsigned long long acc[4][4];
    #pragma unroll
    for (int i = 0; i < 4; i++)
        #pragma unroll
        for (int j = 0; j < 4; j++) acc[i][j] = 0ull;

    #pragma unroll 4
    for (int c = 0; c < 128; c++){
        unsigned long long wv[4]; float xn[4];
        #pragma unroll
        for (int j = 0; j < 4; j++)
            wv[j] = *(const unsigned long long*)(Wt + c*130 + 2*tx + 32*j);
        #pragma unroll
        for (int i = 0; i < 4; i++) xn[i] = Xs[c*64 + ty + 16*i];
        #pragma unroll
        for (int i = 0; i < 4; i++){
            unsigned long long xd = pk2(xn[i], xn[i]);
            #pragma unroll
            for (int j = 0; j < 4; j++) ffma2(acc[i][j], wv[j], xd);
        }
    }
    __syncthreads();

    float* St = Xs;  // [o][65]
    #pragma unroll
    for (int i = 0; i < 4; i++)
        #pragma unroll
        for (int j = 0; j < 4; j++){
            float a, bv; upk2(acc[i][j], a, bv);
            int o = 2*tx + 32*j, n = ty + 16*i;
            St[ o   *65 + n] = a;
            St[(o+1)*65 + n] = bv;
        }
    __syncthreads();

    if (z < 2){
        uint32_t* oh = (z == 0 ? g_Qh : g_Kh) + ((size_t)b*NSP + n0)*64;
        uint32_t* ol = (z == 0 ? g_Ql : g_Kl) + ((size_t)b*NSP + n0)*64;
        for (int idx = tid; idx < 64*64; idx += 256){
            int n = idx >> 6, cw = idx & 63;
            uint32_t hw, lw;
            split2(St[(2*cw)*65 + n], St[(2*cw+1)*65 + n], hw, lw);
            oh[n*64 + cw] = hw;
            ol[n*64 + cw] = lw;
        }
    } else {
        uint32_t* oh = g_Vh + (size_t)b*CH*2048 + (n0 >> 1);
        uint32_t* ol = g_Vl + (size_t)b*CH*2048 + (n0 >> 1);
        for (int idx = tid; idx < 128*32; idx += 256){
            int c = idx >> 5, mw = idx & 31;
            uint32_t hw, lw;
            split2(St[c*65 + 2*mw], St[c*65 + 2*mw + 1], hw, lw);
            oh[(size_t)c*2048 + mw] = hw;
            ol[(size_t)c*2048 + mw] = lw;
        }
    }
}

// ============================================================================
// K2: HMMA flash attention, unnormalized softmax (fixed shift), split-K.
// TK=64 tiles, double-buffered K and V, ONE __syncthreads per tile.
// Commit ladder: ..., K(t), V(t), K(t+1), V(t+1) ... ; consumers use wait_group 1.
// ============================================================================
__global__ __launch_bounds__(256) void k_attn()
{
    extern __shared__ char smc[];
    const uint32_t sb = smem_u32(smc);
    const int tid = threadIdx.x;
    const int wid = tid >> 5, lane = tid & 31;
    const int n0 = blockIdx.x * TQ;
    const int b  = blockIdx.y;
    const int sp = blockIdx.z;
    const int m_base = sp * (NSP/KSPLIT);

    const uint32_t* Qh = g_Qh + ((size_t)b*NSP + n0)*64;
    const uint32_t* Ql = g_Ql + ((size_t)b*NSP + n0)*64;
    const uint32_t* Kh = g_Kh + (size_t)b*NSP*64;
    const uint32_t* Kl = g_Kl + (size_t)b*NSP*64;
    const uint32_t* Vh = g_Vh + (size_t)b*CH*2048;
    const uint32_t* Vl = g_Vl + (size_t)b*CH*2048;

    // ---- prologue group 0: Q hi/lo + K(0) into K buf 0 ----
    for (int i = tid; i < 2048; i += 256){
        int r = i >> 4, q = i & 15;
        uint32_t so = (uint32_t)r*272 + q*16;
        cpa(sb + QHS + so, Qh + r*64 + q*4);
        cpa(sb + QLS + so, Ql + r*64 + q*4);
    }
    for (int i = tid; i < 1024; i += 256){
        int r = i >> 4, q = i & 15;
        uint32_t so = (uint32_t)r*272 + q*16;
        cpa(sb + KB0 + so,         Kh + (size_t)(m_base + r)*64 + q*4);
        cpa(sb + KB0 + 17408 + so, Kl + (size_t)(m_base + r)*64 + q*4);
    }
    CPA_COMMIT();
    // ---- prologue group 1: V(0) into V buf 0 ----
    for (int i = tid; i < 1024; i += 256){
        int r = i >> 3, q = i & 7;
        uint32_t so = (uint32_t)r*144 + q*16;
        cpa(sb + VB0 + so,         Vh + (size_t)r*2048 + (m_base >> 1) + q*4);
        cpa(sb + VB0 + 18432 + so, Vl + (size_t)r*2048 + (m_base >> 1) + q*4);
    }
    CPA_COMMIT();
    CPA_WAIT1();            // Q + K(0) ready (V(0) may still fly)
    __syncthreads();

    // fragment address bases (Q/K row stride 272B; V row stride 144B)
    const int arow = 16*wid + (lane & 7) + ((lane >> 3) & 1)*8;
    const uint32_t aoff = (uint32_t)arow*272 + ((lane >> 4) & 1)*16;
    const int brow = (lane & 7) + ((lane >> 4) & 1)*8;
    const uint32_t boff = ((lane >> 3) & 1)*16;

    // ---- cache Q_hi A-fragments for the whole kernel ----
    uint32_t qfh[8][4];
    #pragma unroll
    for (int k = 0; k < 8; k++) ldsm4(sb + QHS + aoff + k*32, qfh[k]);

    float oacc[16][4];
    #pragma unroll
    for (int i = 0; i < 16; i++)
        #pragma unroll
        for (int j = 0; j < 4; j++) oacc[i][j] = 0.f;
    float lsum0 = 0.f, lsum1 = 0.f;

    for (int t = 0; t < NT2; t++){
        const uint32_t kb = sb + KB0 + (uint32_t)(t & 1)*KBSZ;
        const uint32_t vb = sb + VB0 + (uint32_t)(t & 1)*VBSZ;

        // tile barrier: K(t) ready (wait done previous iteration / prologue)
        __syncthreads();

        // earliest possible K(t+1) prefetch (writes other K buf; readers passed barrier)
        if (t + 1 < NT2){
            const int m1 = m_base + (t + 1)*TKK;
            const uint32_t kn = sb + KB0 + (uint32_t)((t + 1) & 1)*KBSZ;
            for (int i = tid; i < 1024; i += 256){
                int r = i >> 4, q = i & 15;
                uint32_t so = (uint32_t)r*272 + q*16;
                cpa(kn + so,         Kh + (size_t)(m1 + r)*64 + q*4);
                cpa(kn + 17408 + so, Kl + (size_t)(m1 + r)*64 + q*4);
            }
            CPA_COMMIT();
        }

        // ---- S = Q K^T : B hi+lo loaded once per (k,jj), 3 split passes from regs ----
        float sacc[8][4];
        #pragma unroll
        for (int i = 0; i < 8; i++)
            #pragma unroll
            for (int j = 0; j < 4; j++) sacc[i][j] = 0.f;

        #pragma unroll
        for (int k = 0; k < 8; k++){
            uint32_t al[4];
            ldsm4(sb + QLS + aoff + k*32, al);
            #pragma unroll
            for (int jj = 0; jj < 4; jj++){
                uint32_t bh[4], bl[4];
                uint32_t ro = (uint32_t)(16*jj + brow)*272 + boff + k*32;
                ldsm4(kb + ro,         bh);
                ldsm4(kb + 17408 + ro, bl);
                mmabf(sacc[2*jj],     qfh[k], bh);
                mmabf(sacc[2*jj + 1], qfh[k], bh + 2);
                mmabf(sacc[2*jj],     qfh[k], bl);
                mmabf(sacc[2*jj + 1], qfh[k], bl + 2);
                mmabf(sacc[2*jj],     al,     bh);
                mmabf(sacc[2*jj + 1], al,     bh + 2);
            }
        }

        // ---- P = exp(S - SHIFT); pack into A-fragments (hi/lo) ----
        uint32_t pfh[4][4], pfl[4][4];
        #pragma unroll
        for (int j = 0; j < 8; j++){
            float p0 = __expf(sacc[j][0] - SHIFT);
            float p1 = __expf(sacc[j][1] - SHIFT);
            float p2 = __expf(sacc[j][2] - SHIFT);
            float p3 = __expf(sacc[j][3] - SHIFT);
            lsum0 += p0 + p1; lsum1 += p2 + p3;
            int jk = j >> 1, hv = (j & 1) << 1;
            split2(p0, p1, pfh[jk][hv],     pfl[jk][hv]);
            split2(p2, p3, pfh[jk][hv + 1], pfl[jk][hv + 1]);
        }

        // V(t) ready?  pending: {V(t), K(t+1)} -> wait 1;  last tile: wait 0
        if (t + 1 < NT2) { CPA_WAIT1(); } else { CPA_WAIT0(); }

        // earliest possible V(t+1) prefetch (writes other V buf)
        if (t + 1 < NT2){
            const int m1 = m_base + (t + 1)*TKK;
            const uint32_t vn = sb + VB0 + (uint32_t)((t + 1) & 1)*VBSZ;
            for (int i = tid; i < 1024; i += 256){
                int r = i >> 3, q = i & 7;
                uint32_t so = (uint32_t)r*144 + q*16;
                cpa(vn + so,         Vh + (size_t)r*2048 + (m1 >> 1) + q*4);
                cpa(vn + 18432 + so, Vl + (size_t)r*2048 + (m1 >> 1) + q*4);
            }
            CPA_COMMIT();
        }

        // ---- O += P V^T : B hi+lo loaded once per (k,jj), 3 split passes ----
        #pragma unroll
        for (int k = 0; k < 4; k++){
            #pragma unroll
            for (int jj = 0; jj < 8; jj++){
                uint32_t bh[4], bl[4];
                uint32_t ro = (uint32_t)(16*jj + brow)*144 + boff + k*32;
                ldsm4(vb + ro,         bh);
                ldsm4(vb + 18432 + ro, bl);
                mmabf(oacc[2*jj],     pfh[k], bh);
                mmabf(oacc[2*jj + 1], pfh[k], bh + 2);
                mmabf(oacc[2*jj],     pfh[k], bl);
                mmabf(oacc[2*jj + 1], pfh[k], bl + 2);
                mmabf(oacc[2*jj],     pfl[k], bh);
                mmabf(oacc[2*jj + 1], pfl[k], bh + 2);
            }
        }
    }

    // ---- epilogue: l per row, unnormalized O out ----
    #pragma unroll
    for (int d = 1; d < 4; d <<= 1){
        lsum0 += __shfl_xor_sync(0xffffffffu, lsum0, d);
        lsum1 += __shfl_xor_sync(0xffffffffu, lsum1, d);
    }
    const int g = lane >> 2, q = lane & 3;
    const int row = 16*wid + g;
    if (q == 0){
        size_t lb = ((size_t)sp*BATCH + b)*NSP + n0;
        g_lp[lb + row]     = lsum0;
        g_lp[lb + row + 8] = lsum1;
    }
    float* Ob = g_Op + (((size_t)sp*BATCH + b)*NSP + n0)*CH;
    #pragma unroll
    for (int tt = 0; tt < 16; tt++){
        int c = 8*tt + 2*q;
        *(float2*)(Ob + (size_t)row*CH + c)       = make_float2(oacc[tt][0], oacc[tt][1]);
        *(float2*)(Ob + (size_t)(row + 8)*CH + c) = make_float2(oacc[tt][2], oacc[tt][3]);
    }
}

// ============================================================================
// K3: combine splits, y = x + Wo @ h, per-(b,group) partial sums.
// ============================================================================
__global__ __launch_bounds__(256) void k_proj(const float* __restrict__ x,
                                              const float* __restrict__ Wo)
{
    extern __shared__ float sm[];
    __shared__ float rlS[64];
    float* Wt = sm;               // [c][130]
    float* HS = sm + 128*130;     // [n][129] compute; [o][65] staging

    const int n0 = blockIdx.x * TN;
    const int b  = blockIdx.y;
    const int tid = threadIdx.x;
    const int tx  = tid & 15;
    const int ty  = tid >> 4;

    if (tid < 64){
        float l0 = g_lp[((size_t)0*BATCH + b)*NSP + n0 + tid];
        float l1 = g_lp[((size_t)1*BATCH + b)*NSP + n0 + tid];
        rlS[tid] = 1.0f / (l0 + l1);
    }
    for (int idx = tid; idx < 128*64; idx += 256){
        int o  = idx >> 6;
        int cq = (idx & 63) << 1;
        float2 w = *(const float2*)(Wo + o*128 + cq);
        Wt[ cq   *130 + o] = w.x;
        Wt[(cq+1)*130 + o] = w.y;
    }
    __syncthreads();

    const float* O0 = g_Op + (((size_t)0*BATCH + b)*NSP + n0)*CH;
    const float* O1 = g_Op + (((size_t)1*BATCH + b)*NSP + n0)*CH;
    for (int idx = tid; idx < 64*128; idx += 256){
        int n = idx >> 7, c = idx & 127;
        HS[n*129 + c] = (O0[idx] + O1[idx]) * rlS[n];
    }
    __syncthreads();

    unsigned long long acc[4][4];
    #pragma unroll
    for (int i = 0; i < 4; i++)
        #pragma unroll
        for (int j = 0; j < 4; j++) acc[i][j] = 0ull;

    #pragma unroll 4
    for (int c = 0; c < 128; c++){
        unsigned long long wv[4]; float hv[4];
        #pragma unroll
        for (int j = 0; j < 4; j++)
            wv[j] = *(const unsigned long long*)(Wt + c*130 + 2*tx + 32*j);
        #pragma unroll
        for (int i = 0; i < 4; i++) hv[i] = HS[(ty + 16*i)*129 + c];
        #pragma unroll
        for (int i = 0; i < 4; i++){
            unsigned long long hd = pk2(hv[i], hv[i]);
            #pragma unroll
            for (int j = 0; j < 4; j++) ffma2(acc[i][j], wv[j], hd);
        }
    }
    __syncthreads();

    float* St = HS;  // [o][65]
    #pragma unroll
    for (int i = 0; i < 4; i++)
        #pragma unroll
        for (int j = 0; j < 4; j++){
            float a, bv; upk2(acc[i][j], a, bv);
            int o = 2*tx + 32*j, n = ty + 16*i;
            St[ o   *65 + n] = a;
            St[(o+1)*65 + n] = bv;
        }
    __syncthreads();

    const float* xb = x   + (size_t)b*CH*NSP + n0;
    float*       yb = g_Y + (size_t)b*CH*NSP + n0;
    const int w = tid >> 5, lane = tid & 31;
    float s1 = 0.f, s2 = 0.f;
    for (int k = 0; k < 32; k++){
        int e = w*1024 + k*32 + lane;
        int o = e >> 6, n = e & 63;
        float val = xb[o*NSP + n] + St[o*65 + n];
        yb[o*NSP + n] = val;
        s1 += val; s2 += val*val;
    }
    #pragma unroll
    for (int d = 16; d >= 1; d >>= 1){
        s1 += __shfl_xor_sync(0xffffffffu, s1, d);
        s2 += __shfl_xor_sync(0xffffffffu, s2, d);
    }
    if (lane == 0){
        float* p = g_part + ((size_t)(b*64 + blockIdx.x)*GROUPS + w)*2;
        p[0] = s1; p[1] = s2;
    }
}

// K4: GroupNorm + affine + SiLU, with fused (redundant, deterministic)
// per-block reduction of the 64 partial sums for this block's group.
__global__ __launch_bounds__(256) void k_norm(const float* __restrict__ gamma,
                                              const float* __restrict__ beta,
                                              float* __restrict__ out)
{
    __shared__ float sh_mean, sh_inv;
    const int tid = threadIdx.x;
    const int e0 = blockIdx.x << 10;        // 1024 elems per block
    const int b = e0 >> 19;
    const int c = (e0 >> 12) & 127;
    const int g = c >> 4;

    if (tid < 32){
        const float* p = g_part + ((size_t)(b*64)*GROUPS + g)*2;
        float s1 = p[(size_t)tid*GROUPS*2]     + p[(size_t)(tid+32)*GROUPS*2];
        float s2 = p[(size_t)tid*GROUPS*2 + 1] + p[(size_t)(tid+32)*GROUPS*2 + 1];
        #pragma unroll
        for (int d = 16; d >= 1; d >>= 1){
            s1 += __shfl_xor_sync(0xffffffffu, s1, d);
            s2 += __shfl_xor_sync(0xffffffffu, s2, d);
        }
        if (tid == 0){
            const float icnt = 1.0f / 65536.0f;
            float mean = s1 * icnt;
            float var  = s2 * icnt - mean*mean;
            sh_mean = mean;
            sh_inv  = rsqrtf(var + EPSV);
        }
    }
    __syncthreads();

    const float mean = sh_mean, inv = sh_inv;
    const float ga = gamma[c], be = beta[c];
    const int e = e0 + tid*4;
    float4 y = *(const float4*)(g_Y + e);
    float4 r;
    float t = (y.x - mean)*inv*ga + be; r.x = t / (1.0f + __expf(-t));
    t = (y.y - mean)*inv*ga + be;       r.y = t / (1.0f + __expf(-t));
    t = (y.z - mean)*inv*ga + be;       r.z = t / (1.0f + __expf(-t));
    t = (y.w - mean)*inv*ga + be;       r.w = t / (1.0f + __expf(-t));
    *(float4*)(out + e) = r;
}

// ============================================================================
extern "C" void kernel_launch(void* const* d_in, const int* in_sizes, int n_in,
                              void* d_out, int out_size)
{
    const float* x     = (const float*)d_in[0];
    const float* Wq    = (const float*)d_in[1];
    const float* Wk    = (const float*)d_in[2];
    const float* Wv    = (const float*)d_in[3];
    const float* Wo    = (const float*)d_in[4];
    const float* gamma = (const float*)d_in[5];
    const float* beta  = (const float*)d_in[6];
    float* out = (float*)d_out;

    const int SM1 = (128*130 + 128*65) * 4;
    const int SM3 = (128*130 + 128*65) * 4;

    cudaFuncSetAttribute(k_qkv,  cudaFuncAttributeMaxDynamicSharedMemorySize, SM1);
    cudaFuncSetAttribute(k_attn, cudaFuncAttributeMaxDynamicSharedMemorySize, SM_ATTN);
    cudaFuncSetAttribute(k_proj, cudaFuncAttributeMaxDynamicSharedMemorySize, SM3);

    k_qkv <<<dim3(NSP/TN, BATCH, 3),      256, SM1>>>(x, Wq, Wk, Wv);
    k_attn<<<dim3(NSP/TQ, BATCH, KSPLIT), 256, SM_ATTN>>>();
    k_proj<<<dim3(NSP/TN, BATCH),         256, SM3>>>(x, Wo);
    k_norm<<<(BATCH*CH*NSP)/(4*256), 256>>>(gamma, beta, out);
}

// round 10
// speedup vs baseline: 3.2805x; 1.1303x over previous
#include <cuda_runtime.h>
#include <cuda_bf16.h>
#include <cuda_fp16.h>
#include <math_constants.h>
#include <cstdint>

#define BATCH 2
#define CH    128
#define NSP   4096
#define GROUPS 8
#define TN    64
#define EPSV  1e-5f

// attention tiling
#define TQ     128
#define TKK    64
#define KSPLIT 2
#define NT2    (NSP/KSPLIT/TKK)   // 32
#define SHIFT  40.0f

// ---------------- scratch (static __device__, allocation-free) ----------------
__device__ uint32_t g_Qh[BATCH*NSP*64], g_Ql[BATCH*NSP*64];   // [b][n][cw] fp16x2 hi/lo
__device__ uint32_t g_K16[BATCH*NSP*64];                      // [b][m][cw] fp16x2 single
__device__ uint32_t g_Vh[BATCH*CH*2048], g_Vl[BATCH*CH*2048]; // [b][c][mw] bf16x2 (V^T)
__device__ float g_Op[KSPLIT*BATCH*NSP*CH];   // unnormalized O  [s][b][n][c]
__device__ float g_lp[KSPLIT*BATCH*NSP];      // exp-sums        [s][b][n]
__device__ float g_Y [BATCH*CH*NSP];
__device__ float g_part [BATCH*64*GROUPS*2];

// ---------------- f32x2 helpers ----------------
__device__ __forceinline__ unsigned long long pk2(float x, float y){
    unsigned long long r; asm("mov.b64 %0, {%1,%2};" : "=l"(r) : "f"(x), "f"(y)); return r;
}
__device__ __forceinline__ void upk2(unsigned long long v, float& x, float& y){
    asm("mov.b64 {%0,%1}, %2;" : "=f"(x), "=f"(y) : "l"(v));
}
__device__ __forceinline__ void ffma2(unsigned long long& d, unsigned long long a, unsigned long long b){
    asm("fma.rn.f32x2 %0, %1, %2, %0;" : "+l"(d) : "l"(a), "l"(b));
}

// ---------------- smem / mma / ldmatrix / cp.async helpers ----------------
__device__ __forceinline__ uint32_t smem_u32(const void* p){
    uint32_t a;
    asm("{ .reg .u64 t; cvta.to.shared.u64 t, %1; cvt.u32.u64 %0, t; }" : "=r"(a) : "l"(p));
    return a;
}
__device__ __forceinline__ void cpa(uint32_t saddr, const void* g){
    asm volatile("cp.async.ca.shared.global [%0], [%1], 16;" :: "r"(saddr), "l"(g) : "memory");
}
#define CPA_COMMIT() asm volatile("cp.async.commit_group;" ::: "memory")
#define CPA_WAIT0()  asm volatile("cp.async.wait_group 0;" ::: "memory")
#define CPA_WAIT1()  asm volatile("cp.async.wait_group 1;" ::: "memory")

__device__ __forceinline__ void ldsm4(uint32_t a, uint32_t r[4]){
    asm volatile("ldmatrix.sync.aligned.m8n8.x4.shared.b16 {%0,%1,%2,%3}, [%4];"
      : "=r"(r[0]), "=r"(r[1]), "=r"(r[2]), "=r"(r[3]) : "r"(a));
}
// bf16 mma (PV path)
__device__ __forceinline__ void mmabf(float c[4], const uint32_t a[4], const uint32_t b[2]){
    asm volatile("mma.sync.aligned.m16n8k16.row.col.f32.bf16.bf16.f32 "
      "{%0,%1,%2,%3}, {%4,%5,%6,%7}, {%8,%9}, {%0,%1,%2,%3};"
      : "+f"(c[0]), "+f"(c[1]), "+f"(c[2]), "+f"(c[3])
      : "r"(a[0]), "r"(a[1]), "r"(a[2]), "r"(a[3]), "r"(b[0]), "r"(b[1]));
}
// fp16 mma (QK path)
__device__ __forceinline__ void mmah(float c[4], const uint32_t a[4], const uint32_t b[2]){
    asm volatile("mma.sync.aligned.m16n8k16.row.col.f32.f16.f16.f32 "
      "{%0,%1,%2,%3}, {%4,%5,%6,%7}, {%8,%9}, {%0,%1,%2,%3};"
      : "+f"(c[0]), "+f"(c[1]), "+f"(c[2]), "+f"(c[3])
      : "r"(a[0]), "r"(a[1]), "r"(a[2]), "r"(a[3]), "r"(b[0]), "r"(b[1]));
}

// bf16 hi/lo split of a float pair (PV path)
__device__ __forceinline__ void split2(float a, float b, uint32_t& hw, uint32_t& lw){
    __nv_bfloat16 ah = __float2bfloat16(a), bh = __float2bfloat16(b);
    float ar = a - __bfloat162float(ah), br = b - __bfloat162float(bh);
    __nv_bfloat16 al = __float2bfloat16(ar), bl = __float2bfloat16(br);
    hw = ((uint32_t)__bfloat16_as_ushort(bh) << 16) | __bfloat16_as_ushort(ah);
    lw = ((uint32_t)__bfloat16_as_ushort(bl) << 16) | __bfloat16_as_ushort(al);
}
// fp16 hi/lo split of a float pair
__device__ __forceinline__ void split2h(float a, float b, uint32_t& hw, uint32_t& lw){
    __half ah = __float2half_rn(a), bh = __float2half_rn(b);
    float ar = a - __half2float(ah), br = b - __half2float(bh);
    __half al = __float2half_rn(ar), bl = __float2half_rn(br);
    hw = ((uint32_t)__half_as_ushort(bh) << 16) | __half_as_ushort(ah);
    lw = ((uint32_t)__half_as_ushort(bl) << 16) | __half_as_ushort(al);
}
// single fp16 pack of a float pair
__device__ __forceinline__ uint32_t packh2(float a, float b){
    __half2 h = __floats2half2_rn(a, b);
    return *reinterpret_cast<uint32_t*>(&h);
}

// smem byte offsets for k_attn
// Q: 128 rows x 272B (hi, lo).  K bufs: 64 rows x 272B (single fp16).  V bufs: 128 rows x 144B (hi, lo).
#define QHS  0
#define QLS  34816
#define KB0  69632
#define KBSZ 17408
#define VB0  104448
#define VBSZ 36864        /* hi 18432 + lo 18432 */
#define SM_ATTN 178176

// ============================================================================
// K1: Q/K/V projections (fp32 scalar).
// Q -> fp16 hi/lo [b][n][c];  K -> single fp16 [b][m][c];  V -> bf16 hi/lo [b][c][m].
// ============================================================================
__global__ __launch_bounds__(256) void k_qkv(const float* __restrict__ x,
                                             const float* __restrict__ Wq,
                                             const float* __restrict__ Wk,
                                             const float* __restrict__ Wv)
{
    extern __shared__ float sm[];
    float* Wt = sm;               // [c][130]
    float* Xs = sm + 128*130;     // [c][64] during compute; [o][65] staging after

    const int n0  = blockIdx.x * TN;
    const int b   = blockIdx.y;
    const int z   = blockIdx.z;
    const float* W = (z == 0) ? Wq : ((z == 1) ? Wk : Wv);

    const int tid = threadIdx.x;
    const int tx  = tid & 15;
    const int ty  = tid >> 4;

    for (int idx = tid; idx < 128*64; idx += 256){
        int o  = idx >> 6;
        int cq = (idx & 63) << 1;
        float2 w = *(const float2*)(W + o*128 + cq);
        Wt[ cq   *130 + o] = w.x;
        Wt[(cq+1)*130 + o] = w.y;
    }
    const float* xb = x + (size_t)b*CH*NSP + n0;
    for (int idx = tid; idx < 128*16; idx += 256){
        int c = idx >> 4, u = (idx & 15) << 2;
        *(float4*)(Xs + c*64 + u) = *(const float4*)(xb + c*NSP + u);
    }
    __syncthreads();

    unsigned long long acc[4][4];
    #pragma unroll
    for (int i = 0; i < 4; i++)
        #pragma unroll
        for (int j = 0; j < 4; j++) acc[i][j] = 0ull;

    #pragma unroll 4
    for (int c = 0; c < 128; c++){
        unsigned long long wv[4]; float xn[4];
        #pragma unroll
        for (int j = 0; j < 4; j++)
            wv[j] = *(const unsigned long long*)(Wt + c*130 + 2*tx + 32*j);
        #pragma unroll
        for (int i = 0; i < 4; i++) xn[i] = Xs[c*64 + ty + 16*i];
        #pragma unroll
        for (int i = 0; i < 4; i++){
            unsigned long long xd = pk2(xn[i], xn[i]);
            #pragma unroll
            for (int j = 0; j < 4; j++) ffma2(acc[i][j], wv[j], xd);
        }
    }
    __syncthreads();

    float* St = Xs;  // [o][65]
    #pragma unroll
    for (int i = 0; i < 4; i++)
        #pragma unroll
        for (int j = 0; j < 4; j++){
            float a, bv; upk2(acc[i][j], a, bv);
            int o = 2*tx + 32*j, n = ty + 16*i;
            St[ o   *65 + n] = a;
            St[(o+1)*65 + n] = bv;
        }
    __syncthreads();

    if (z == 0){
        uint32_t* oh = g_Qh + ((size_t)b*NSP + n0)*64;
        uint32_t* ol = g_Ql + ((size_t)b*NSP + n0)*64;
        for (int idx = tid; idx < 64*64; idx += 256){
            int n = idx >> 6, cw = idx & 63;
            uint32_t hw, lw;
            split2h(St[(2*cw)*65 + n], St[(2*cw+1)*65 + n], hw, lw);
            oh[n*64 + cw] = hw;
            ol[n*64 + cw] = lw;
        }
    } else if (z == 1){
        uint32_t* ok = g_K16 + ((size_t)b*NSP + n0)*64;
        for (int idx = tid; idx < 64*64; idx += 256){
            int n = idx >> 6, cw = idx & 63;
            ok[n*64 + cw] = packh2(St[(2*cw)*65 + n], St[(2*cw+1)*65 + n]);
        }
    } else {
        uint32_t* oh = g_Vh + (size_t)b*CH*2048 + (n0 >> 1);
        uint32_t* ol = g_Vl + (size_t)b*CH*2048 + (n0 >> 1);
        for (int idx = tid; idx < 128*32; idx += 256){
            int c = idx >> 5, mw = idx & 31;
            uint32_t hw, lw;
            split2(St[c*65 + 2*mw], St[c*65 + 2*mw + 1], hw, lw);
            oh[(size_t)c*2048 + mw] = hw;
            ol[(size_t)c*2048 + mw] = lw;
        }
    }
}

// ============================================================================
// K2: HMMA flash attention, unnormalized softmax (fixed shift), split-K.
// QK^T: fp16 2-pass (Qh+Ql)*K16.  PV^T: bf16 3-pass.
// TK=64 tiles, double-buffered K and V, one __syncthreads per tile.
// ============================================================================
__global__ __launch_bounds__(256) void k_attn()
{
    extern __shared__ char smc[];
    const uint32_t sb = smem_u32(smc);
    const int tid = threadIdx.x;
    const int wid = tid >> 5, lane = tid & 31;
    const int n0 = blockIdx.x * TQ;
    const int b  = blockIdx.y;
    const int sp = blockIdx.z;
    const int m_base = sp * (NSP/KSPLIT);

    const uint32_t* Qh  = g_Qh  + ((size_t)b*NSP + n0)*64;
    const uint32_t* Ql  = g_Ql  + ((size_t)b*NSP + n0)*64;
    const uint32_t* K16 = g_K16 + (size_t)b*NSP*64;
    const uint32_t* Vh  = g_Vh  + (size_t)b*CH*2048;
    const uint32_t* Vl  = g_Vl  + (size_t)b*CH*2048;

    // ---- prologue group 0: Q hi/lo + K(0) into K buf 0 ----
    for (int i = tid; i < 2048; i += 256){
        int r = i >> 4, q = i & 15;
        uint32_t so = (uint32_t)r*272 + q*16;
        cpa(sb + QHS + so, Qh + r*64 + q*4);
        cpa(sb + QLS + so, Ql + r*64 + q*4);
    }
    for (int i = tid; i < 1024; i += 256){
        int r = i >> 4, q = i & 15;
        uint32_t so = (uint32_t)r*272 + q*16;
        cpa(sb + KB0 + so, K16 + (size_t)(m_base + r)*64 + q*4);
    }
    CPA_COMMIT();
    // ---- prologue group 1: V(0) into V buf 0 ----
    for (int i = tid; i < 1024; i += 256){
        int r = i >> 3, q = i & 7;
        uint32_t so = (uint32_t)r*144 + q*16;
        cpa(sb + VB0 + so,         Vh + (size_t)r*2048 + (m_base >> 1) + q*4);
        cpa(sb + VB0 + 18432 + so, Vl + (size_t)r*2048 + (m_base >> 1) + q*4);
    }
    CPA_COMMIT();
    CPA_WAIT1();            // Q + K(0) ready (V(0) may still fly)
    __syncthreads();

    // fragment address bases (Q/K row stride 272B; V row stride 144B)
    const int arow = 16*wid + (lane & 7) + ((lane >> 3) & 1)*8;
    const uint32_t aoff = (uint32_t)arow*272 + ((lane >> 4) & 1)*16;
    const int brow = (lane & 7) + ((lane >> 4) & 1)*8;
    const uint32_t boff = ((lane >> 3) & 1)*16;

    // ---- cache Q_hi A-fragments for the whole kernel ----
    uint32_t qfh[8][4];
    #pragma unroll
    for (int k = 0; k < 8; k++) ldsm4(sb + QHS + aoff + k*32, qfh[k]);

    float oacc[16][4];
    #pragma unroll
    for (int i = 0; i < 16; i++)
        #pragma unroll
        for (int j = 0; j < 4; j++) oacc[i][j] = 0.f;
    float lsum0 = 0.f, lsum1 = 0.f;

    for (int t = 0; t < NT2; t++){
        const uint32_t kb = sb + KB0 + (uint32_t)(t & 1)*KBSZ;
        const uint32_t vb = sb + VB0 + (uint32_t)(t & 1)*VBSZ;

        // tile barrier: K(t) ready (wait done previous iteration / prologue)
        __syncthreads();

        // earliest possible K(t+1) prefetch (writes other K buf; readers passed barrier)
        if (t + 1 < NT2){
            const int m1 = m_base + (t + 1)*TKK;
            const uint32_t kn = sb + KB0 + (uint32_t)((t + 1) & 1)*KBSZ;
            for (int i = tid; i < 1024; i += 256){
                int r = i >> 4, q = i & 15;
                uint32_t so = (uint32_t)r*272 + q*16;
                cpa(kn + so, K16 + (size_t)(m1 + r)*64 + q*4);
            }
            CPA_COMMIT();
        }

        // ---- S = Q K^T : fp16, 2 passes (Qh*K + Ql*K), B loaded once ----
        float sacc[8][4];
        #pragma unroll
        for (int i = 0; i < 8; i++)
            #pragma unroll
            for (int j = 0; j < 4; j++) sacc[i][j] = 0.f;

        #pragma unroll
        for (int k = 0; k < 8; k++){
            uint32_t al[4];
            ldsm4(sb + QLS + aoff + k*32, al);
            #pragma unroll
            for (int jj = 0; jj < 4; jj++){
                uint32_t bh[4];
                uint32_t ro = (uint32_t)(16*jj + brow)*272 + boff + k*32;
                ldsm4(kb + ro, bh);
                mmah(sacc[2*jj],     qfh[k], bh);
                mmah(sacc[2*jj + 1], qfh[k], bh + 2);
                mmah(sacc[2*jj],     al,     bh);
                mmah(sacc[2*jj + 1], al,     bh + 2);
            }
        }

        // ---- P = exp(S - SHIFT); pack into bf16 A-fragments (hi/lo) ----
        uint32_t pfh[4][4], pfl[4][4];
        #pragma unroll
        for (int j = 0; j < 8; j++){
            float p0 = __expf(sacc[j][0] - SHIFT);
            float p1 = __expf(sacc[j][1] - SHIFT);
            float p2 = __expf(sacc[j][2] - SHIFT);
            float p3 = __expf(sacc[j][3] - SHIFT);
            lsum0 += p0 + p1; lsum1 += p2 + p3;
            int jk = j >> 1, hv = (j & 1) << 1;
            split2(p0, p1, pfh[jk][hv],     pfl[jk][hv]);
            split2(p2, p3, pfh[jk][hv + 1], pfl[jk][hv + 1]);
        }

        // V(t) ready?  pending: {V(t), K(t+1)} -> wait 1;  last tile: wait 0
        if (t + 1 < NT2) { CPA_WAIT1(); } else { CPA_WAIT0(); }

        // earliest possible V(t+1) prefetch (writes other V buf)
        if (t + 1 < NT2){
            const int m1 = m_base + (t + 1)*TKK;
            const uint32_t vn = sb + VB0 + (uint32_t)((t + 1) & 1)*VBSZ;
            for (int i = tid; i < 1024; i += 256){
                int r = i >> 3, q = i & 7;
                uint32_t so = (uint32_t)r*144 + q*16;
                cpa(vn + so,         Vh + (size_t)r*2048 + (m1 >> 1) + q*4);
                cpa(vn + 18432 + so, Vl + (size_t)r*2048 + (m1 >> 1) + q*4);
            }
            CPA_COMMIT();
        }

        // ---- O += P V^T : bf16, 3 passes, B hi+lo loaded once per (k,jj) ----
        #pragma unroll
        for (int k = 0; k < 4; k++){
            #pragma unroll
            for (int jj = 0; jj < 8; jj++){
                uint32_t bh[4], bl[4];
                uint32_t ro = (uint32_t)(16*jj + brow)*144 + boff + k*32;
                ldsm4(vb + ro,         bh);
                ldsm4(vb + 18432 + ro, bl);
                mmabf(oacc[2*jj],     pfh[k], bh);
                mmabf(oacc[2*jj + 1], pfh[k], bh + 2);
                mmabf(oacc[2*jj],     pfh[k], bl);
                mmabf(oacc[2*jj + 1], pfh[k], bl + 2);
                mmabf(oacc[2*jj],     pfl[k], bh);
                mmabf(oacc[2*jj + 1], pfl[k], bh + 2);
            }
        }
    }

    // ---- epilogue: l per row, unnormalized O out ----
    #pragma unroll
    for (int d = 1; d < 4; d <<= 1){
        lsum0 += __shfl_xor_sync(0xffffffffu, lsum0, d);
        lsum1 += __shfl_xor_sync(0xffffffffu, lsum1, d);
    }
    const int g = lane >> 2, q = lane & 3;
    const int row = 16*wid + g;
    if (q == 0){
        size_t lb = ((size_t)sp*BATCH + b)*NSP + n0;
        g_lp[lb + row]     = lsum0;
        g_lp[lb + row + 8] = lsum1;
    }
    float* Ob = g_Op + (((size_t)sp*BATCH + b)*NSP + n0)*CH;
    #pragma unroll
    for (int tt = 0; tt < 16; tt++){
        int c = 8*tt + 2*q;
        *(float2*)(Ob + (size_t)row*CH + c)       = make_float2(oacc[tt][0], oacc[tt][1]);
        *(float2*)(Ob + (size_t)(row + 8)*CH + c) = make_float2(oacc[tt][2], oacc[tt][3]);
    }
}

// ============================================================================
// K3: combine splits, y = x + Wo @ h, per-(b,group) partial sums.
// ============================================================================
__global__ __launch_bounds__(256) void k_proj(const float* __restrict__ x,
                                              const float* __restrict__ Wo)
{
    extern __shared__ float sm[];
    __shared__ float rlS[64];
    float* Wt = sm;               // [c][130]
    float* HS = sm + 128*130;     // [n][129] compute; [o][65] staging

    const int n0 = blockIdx.x * TN;
    const int b  = blockIdx.y;
    const int tid = threadIdx.x;
    const int tx  = tid & 15;
    const int ty  = tid >> 4;

    if (tid < 64){
        float l0 = g_lp[((size_t)0*BATCH + b)*NSP + n0 + tid];
        float l1 = g_lp[((size_t)1*BATCH + b)*NSP + n0 + tid];
        rlS[tid] = 1.0f / (l0 + l1);
    }
    for (int idx = tid; idx < 128*64; idx += 256){
        int o  = idx >> 6;
        int cq = (idx & 63) << 1;
        float2 w = *(const float2*)(Wo + o*128 + cq);
        Wt[ cq   *130 + o] = w.x;
        Wt[(cq+1)*130 + o] = w.y;
    }
    __syncthreads();

    const float* O0 = g_Op + (((size_t)0*BATCH + b)*NSP + n0)*CH;
    const float* O1 = g_Op + (((size_t)1*BATCH + b)*NSP + n0)*CH;
    for (int idx = tid; idx < 64*128; idx += 256){
        int n = idx >> 7, c = idx & 127;
        HS[n*129 + c] = (O0[idx] + O1[idx]) * rlS[n];
    }
    __syncthreads();

    unsigned long long acc[4][4];
    #pragma unroll
    for (int i = 0; i < 4; i++)
        #pragma unroll
        for (int j = 0; j < 4; j++) acc[i][j] = 0ull;

    #pragma unroll 4
    for (int c = 0; c < 128; c++){
        unsigned long long wv[4]; float hv[4];
        #pragma unroll
        for (int j = 0; j < 4; j++)
            wv[j] = *(const unsigned long long*)(Wt + c*130 + 2*tx + 32*j);
        #pragma unroll
        for (int i = 0; i < 4; i++) hv[i] = HS[(ty + 16*i)*129 + c];
        #pragma unroll
        for (int i = 0; i < 4; i++){
            unsigned long long hd = pk2(hv[i], hv[i]);
            #pragma unroll
            for (int j = 0; j < 4; j++) ffma2(acc[i][j], wv[j], hd);
        }
    }
    __syncthreads();

    float* St = HS;  // [o][65]
    #pragma unroll
    for (int i = 0; i < 4; i++)
        #pragma unroll
        for (int j = 0; j < 4; j++){
            float a, bv; upk2(acc[i][j], a, bv);
            int o = 2*tx + 32*j, n = ty + 16*i;
            St[ o   *65 + n] = a;
            St[(o+1)*65 + n] = bv;
        }
    __syncthreads();

    const float* xb = x   + (size_t)b*CH*NSP + n0;
    float*       yb = g_Y + (size_t)b*CH*NSP + n0;
    const int w = tid >> 5, lane = tid & 31;
    float s1 = 0.f, s2 = 0.f;
    for (int k = 0; k < 32; k++){
        int e = w*1024 + k*32 + lane;
        int o = e >> 6, n = e & 63;
        float val = xb[o*NSP + n] + St[o*65 + n];
        yb[o*NSP + n] = val;
        s1 += val; s2 += val*val;
    }
    #pragma unroll
    for (int d = 16; d >= 1; d >>= 1){
        s1 += __shfl_xor_sync(0xffffffffu, s1, d);
        s2 += __shfl_xor_sync(0xffffffffu, s2, d);
    }
    if (lane == 0){
        float* p = g_part + ((size_t)(b*64 + blockIdx.x)*GROUPS + w)*2;
        p[0] = s1; p[1] = s2;
    }
}

// K4: GroupNorm + affine + SiLU, with fused (redundant, deterministic)
// per-block reduction of the 64 partial sums for this block's group.
__global__ __launch_bounds__(256) void k_norm(const float* __restrict__ gamma,
                                              const float* __restrict__ beta,
                                              float* __restrict__ out)
{
    __shared__ float sh_mean, sh_inv;
    const int tid = threadIdx.x;
    const int e0 = blockIdx.x << 10;        // 1024 elems per block
    const int b = e0 >> 19;
    const int c = (e0 >> 12) & 127;
    const int g = c >> 4;

    if (tid < 32){
        const float* p = g_part + ((size_t)(b*64)*GROUPS + g)*2;
        float s1 = p[(size_t)tid*GROUPS*2]     + p[(size_t)(tid+32)*GROUPS*2];
        float s2 = p[(size_t)tid*GROUPS*2 + 1] + p[(size_t)(tid+32)*GROUPS*2 + 1];
        #pragma unroll
        for (int d = 16; d >= 1; d >>= 1){
            s1 += __shfl_xor_sync(0xffffffffu, s1, d);
            s2 += __shfl_xor_sync(0xffffffffu, s2, d);
        }
        if (tid == 0){
            const float icnt = 1.0f / 65536.0f;
            float mean = s1 * icnt;
            float var  = s2 * icnt - mean*mean;
            sh_mean = mean;
            sh_inv  = rsqrtf(var + EPSV);
        }
    }
    __syncthreads();

    const float mean = sh_mean, inv = sh_inv;
    const float ga = gamma[c], be = beta[c];
    const int e = e0 + tid*4;
    float4 y = *(const float4*)(g_Y + e);
    float4 r;
    float t = (y.x - mean)*inv*ga + be; r.x = t / (1.0f + __expf(-t));
    t = (y.y - mean)*inv*ga + be;       r.y = t / (1.0f + __expf(-t));
    t = (y.z - mean)*inv*ga + be;       r.z = t / (1.0f + __expf(-t));
    t = (y.w - mean)*inv*ga + be;       r.w = t / (1.0f + __expf(-t));
    *(float4*)(out + e) = r;
}

// ============================================================================
extern "C" void kernel_launch(void* const* d_in, const int* in_sizes, int n_in,
                              void* d_out, int out_size)
{
    const float* x     = (const float*)d_in[0];
    const float* Wq    = (const float*)d_in[1];
    const float* Wk    = (const float*)d_in[2];
    const float* Wv    = (const float*)d_in[3];
    const float* Wo    = (const float*)d_in[4];
    const float* gamma = (const float*)d_in[5];
    const float* beta  = (const float*)d_in[6];
    float* out = (float*)d_out;

    const int SM1 = (128*130 + 128*65) * 4;
    const int SM3 = (128*130 + 128*65) * 4;

    cudaFuncSetAttribute(k_qkv,  cudaFuncAttributeMaxDynamicSharedMemorySize, SM1);
    cudaFuncSetAttribute(k_attn, cudaFuncAttributeMaxDynamicSharedMemorySize, SM_ATTN);
    cudaFuncSetAttribute(k_proj, cudaFuncAttributeMaxDynamicSharedMemorySize, SM3);

    k_qkv <<<dim3(NSP/TN, BATCH, 3),      256, SM1>>>(x, Wq, Wk, Wv);
    k_attn<<<dim3(NSP/TQ, BATCH, KSPLIT), 256, SM_ATTN>>>();
    k_proj<<<dim3(NSP/TN, BATCH),         256, SM3>>>(x, Wo);
    k_norm<<<(BATCH*CH*NSP)/(4*256), 256>>>(gamma, beta, out);
}

// round 11
// speedup vs baseline: 3.7004x; 1.1280x over previous
#include <cuda_runtime.h>
#include <cuda_bf16.h>
#include <cuda_fp16.h>
#include <math_constants.h>
#include <cstdint>

#define BATCH 2
#define CH    128
#define NSP   4096
#define GROUPS 8
#define TN    64
#define EPSV  1e-5f

// attention tiling
#define TQ     128
#define TKK    64
#define KSPLIT 2
#define NT2    (NSP/KSPLIT/TKK)   // 32

// ---------------- scratch (static __device__, allocation-free) ----------------
__device__ uint32_t g_Qh[BATCH*NSP*64], g_Ql[BATCH*NSP*64];   // [b][n][cw] fp16x2 hi/lo
__device__ uint32_t g_K16[BATCH*NSP*64];                      // [b][m][cw] fp16x2 single
__device__ uint32_t g_V16[BATCH*CH*2048];                     // [b][c][mw] fp16x2 single (V^T)
__device__ float g_Op[KSPLIT*BATCH*NSP*CH];   // unnormalized O  [s][b][n][c]
__device__ float g_lp[KSPLIT*BATCH*NSP];      // exp-sums        [s][b][n]
__device__ float g_mx[KSPLIT*BATCH*NSP];      // row maxes       [s][b][n]
__device__ float g_Y [BATCH*CH*NSP];
__device__ float g_part [BATCH*64*GROUPS*2];

// ---------------- f32x2 helpers ----------------
__device__ __forceinline__ unsigned long long pk2(float x, float y){
    unsigned long long r; asm("mov.b64 %0, {%1,%2};" : "=l"(r) : "f"(x), "f"(y)); return r;
}
__device__ __forceinline__ void upk2(unsigned long long v, float& x, float& y){
    asm("mov.b64 {%0,%1}, %2;" : "=f"(x), "=f"(y) : "l"(v));
}
__device__ __forceinline__ void ffma2(unsigned long long& d, unsigned long long a, unsigned long long b){
    asm("fma.rn.f32x2 %0, %1, %2, %0;" : "+l"(d) : "l"(a), "l"(b));
}

// ---------------- smem / mma / ldmatrix / cp.async helpers ----------------
__device__ __forceinline__ uint32_t smem_u32(const void* p){
    uint32_t a;
    asm("{ .reg .u64 t; cvta.to.shared.u64 t, %1; cvt.u32.u64 %0, t; }" : "=r"(a) : "l"(p));
    return a;
}
__device__ __forceinline__ void cpa(uint32_t saddr, const void* g){
    asm volatile("cp.async.ca.shared.global [%0], [%1], 16;" :: "r"(saddr), "l"(g) : "memory");
}
#define CPA_COMMIT() asm volatile("cp.async.commit_group;" ::: "memory")
#define CPA_WAIT0()  asm volatile("cp.async.wait_group 0;" ::: "memory")
#define CPA_WAIT1()  asm volatile("cp.async.wait_group 1;" ::: "memory")

__device__ __forceinline__ void ldsm4(uint32_t a, uint32_t r[4]){
    asm volatile("ldmatrix.sync.aligned.m8n8.x4.shared.b16 {%0,%1,%2,%3}, [%4];"
      : "=r"(r[0]), "=r"(r[1]), "=r"(r[2]), "=r"(r[3]) : "r"(a));
}
// fp16 mma
__device__ __forceinline__ void mmah(float c[4], const uint32_t a[4], const uint32_t b[2]){
    asm volatile("mma.sync.aligned.m16n8k16.row.col.f32.f16.f16.f32 "
      "{%0,%1,%2,%3}, {%4,%5,%6,%7}, {%8,%9}, {%0,%1,%2,%3};"
      : "+f"(c[0]), "+f"(c[1]), "+f"(c[2]), "+f"(c[3])
      : "r"(a[0]), "r"(a[1]), "r"(a[2]), "r"(a[3]), "r"(b[0]), "r"(b[1]));
}

// fp16 hi/lo split of a float pair
__device__ __forceinline__ void split2h(float a, float b, uint32_t& hw, uint32_t& lw){
    __half ah = __float2half_rn(a), bh = __float2half_rn(b);
    float ar = a - __half2float(ah), br = b - __half2float(bh);
    __half al = __float2half_rn(ar), bl = __float2half_rn(br);
    hw = ((uint32_t)__half_as_ushort(bh) << 16) | __half_as_ushort(ah);
    lw = ((uint32_t)__half_as_ushort(bl) << 16) | __half_as_ushort(al);
}
// single fp16 pack of a float pair
__device__ __forceinline__ uint32_t packh2(float a, float b){
    __half2 h = __floats2half2_rn(a, b);
    return *reinterpret_cast<uint32_t*>(&h);
}

// smem byte offsets for k_attn
// Q: 128 rows x 272B (hi, lo).  K bufs: 64 rows x 272B.  V bufs: 128 rows x 144B.
#define QHS  0
#define QLS  34816
#define KB0  69632
#define KBSZ 17408
#define VB0  104448
#define VBSZ 18432
#define SM_ATTN 141312

// ============================================================================
// K1: Q/K/V projections (fp32 scalar).
// Q -> fp16 hi/lo [b][n][c];  K -> single fp16 [b][m][c];  V -> single fp16 [b][c][m].
// ============================================================================
__global__ __launch_bounds__(256) void k_qkv(const float* __restrict__ x,
                                             const float* __restrict__ Wq,
                                             const float* __restrict__ Wk,
                                             const float* __restrict__ Wv)
{
    extern __shared__ float sm[];
    float* Wt = sm;               // [c][130]
    float* Xs = sm + 128*130;     // [c][64] during compute; [o][65] staging after

    const int n0  = blockIdx.x * TN;
    const int b   = blockIdx.y;
    const int z   = blockIdx.z;
    const float* W = (z == 0) ? Wq : ((z == 1) ? Wk : Wv);

    const int tid = threadIdx.x;
    const int tx  = tid & 15;
    const int ty  = tid >> 4;

    for (int idx = tid; idx < 128*64; idx += 256){
        int o  = idx >> 6;
        int cq = (idx & 63) << 1;
        float2 w = *(const float2*)(W + o*128 + cq);
        Wt[ cq   *130 + o] = w.x;
        Wt[(cq+1)*130 + o] = w.y;
    }
    const float* xb = x + (size_t)b*CH*NSP + n0;
    for (int idx = tid; idx < 128*16; idx += 256){
        int c = idx >> 4, u = (idx & 15) << 2;
        *(float4*)(Xs + c*64 + u) = *(const float4*)(xb + c*NSP + u);
    }
    __syncthreads();

    unsigned long long acc[4][4];
    #pragma unroll
    for (int i = 0; i < 4; i++)
        #pragma unroll
        for (int j = 0; j < 4; j++) acc[i][j] = 0ull;

    #pragma unroll 4
    for (int c = 0; c < 128; c++){
        unsigned long long wv[4]; float xn[4];
        #pragma unroll
        for (int j = 0; j < 4; j++)
            wv[j] = *(const unsigned long long*)(Wt + c*130 + 2*tx + 32*j);
        #pragma unroll
        for (int i = 0; i < 4; i++) xn[i] = Xs[c*64 + ty + 16*i];
        #pragma unroll
        for (int i = 0; i < 4; i++){
            unsigned long long xd = pk2(xn[i], xn[i]);
            #pragma unroll
            for (int j = 0; j < 4; j++) ffma2(acc[i][j], wv[j], xd);
        }
    }
    __syncthreads();

    float* St = Xs;  // [o][65]
    #pragma unroll
    for (int i = 0; i < 4; i++)
        #pragma unroll
        for (int j = 0; j < 4; j++){
            float a, bv; upk2(acc[i][j], a, bv);
            int o = 2*tx + 32*j, n = ty + 16*i;
            St[ o   *65 + n] = a;
            St[(o+1)*65 + n] = bv;
        }
    __syncthreads();

    if (z == 0){
        uint32_t* oh = g_Qh + ((size_t)b*NSP + n0)*64;
        uint32_t* ol = g_Ql + ((size_t)b*NSP + n0)*64;
        for (int idx = tid; idx < 64*64; idx += 256){
            int n = idx >> 6, cw = idx & 63;
            uint32_t hw, lw;
            split2h(St[(2*cw)*65 + n], St[(2*cw+1)*65 + n], hw, lw);
            oh[n*64 + cw] = hw;
            ol[n*64 + cw] = lw;
        }
    } else if (z == 1){
        uint32_t* ok = g_K16 + ((size_t)b*NSP + n0)*64;
        for (int idx = tid; idx < 64*64; idx += 256){
            int n = idx >> 6, cw = idx & 63;
            ok[n*64 + cw] = packh2(St[(2*cw)*65 + n], St[(2*cw+1)*65 + n]);
        }
    } else {
        uint32_t* ov = g_V16 + (size_t)b*CH*2048 + (n0 >> 1);
        for (int idx = tid; idx < 128*32; idx += 256){
            int c = idx >> 5, mw = idx & 31;
            ov[(size_t)c*2048 + mw] = packh2(St[c*65 + 2*mw], St[c*65 + 2*mw + 1]);
        }
    }
}

// ============================================================================
// K2: HMMA flash attention, online softmax (per-row running max), split-K.
// QK^T: fp16 2-pass (Qh+Ql)*K16.  PV^T: fp16 2-pass (Ph+Pl)*V16.
// TK=64 tiles, double-buffered K and V, one __syncthreads per tile.
// ============================================================================
__global__ __launch_bounds__(256) void k_attn()
{
    extern __shared__ char smc[];
    const uint32_t sb = smem_u32(smc);
    const int tid = threadIdx.x;
    const int wid = tid >> 5, lane = tid & 31;
    const int n0 = blockIdx.x * TQ;
    const int b  = blockIdx.y;
    const int sp = blockIdx.z;
    const int m_base = sp * (NSP/KSPLIT);

    const uint32_t* Qh  = g_Qh  + ((size_t)b*NSP + n0)*64;
    const uint32_t* Ql  = g_Ql  + ((size_t)b*NSP + n0)*64;
    const uint32_t* K16 = g_K16 + (size_t)b*NSP*64;
    const uint32_t* V16 = g_V16 + (size_t)b*CH*2048;

    // ---- prologue group 0: Q hi/lo + K(0) into K buf 0 ----
    for (int i = tid; i < 2048; i += 256){
        int r = i >> 4, q = i & 15;
        uint32_t so = (uint32_t)r*272 + q*16;
        cpa(sb + QHS + so, Qh + r*64 + q*4);
        cpa(sb + QLS + so, Ql + r*64 + q*4);
    }
    for (int i = tid; i < 1024; i += 256){
        int r = i >> 4, q = i & 15;
        uint32_t so = (uint32_t)r*272 + q*16;
        cpa(sb + KB0 + so, K16 + (size_t)(m_base + r)*64 + q*4);
    }
    CPA_COMMIT();
    // ---- prologue group 1: V(0) into V buf 0 ----
    for (int i = tid; i < 1024; i += 256){
        int r = i >> 3, q = i & 7;
        uint32_t so = (uint32_t)r*144 + q*16;
        cpa(sb + VB0 + so, V16 + (size_t)r*2048 + (m_base >> 1) + q*4);
    }
    CPA_COMMIT();
    CPA_WAIT1();            // Q + K(0) ready (V(0) may still fly)
    __syncthreads();

    // fragment address bases (Q/K row stride 272B; V row stride 144B)
    const int arow = 16*wid + (lane & 7) + ((lane >> 3) & 1)*8;
    const uint32_t aoff = (uint32_t)arow*272 + ((lane >> 4) & 1)*16;
    const int brow = (lane & 7) + ((lane >> 4) & 1)*8;
    const uint32_t boff = ((lane >> 3) & 1)*16;

    // ---- cache Q_hi A-fragments for the whole kernel ----
    uint32_t qfh[8][4];
    #pragma unroll
    for (int k = 0; k < 8; k++) ldsm4(sb + QHS + aoff + k*32, qfh[k]);

    float oacc[16][4];
    #pragma unroll
    for (int i = 0; i < 16; i++)
        #pragma unroll
        for (int j = 0; j < 4; j++) oacc[i][j] = 0.f;
    float lsum0 = 0.f, lsum1 = 0.f;
    float mrow0 = -CUDART_INF_F, mrow1 = -CUDART_INF_F;

    for (int t = 0; t < NT2; t++){
        const uint32_t kb = sb + KB0 + (uint32_t)(t & 1)*KBSZ;
        const uint32_t vb = sb + VB0 + (uint32_t)(t & 1)*VBSZ;

        // tile barrier: K(t) ready (wait done previous iteration / prologue)
        __syncthreads();

        // earliest possible K(t+1) prefetch
        if (t + 1 < NT2){
            const int m1 = m_base + (t + 1)*TKK;
            const uint32_t kn = sb + KB0 + (uint32_t)((t + 1) & 1)*KBSZ;
            for (int i = tid; i < 1024; i += 256){
                int r = i >> 4, q = i & 15;
                uint32_t so = (uint32_t)r*272 + q*16;
                cpa(kn + so, K16 + (size_t)(m1 + r)*64 + q*4);
            }
            CPA_COMMIT();
        }

        // ---- S = Q K^T : fp16, 2 passes (Qh*K + Ql*K), B loaded once ----
        float sacc[8][4];
        #pragma unroll
        for (int i = 0; i < 8; i++)
            #pragma unroll
            for (int j = 0; j < 4; j++) sacc[i][j] = 0.f;

        #pragma unroll
        for (int k = 0; k < 8; k++){
            uint32_t al[4];
            ldsm4(sb + QLS + aoff + k*32, al);
            #pragma unroll
            for (int jj = 0; jj < 4; jj++){
                uint32_t bh[4];
                uint32_t ro = (uint32_t)(16*jj + brow)*272 + boff + k*32;
                ldsm4(kb + ro, bh);
                mmah(sacc[2*jj],     qfh[k], bh);
                mmah(sacc[2*jj + 1], qfh[k], bh + 2);
                mmah(sacc[2*jj],     al,     bh);
                mmah(sacc[2*jj + 1], al,     bh + 2);
            }
        }

        // ---- online row max over this tile (rows g and g+8 of the quad) ----
        float tm0 = sacc[0][0], tm1 = sacc[0][2];
        #pragma unroll
        for (int j = 0; j < 8; j++){
            tm0 = fmaxf(tm0, fmaxf(sacc[j][0], sacc[j][1]));
            tm1 = fmaxf(tm1, fmaxf(sacc[j][2], sacc[j][3]));
        }
        #pragma unroll
        for (int d = 1; d < 4; d <<= 1){
            tm0 = fmaxf(tm0, __shfl_xor_sync(0xffffffffu, tm0, d));
            tm1 = fmaxf(tm1, __shfl_xor_sync(0xffffffffu, tm1, d));
        }
        float mn0 = fmaxf(mrow0, tm0), mn1 = fmaxf(mrow1, tm1);
        float sc0 = __expf(mrow0 - mn0), sc1 = __expf(mrow1 - mn1);
        mrow0 = mn0; mrow1 = mn1;
        #pragma unroll
        for (int i = 0; i < 16; i++){
            oacc[i][0] *= sc0; oacc[i][1] *= sc0;
            oacc[i][2] *= sc1; oacc[i][3] *= sc1;
        }
        lsum0 *= sc0; lsum1 *= sc1;

        // ---- P = exp(S - m_row); pack into fp16 A-fragments (hi/lo) ----
        uint32_t pfh[4][4], pfl[4][4];
        #pragma unroll
        for (int j = 0; j < 8; j++){
            float p0 = __expf(sacc[j][0] - mn0);
            float p1 = __expf(sacc[j][1] - mn0);
            float p2 = __expf(sacc[j][2] - mn1);
            float p3 = __expf(sacc[j][3] - mn1);
            lsum0 += p0 + p1; lsum1 += p2 + p3;
            int jk = j >> 1, hv = (j & 1) << 1;
            split2h(p0, p1, pfh[jk][hv],     pfl[jk][hv]);
            split2h(p2, p3, pfh[jk][hv + 1], pfl[jk][hv + 1]);
        }

        // V(t) ready?  pending: {V(t), K(t+1)} -> wait 1;  last tile: wait 0
        if (t + 1 < NT2) { CPA_WAIT1(); } else { CPA_WAIT0(); }

        // earliest possible V(t+1) prefetch
        if (t + 1 < NT2){
            const int m1 = m_base + (t + 1)*TKK;
            const uint32_t vn = sb + VB0 + (uint32_t)((t + 1) & 1)*VBSZ;
            for (int i = tid; i < 1024; i += 256){
                int r = i >> 3, q = i & 7;
                uint32_t so = (uint32_t)r*144 + q*16;
                cpa(vn + so, V16 + (size_t)r*2048 + (m1 >> 1) + q*4);
            }
            CPA_COMMIT();
        }

        // ---- O += P V^T : fp16, 2 passes (Ph+Pl)*V16, B loaded once ----
        #pragma unroll
        for (int k = 0; k < 4; k++){
            #pragma unroll
            for (int jj = 0; jj < 8; jj++){
                uint32_t bh[4];
                uint32_t ro = (uint32_t)(16*jj + brow)*144 + boff + k*32;
                ldsm4(vb + ro, bh);
                mmah(oacc[2*jj],     pfh[k], bh);
                mmah(oacc[2*jj + 1], pfh[k], bh + 2);
                mmah(oacc[2*jj],     pfl[k], bh);
                mmah(oacc[2*jj + 1], pfl[k], bh + 2);
            }
        }
    }

    // ---- epilogue: l and m per row, unnormalized (max-relative) O out ----
    #pragma unroll
    for (int d = 1; d < 4; d <<= 1){
        lsum0 += __shfl_xor_sync(0xffffffffu, lsum0, d);
        lsum1 += __shfl_xor_sync(0xffffffffu, lsum1, d);
    }
    const int g = lane >> 2, q = lane & 3;
    const int row = 16*wid + g;
    if (q == 0){
        size_t lb = ((size_t)sp*BATCH + b)*NSP + n0;
        g_lp[lb + row]     = lsum0;
        g_lp[lb + row + 8] = lsum1;
        g_mx[lb + row]     = mrow0;
        g_mx[lb + row + 8] = mrow1;
    }
    float* Ob = g_Op + (((size_t)sp*BATCH + b)*NSP + n0)*CH;
    #pragma unroll
    for (int tt = 0; tt < 16; tt++){
        int c = 8*tt + 2*q;
        *(float2*)(Ob + (size_t)row*CH + c)       = make_float2(oacc[tt][0], oacc[tt][1]);
        *(float2*)(Ob + (size_t)(row + 8)*CH + c) = make_float2(oacc[tt][2], oacc[tt][3]);
    }
}

// ============================================================================
// K3: combine splits (m/l merge), y = x + Wo @ h, per-(b,group) partials.
// ============================================================================
__global__ __launch_bounds__(256) void k_proj(const float* __restrict__ x,
                                              const float* __restrict__ Wo)
{
    extern __shared__ float sm[];
    __shared__ float w0S[64], w1S[64];
    float* Wt = sm;               // [c][130]
    float* HS = sm + 128*130;     // [n][129] compute; [o][65] staging

    const int n0 = blockIdx.x * TN;
    const int b  = blockIdx.y;
    const int tid = threadIdx.x;
    const int tx  = tid & 15;
    const int ty  = tid >> 4;

    if (tid < 64){
        size_t i0 = ((size_t)0*BATCH + b)*NSP + n0 + tid;
        size_t i1 = ((size_t)1*BATCH + b)*NSP + n0 + tid;
        float l0 = g_lp[i0], l1 = g_lp[i1];
        float m0 = g_mx[i0], m1 = g_mx[i1];
        float M  = fmaxf(m0, m1);
        float e0 = __expf(m0 - M), e1 = __expf(m1 - M);
        float rl = 1.0f / (l0*e0 + l1*e1);
        w0S[tid] = e0 * rl;
        w1S[tid] = e1 * rl;
    }
    for (int idx = tid; idx < 128*64; idx += 256){
        int o  = idx >> 6;
        int cq = (idx & 63) << 1;
        float2 w = *(const float2*)(Wo + o*128 + cq);
        Wt[ cq   *130 + o] = w.x;
        Wt[(cq+1)*130 + o] = w.y;
    }
    __syncthreads();

    const float* O0 = g_Op + (((size_t)0*BATCH + b)*NSP + n0)*CH;
    const float* O1 = g_Op + (((size_t)1*BATCH + b)*NSP + n0)*CH;
    for (int idx = tid; idx < 64*128; idx += 256){
        int n = idx >> 7, c = idx & 127;
        HS[n*129 + c] = O0[idx]*w0S[n] + O1[idx]*w1S[n];
    }
    __syncthreads();

    unsigned long long acc[4][4];
    #pragma unroll
    for (int i = 0; i < 4; i++)
        #pragma unroll
        for (int j = 0; j < 4; j++) acc[i][j] = 0ull;

    #pragma unroll 4
    for (int c = 0; c < 128; c++){
        unsigned long long wv[4]; float hv[4];
        #pragma unroll
        for (int j = 0; j < 4; j++)
            wv[j] = *(const unsigned long long*)(Wt + c*130 + 2*tx + 32*j);
        #pragma unroll
        for (int i = 0; i < 4; i++) hv[i] = HS[(ty + 16*i)*129 + c];
        #pragma unroll
        for (int i = 0; i < 4; i++){
            unsigned long long hd = pk2(hv[i], hv[i]);
            #pragma unroll
            for (int j = 0; j < 4; j++) ffma2(acc[i][j], wv[j], hd);
        }
    }
    __syncthreads();

    float* St = HS;  // [o][65]
    #pragma unroll
    for (int i = 0; i < 4; i++)
        #pragma unroll
        for (int j = 0; j < 4; j++){
            float a, bv; upk2(acc[i][j], a, bv);
            int o = 2*tx + 32*j, n = ty + 16*i;
            St[ o   *65 + n] = a;
            St[(o+1)*65 + n] = bv;
        }
    __syncthreads();

    const float* xb = x   + (size_t)b*CH*NSP + n0;
    float*       yb = g_Y + (size_t)b*CH*NSP + n0;
    const int w = tid >> 5, lane = tid & 31;
    float s1 = 0.f, s2 = 0.f;
    for (int k = 0; k < 32; k++){
        int e = w*1024 + k*32 + lane;
        int o = e >> 6, n = e & 63;
        float val = xb[o*NSP + n] + St[o*65 + n];
        yb[o*NSP + n] = val;
        s1 += val; s2 += val*val;
    }
    #pragma unroll
    for (int d = 16; d >= 1; d >>= 1){
        s1 += __shfl_xor_sync(0xffffffffu, s1, d);
        s2 += __shfl_xor_sync(0xffffffffu, s2, d);
    }
    if (lane == 0){
        float* p = g_part + ((size_t)(b*64 + blockIdx.x)*GROUPS + w)*2;
        p[0] = s1; p[1] = s2;
    }
}

// K4: GroupNorm + affine + SiLU, with fused (redundant, deterministic)
// per-block reduction of the 64 partial sums for this block's group.
__global__ __launch_bounds__(256) void k_norm(const float* __restrict__ gamma,
                                              const float* __restrict__ beta,
                                              float* __restrict__ out)
{
    __shared__ float sh_mean, sh_inv;
    const int tid = threadIdx.x;
    const int e0 = blockIdx.x << 10;        // 1024 elems per block
    const int b = e0 >> 19;
    const int c = (e0 >> 12) & 127;
    const int g = c >> 4;

    if (tid < 32){
        const float* p = g_part + ((size_t)(b*64)*GROUPS + g)*2;
        float s1 = p[(size_t)tid*GROUPS*2]     + p[(size_t)(tid+32)*GROUPS*2];
        float s2 = p[(size_t)tid*GROUPS*2 + 1] + p[(size_t)(tid+32)*GROUPS*2 + 1];
        #pragma unroll
        for (int d = 16; d >= 1; d >>= 1){
            s1 += __shfl_xor_sync(0xffffffffu, s1, d);
            s2 += __shfl_xor_sync(0xffffffffu, s2, d);
        }
        if (tid == 0){
            const float icnt = 1.0f / 65536.0f;
            float mean = s1 * icnt;
            float var  = s2 * icnt - mean*mean;
            sh_mean = mean;
            sh_inv  = rsqrtf(var + EPSV);
        }
    }
    __syncthreads();

    const float mean = sh_mean, inv = sh_inv;
    const float ga = gamma[c], be = beta[c];
    const int e = e0 + tid*4;
    float4 y = *(const float4*)(g_Y + e);
    float4 r;
    float t = (y.x - mean)*inv*ga + be; r.x = t / (1.0f + __expf(-t));
    t = (y.y - mean)*inv*ga + be;       r.y = t / (1.0f + __expf(-t));
    t = (y.z - mean)*inv*ga + be;       r.z = t / (1.0f + __expf(-t));
    t = (y.w - mean)*inv*ga + be;       r.w = t / (1.0f + __expf(-t));
    *(float4*)(out + e) = r;
}

// ============================================================================
extern "C" void kernel_launch(void* const* d_in, const int* in_sizes, int n_in,
                              void* d_out, int out_size)
{
    const float* x     = (const float*)d_in[0];
    const float* Wq    = (const float*)d_in[1];
    const float* Wk    = (const float*)d_in[2];
    const float* Wv    = (const float*)d_in[3];
    const float* Wo    = (const float*)d_in[4];
    const float* gamma = (const float*)d_in[5];
    const float* beta  = (const float*)d_in[6];
    float* out = (float*)d_out;

    const int SM1 = (128*130 + 128*65) * 4;
    const int SM3 = (128*130 + 128*65) * 4;

    cudaFuncSetAttribute(k_qkv,  cudaFuncAttributeMaxDynamicSharedMemorySize, SM1);
    cudaFuncSetAttribute(k_attn, cudaFuncAttributeMaxDynamicSharedMemorySize, SM_ATTN);
    cudaFuncSetAttribute(k_proj, cudaFuncAttributeMaxDynamicSharedMemorySize, SM3);

    k_qkv <<<dim3(NSP/TN, BATCH, 3),      256, SM1>>>(x, Wq, Wk, Wv);
    k_attn<<<dim3(NSP/TQ, BATCH, KSPLIT), 256, SM_ATTN>>>();
    k_proj<<<dim3(NSP/TN, BATCH),         256, SM3>>>(x, Wo);
    k_norm<<<(BATCH*CH*NSP)/(4*256), 256>>>(gamma, beta, out);
}

// round 12
// speedup vs baseline: 4.4310x; 1.1974x over previous
#include <cuda_runtime.h>
#include <cuda_bf16.h>
#include <cuda_fp16.h>
#include <math_constants.h>
#include <cstdint>

#define BATCH 2
#define CH    128
#define NSP   4096
#define GROUPS 8
#define TN    64
#define EPSV  1e-5f

// attention tiling
#define TQ     128
#define TKK    64
#define KSPLIT 2
#define NT2    (NSP/KSPLIT/TKK)   // 32

// ---------------- scratch (static __device__, allocation-free) ----------------
__device__ uint32_t g_Qh[BATCH*NSP*64], g_Ql[BATCH*NSP*64];   // [b][n][cw] fp16x2 hi/lo
__device__ uint32_t g_K16[BATCH*NSP*64];                      // [b][m][cw] fp16x2 single
__device__ uint32_t g_V16[BATCH*CH*2048];                     // [b][c][mw] fp16x2 single (V^T)
__device__ float g_Op[KSPLIT*BATCH*NSP*CH];   // unnormalized O  [s][b][n][c]
__device__ float g_lp[KSPLIT*BATCH*NSP];      // exp-sums        [s][b][n]
__device__ float g_mx[KSPLIT*BATCH*NSP];      // row maxes       [s][b][n]
__device__ float g_Y [BATCH*CH*NSP];
__device__ float g_part [BATCH*64*GROUPS*2];

// ---------------- f32x2 helpers ----------------
__device__ __forceinline__ unsigned long long pk2(float x, float y){
    unsigned long long r; asm("mov.b64 %0, {%1,%2};" : "=l"(r) : "f"(x), "f"(y)); return r;
}
__device__ __forceinline__ void upk2(unsigned long long v, float& x, float& y){
    asm("mov.b64 {%0,%1}, %2;" : "=f"(x), "=f"(y) : "l"(v));
}
__device__ __forceinline__ void ffma2(unsigned long long& d, unsigned long long a, unsigned long long b){
    asm("fma.rn.f32x2 %0, %1, %2, %0;" : "+l"(d) : "l"(a), "l"(b));
}

// ---------------- smem / mma / ldmatrix / cp.async helpers ----------------
__device__ __forceinline__ uint32_t smem_u32(const void* p){
    uint32_t a;
    asm("{ .reg .u64 t; cvta.to.shared.u64 t, %1; cvt.u32.u64 %0, t; }" : "=r"(a) : "l"(p));
    return a;
}
__device__ __forceinline__ void cpa(uint32_t saddr, const void* g){
    asm volatile("cp.async.ca.shared.global [%0], [%1], 16;" :: "r"(saddr), "l"(g) : "memory");
}
#define CPA_COMMIT() asm volatile("cp.async.commit_group;" ::: "memory")
#define CPA_WAIT0()  asm volatile("cp.async.wait_group 0;" ::: "memory")
#define CPA_WAIT1()  asm volatile("cp.async.wait_group 1;" ::: "memory")

__device__ __forceinline__ void ldsm4(uint32_t a, uint32_t r[4]){
    asm volatile("ldmatrix.sync.aligned.m8n8.x4.shared.b16 {%0,%1,%2,%3}, [%4];"
      : "=r"(r[0]), "=r"(r[1]), "=r"(r[2]), "=r"(r[3]) : "r"(a));
}
// fp16 mma
__device__ __forceinline__ void mmah(float c[4], const uint32_t a[4], const uint32_t b[2]){
    asm volatile("mma.sync.aligned.m16n8k16.row.col.f32.f16.f16.f32 "
      "{%0,%1,%2,%3}, {%4,%5,%6,%7}, {%8,%9}, {%0,%1,%2,%3};"
      : "+f"(c[0]), "+f"(c[1]), "+f"(c[2]), "+f"(c[3])
      : "r"(a[0]), "r"(a[1]), "r"(a[2]), "r"(a[3]), "r"(b[0]), "r"(b[1]));
}

// fp16 hi/lo split of a float pair
__device__ __forceinline__ void split2h(float a, float b, uint32_t& hw, uint32_t& lw){
    __half ah = __float2half_rn(a), bh = __float2half_rn(b);
    float ar = a - __half2float(ah), br = b - __half2float(bh);
    __half al = __float2half_rn(ar), bl = __float2half_rn(br);
    hw = ((uint32_t)__half_as_ushort(bh) << 16) | __half_as_ushort(ah);
    lw = ((uint32_t)__half_as_ushort(bl) << 16) | __half_as_ushort(al);
}
// single fp16 pack of a float pair
__device__ __forceinline__ uint32_t packh2(float a, float b){
    __half2 h = __floats2half2_rn(a, b);
    return *reinterpret_cast<uint32_t*>(&h);
}

// smem byte offsets for k_attn
// Q: 128 rows x 272B (hi, lo).  K bufs: 64 rows x 272B.  V bufs: 128 rows x 144B.
#define QHS  0
#define QLS  34816
#define KB0  69632
#define KBSZ 17408
#define VB0  104448
#define VBSZ 18432
#define SM_ATTN 141312

// ============================================================================
// K1: Q/K/V projections (fp32 scalar).
// Q -> fp16 hi/lo [b][n][c];  K -> single fp16 [b][m][c];  V -> single fp16 [b][c][m].
// ============================================================================
__global__ __launch_bounds__(256) void k_qkv(const float* __restrict__ x,
                                             const float* __restrict__ Wq,
                                             const float* __restrict__ Wk,
                                             const float* __restrict__ Wv)
{
    extern __shared__ float sm[];
    float* Wt = sm;               // [c][130]
    float* Xs = sm + 128*130;     // [c][64] during compute; [o][65] staging after

    const int n0  = blockIdx.x * TN;
    const int b   = blockIdx.y;
    const int z   = blockIdx.z;
    const float* W = (z == 0) ? Wq : ((z == 1) ? Wk : Wv);

    const int tid = threadIdx.x;
    const int tx  = tid & 15;
    const int ty  = tid >> 4;

    for (int idx = tid; idx < 128*64; idx += 256){
        int o  = idx >> 6;
        int cq = (idx & 63) << 1;
        float2 w = *(const float2*)(W + o*128 + cq);
        Wt[ cq   *130 + o] = w.x;
        Wt[(cq+1)*130 + o] = w.y;
    }
    const float* xb = x + (size_t)b*CH*NSP + n0;
    for (int idx = tid; idx < 128*16; idx += 256){
        int c = idx >> 4, u = (idx & 15) << 2;
        *(float4*)(Xs + c*64 + u) = *(const float4*)(xb + c*NSP + u);
    }
    __syncthreads();

    unsigned long long acc[4][4];
    #pragma unroll
    for (int i = 0; i < 4; i++)
        #pragma unroll
        for (int j = 0; j < 4; j++) acc[i][j] = 0ull;

    #pragma unroll 4
    for (int c = 0; c < 128; c++){
        unsigned long long wv[4]; float xn[4];
        #pragma unroll
        for (int j = 0; j < 4; j++)
            wv[j] = *(const unsigned long long*)(Wt + c*130 + 2*tx + 32*j);
        #pragma unroll
        for (int i = 0; i < 4; i++) xn[i] = Xs[c*64 + ty + 16*i];
        #pragma unroll
        for (int i = 0; i < 4; i++){
            unsigned long long xd = pk2(xn[i], xn[i]);
            #pragma unroll
            for (int j = 0; j < 4; j++) ffma2(acc[i][j], wv[j], xd);
        }
    }
    __syncthreads();

    float* St = Xs;  // [o][65]
    #pragma unroll
    for (int i = 0; i < 4; i++)
        #pragma unroll
        for (int j = 0; j < 4; j++){
            float a, bv; upk2(acc[i][j], a, bv);
            int o = 2*tx + 32*j, n = ty + 16*i;
            St[ o   *65 + n] = a;
            St[(o+1)*65 + n] = bv;
        }
    __syncthreads();

    if (z == 0){
        uint32_t* oh = g_Qh + ((size_t)b*NSP + n0)*64;
        uint32_t* ol = g_Ql + ((size_t)b*NSP + n0)*64;
        for (int idx = tid; idx < 64*64; idx += 256){
            int n = idx >> 6, cw = idx & 63;
            uint32_t hw, lw;
            split2h(St[(2*cw)*65 + n], St[(2*cw+1)*65 + n], hw, lw);
            oh[n*64 + cw] = hw;
            ol[n*64 + cw] = lw;
        }
    } else if (z == 1){
        uint32_t* ok = g_K16 + ((size_t)b*NSP + n0)*64;
        for (int idx = tid; idx < 64*64; idx += 256){
            int n = idx >> 6, cw = idx & 63;
            ok[n*64 + cw] = packh2(St[(2*cw)*65 + n], St[(2*cw+1)*65 + n]);
        }
    } else {
        uint32_t* ov = g_V16 + (size_t)b*CH*2048 + (n0 >> 1);
        for (int idx = tid; idx < 128*32; idx += 256){
            int c = idx >> 5, mw = idx & 31;
            ov[(size_t)c*2048 + mw] = packh2(St[c*65 + 2*mw], St[c*65 + 2*mw + 1]);
        }
    }
}

// ============================================================================
// K2: HMMA flash attention, online softmax (per-row running max), split-K.
// QK^T: fp16 2-pass (Qh+Ql)*K16.  PV^T: fp16 1-pass P16*V16 (P in (0,1]).
// TK=64 tiles, double-buffered K and V, one __syncthreads per tile.
// ============================================================================
__global__ __launch_bounds__(256) void k_attn()
{
    extern __shared__ char smc[];
    const uint32_t sb = smem_u32(smc);
    const int tid = threadIdx.x;
    const int wid = tid >> 5, lane = tid & 31;
    const int n0 = blockIdx.x * TQ;
    const int b  = blockIdx.y;
    const int sp = blockIdx.z;
    const int m_base = sp * (NSP/KSPLIT);

    const uint32_t* Qh  = g_Qh  + ((size_t)b*NSP + n0)*64;
    const uint32_t* Ql  = g_Ql  + ((size_t)b*NSP + n0)*64;
    const uint32_t* K16 = g_K16 + (size_t)b*NSP*64;
    const uint32_t* V16 = g_V16 + (size_t)b*CH*2048;

    // ---- prologue group 0: Q hi/lo + K(0) into K buf 0 ----
    for (int i = tid; i < 2048; i += 256){
        int r = i >> 4, q = i & 15;
        uint32_t so = (uint32_t)r*272 + q*16;
        cpa(sb + QHS + so, Qh + r*64 + q*4);
        cpa(sb + QLS + so, Ql + r*64 + q*4);
    }
    for (int i = tid; i < 1024; i += 256){
        int r = i >> 4, q = i & 15;
        uint32_t so = (uint32_t)r*272 + q*16;
        cpa(sb + KB0 + so, K16 + (size_t)(m_base + r)*64 + q*4);
    }
    CPA_COMMIT();
    // ---- prologue group 1: V(0) into V buf 0 ----
    for (int i = tid; i < 1024; i += 256){
        int r = i >> 3, q = i & 7;
        uint32_t so = (uint32_t)r*144 + q*16;
        cpa(sb + VB0 + so, V16 + (size_t)r*2048 + (m_base >> 1) + q*4);
    }
    CPA_COMMIT();
    CPA_WAIT1();            // Q + K(0) ready (V(0) may still fly)
    __syncthreads();

    // fragment address bases (Q/K row stride 272B; V row stride 144B)
    const int arow = 16*wid + (lane & 7) + ((lane >> 3) & 1)*8;
    const uint32_t aoff = (uint32_t)arow*272 + ((lane >> 4) & 1)*16;
    const int brow = (lane & 7) + ((lane >> 4) & 1)*8;
    const uint32_t boff = ((lane >> 3) & 1)*16;

    // ---- cache Q_hi A-fragments for the whole kernel ----
    uint32_t qfh[8][4];
    #pragma unroll
    for (int k = 0; k < 8; k++) ldsm4(sb + QHS + aoff + k*32, qfh[k]);

    float oacc[16][4];
    #pragma unroll
    for (int i = 0; i < 16; i++)
        #pragma unroll
        for (int j = 0; j < 4; j++) oacc[i][j] = 0.f;
    float lsum0 = 0.f, lsum1 = 0.f;
    float mrow0 = -CUDART_INF_F, mrow1 = -CUDART_INF_F;

    for (int t = 0; t < NT2; t++){
        const uint32_t kb = sb + KB0 + (uint32_t)(t & 1)*KBSZ;
        const uint32_t vb = sb + VB0 + (uint32_t)(t & 1)*VBSZ;

        // tile barrier: K(t) ready (wait done previous iteration / prologue)
        __syncthreads();

        // earliest possible K(t+1) prefetch
        if (t + 1 < NT2){
            const int m1 = m_base + (t + 1)*TKK;
            const uint32_t kn = sb + KB0 + (uint32_t)((t + 1) & 1)*KBSZ;
            for (int i = tid; i < 1024; i += 256){
                int r = i >> 4, q = i & 15;
                uint32_t so = (uint32_t)r*272 + q*16;
                cpa(kn + so, K16 + (size_t)(m1 + r)*64 + q*4);
            }
            CPA_COMMIT();
        }

        // ---- S = Q K^T : fp16, 2 passes (Qh*K + Ql*K), B loaded once ----
        float sacc[8][4];
        #pragma unroll
        for (int i = 0; i < 8; i++)
            #pragma unroll
            for (int j = 0; j < 4; j++) sacc[i][j] = 0.f;

        #pragma unroll
        for (int k = 0; k < 8; k++){
            uint32_t al[4];
            ldsm4(sb + QLS + aoff + k*32, al);
            #pragma unroll
            for (int jj = 0; jj < 4; jj++){
                uint32_t bh[4];
                uint32_t ro = (uint32_t)(16*jj + brow)*272 + boff + k*32;
                ldsm4(kb + ro, bh);
                mmah(sacc[2*jj],     qfh[k], bh);
                mmah(sacc[2*jj + 1], qfh[k], bh + 2);
                mmah(sacc[2*jj],     al,     bh);
                mmah(sacc[2*jj + 1], al,     bh + 2);
            }
        }

        // ---- online row max over this tile (rows g and g+8 of the quad) ----
        float tm0 = sacc[0][0], tm1 = sacc[0][2];
        #pragma unroll
        for (int j = 0; j < 8; j++){
            tm0 = fmaxf(tm0, fmaxf(sacc[j][0], sacc[j][1]));
            tm1 = fmaxf(tm1, fmaxf(sacc[j][2], sacc[j][3]));
        }
        #pragma unroll
        for (int d = 1; d < 4; d <<= 1){
            tm0 = fmaxf(tm0, __shfl_xor_sync(0xffffffffu, tm0, d));
            tm1 = fmaxf(tm1, __shfl_xor_sync(0xffffffffu, tm1, d));
        }
        float mn0 = fmaxf(mrow0, tm0), mn1 = fmaxf(mrow1, tm1);
        float sc0 = __expf(mrow0 - mn0), sc1 = __expf(mrow1 - mn1);
        mrow0 = mn0; mrow1 = mn1;
        #pragma unroll
        for (int i = 0; i < 16; i++){
            oacc[i][0] *= sc0; oacc[i][1] *= sc0;
            oacc[i][2] *= sc1; oacc[i][3] *= sc1;
        }
        lsum0 *= sc0; lsum1 *= sc1;

        // ---- P = exp(S - m_row); pack into SINGLE fp16 A-fragments ----
        uint32_t pf[4][4];
        #pragma unroll
        for (int j = 0; j < 8; j++){
            float p0 = __expf(sacc[j][0] - mn0);
            float p1 = __expf(sacc[j][1] - mn0);
            float p2 = __expf(sacc[j][2] - mn1);
            float p3 = __expf(sacc[j][3] - mn1);
            lsum0 += p0 + p1; lsum1 += p2 + p3;
            int jk = j >> 1, hv = (j & 1) << 1;
            pf[jk][hv]     = packh2(p0, p1);
            pf[jk][hv + 1] = packh2(p2, p3);
        }

        // V(t) ready?  pending: {V(t), K(t+1)} -> wait 1;  last tile: wait 0
        if (t + 1 < NT2) { CPA_WAIT1(); } else { CPA_WAIT0(); }

        // earliest possible V(t+1) prefetch
        if (t + 1 < NT2){
            const int m1 = m_base + (t + 1)*TKK;
            const uint32_t vn = sb + VB0 + (uint32_t)((t + 1) & 1)*VBSZ;
            for (int i = tid; i < 1024; i += 256){
                int r = i >> 3, q = i & 7;
                uint32_t so = (uint32_t)r*144 + q*16;
                cpa(vn + so, V16 + (size_t)r*2048 + (m1 >> 1) + q*4);
            }
            CPA_COMMIT();
        }

        // ---- O += P V^T : fp16, 1 pass P16*V16, B loaded once ----
        #pragma unroll
        for (int k = 0; k < 4; k++){
            #pragma unroll
            for (int jj = 0; jj < 8; jj++){
                uint32_t bh[4];
                uint32_t ro = (uint32_t)(16*jj + brow)*144 + boff + k*32;
                ldsm4(vb + ro, bh);
                mmah(oacc[2*jj],     pf[k], bh);
                mmah(oacc[2*jj + 1], pf[k], bh + 2);
            }
        }
    }

    // ---- epilogue: l and m per row, unnormalized (max-relative) O out ----
    #pragma unroll
    for (int d = 1; d < 4; d <<= 1){
        lsum0 += __shfl_xor_sync(0xffffffffu, lsum0, d);
        lsum1 += __shfl_xor_sync(0xffffffffu, lsum1, d);
    }
    const int g = lane >> 2, q = lane & 3;
    const int row = 16*wid + g;
    if (q == 0){
        size_t lb = ((size_t)sp*BATCH + b)*NSP + n0;
        g_lp[lb + row]     = lsum0;
        g_lp[lb + row + 8] = lsum1;
        g_mx[lb + row]     = mrow0;
        g_mx[lb + row + 8] = mrow1;
    }
    float* Ob = g_Op + (((size_t)sp*BATCH + b)*NSP + n0)*CH;
    #pragma unroll
    for (int tt = 0; tt < 16; tt++){
        int c = 8*tt + 2*q;
        *(float2*)(Ob + (size_t)row*CH + c)       = make_float2(oacc[tt][0], oacc[tt][1]);
        *(float2*)(Ob + (size_t)(row + 8)*CH + c) = make_float2(oacc[tt][2], oacc[tt][3]);
    }
}

// ============================================================================
// K3: combine splits (m/l merge), y = x + Wo @ h, per-(b,group) partials.
// ============================================================================
__global__ __launch_bounds__(256) void k_proj(const float* __restrict__ x,
                                              const float* __restrict__ Wo)
{
    extern __shared__ float sm[];
    __shared__ float w0S[64], w1S[64];
    float* Wt = sm;               // [c][130]
    float* HS = sm + 128*130;     // [n][129] compute; [o][65] staging

    const int n0 = blockIdx.x * TN;
    const int b  = blockIdx.y;
    const int tid = threadIdx.x;
    const int tx  = tid & 15;
    const int ty  = tid >> 4;

    if (tid < 64){
        size_t i0 = ((size_t)0*BATCH + b)*NSP + n0 + tid;
        size_t i1 = ((size_t)1*BATCH + b)*NSP + n0 + tid;
        float l0 = g_lp[i0], l1 = g_lp[i1];
        float m0 = g_mx[i0], m1 = g_mx[i1];
        float M  = fmaxf(m0, m1);
        float e0 = __expf(m0 - M), e1 = __expf(m1 - M);
        float rl = 1.0f / (l0*e0 + l1*e1);
        w0S[tid] = e0 * rl;
        w1S[tid] = e1 * rl;
    }
    for (int idx = tid; idx < 128*64; idx += 256){
        int o  = idx >> 6;
        int cq = (idx & 63) << 1;
        float2 w = *(const float2*)(Wo + o*128 + cq);
        Wt[ cq   *130 + o] = w.x;
        Wt[(cq+1)*130 + o] = w.y;
    }
    __syncthreads();

    const float* O0 = g_Op + (((size_t)0*BATCH + b)*NSP + n0)*CH;
    const float* O1 = g_Op + (((size_t)1*BATCH + b)*NSP + n0)*CH;
    for (int idx = tid; idx < 64*128; idx += 256){
        int n = idx >> 7, c = idx & 127;
        HS[n*129 + c] = O0[idx]*w0S[n] + O1[idx]*w1S[n];
    }
    __syncthreads();

    unsigned long long acc[4][4];
    #pragma unroll
    for (int i = 0; i < 4; i++)
        #pragma unroll
        for (int j = 0; j < 4; j++) acc[i][j] = 0ull;

    #pragma unroll 4
    for (int c = 0; c < 128; c++){
        unsigned long long wv[4]; float hv[4];
        #pragma unroll
        for (int j = 0; j < 4; j++)
            wv[j] = *(const unsigned long long*)(Wt + c*130 + 2*tx + 32*j);
        #pragma unroll
        for (int i = 0; i < 4; i++) hv[i] = HS[(ty + 16*i)*129 + c];
        #pragma unroll
        for (int i = 0; i < 4; i++){
            unsigned long long hd = pk2(hv[i], hv[i]);
            #pragma unroll
            for (int j = 0; j < 4; j++) ffma2(acc[i][j], wv[j], hd);
        }
    }
    __syncthreads();

    float* St = HS;  // [o][65]
    #pragma unroll
    for (int i = 0; i < 4; i++)
        #pragma unroll
        for (int j = 0; j < 4; j++){
            float a, bv; upk2(acc[i][j], a, bv);
            int o = 2*tx + 32*j, n = ty + 16*i;
            St[ o   *65 + n] = a;
            St[(o+1)*65 + n] = bv;
        }
    __syncthreads();

    const float* xb = x   + (size_t)b*CH*NSP + n0;
    float*       yb = g_Y + (size_t)b*CH*NSP + n0;
    const int w = tid >> 5, lane = tid & 31;
    float s1 = 0.f, s2 = 0.f;
    for (int k = 0; k < 32; k++){
        int e = w*1024 + k*32 + lane;
        int o = e >> 6, n = e & 63;
        float val = xb[o*NSP + n] + St[o*65 + n];
        yb[o*NSP + n] = val;
        s1 += val; s2 += val*val;
    }
    #pragma unroll
    for (int d = 16; d >= 1; d >>= 1){
        s1 += __shfl_xor_sync(0xffffffffu, s1, d);
        s2 += __shfl_xor_sync(0xffffffffu, s2, d);
    }
    if (lane == 0){
        float* p = g_part + ((size_t)(b*64 + blockIdx.x)*GROUPS + w)*2;
        p[0] = s1; p[1] = s2;
    }
}

// K4: GroupNorm + affine + SiLU, with fused (redundant, deterministic)
// per-block reduction of the 64 partial sums for this block's group.
__global__ __launch_bounds__(256) void k_norm(const float* __restrict__ gamma,
                                              const float* __restrict__ beta,
                                              float* __restrict__ out)
{
    __shared__ float sh_mean, sh_inv;
    const int tid = threadIdx.x;
    const int e0 = blockIdx.x << 10;        // 1024 elems per block
    const int b = e0 >> 19;
    const int c = (e0 >> 12) & 127;
    const int g = c >> 4;

    if (tid < 32){
        const float* p = g_part + ((size_t)(b*64)*GROUPS + g)*2;
        float s1 = p[(size_t)tid*GROUPS*2]     + p[(size_t)(tid+32)*GROUPS*2];
        float s2 = p[(size_t)tid*GROUPS*2 + 1] + p[(size_t)(tid+32)*GROUPS*2 + 1];
        #pragma unroll
        for (int d = 16; d >= 1; d >>= 1){
            s1 += __shfl_xor_sync(0xffffffffu, s1, d);
            s2 += __shfl_xor_sync(0xffffffffu, s2, d);
        }
        if (tid == 0){
            const float icnt = 1.0f / 65536.0f;
            float mean = s1 * icnt;
            float var  = s2 * icnt - mean*mean;
            sh_mean = mean;
            sh_inv  = rsqrtf(var + EPSV);
        }
    }
    __syncthreads();

    const float mean = sh_mean, inv = sh_inv;
    const float ga = gamma[c], be = beta[c];
    const int e = e0 + tid*4;
    float4 y = *(const float4*)(g_Y + e);
    float4 r;
    float t = (y.x - mean)*inv*ga + be; r.x = t / (1.0f + __expf(-t));
    t = (y.y - mean)*inv*ga + be;       r.y = t / (1.0f + __expf(-t));
    t = (y.z - mean)*inv*ga + be;       r.z = t / (1.0f + __expf(-t));
    t = (y.w - mean)*inv*ga + be;       r.w = t / (1.0f + __expf(-t));
    *(float4*)(out + e) = r;
}

// ============================================================================
extern "C" void kernel_launch(void* const* d_in, const int* in_sizes, int n_in,
                              void* d_out, int out_size)
{
    const float* x     = (const float*)d_in[0];
    const float* Wq    = (const float*)d_in[1];
    const float* Wk    = (const float*)d_in[2];
    const float* Wv    = (const float*)d_in[3];
    const float* Wo    = (const float*)d_in[4];
    const float* gamma = (const float*)d_in[5];
    const float* beta  = (const float*)d_in[6];
    float* out = (float*)d_out;

    const int SM1 = (128*130 + 128*65) * 4;
    const int SM3 = (128*130 + 128*65) * 4;

    cudaFuncSetAttribute(k_qkv,  cudaFuncAttributeMaxDynamicSharedMemorySize, SM1);
    cudaFuncSetAttribute(k_attn, cudaFuncAttributeMaxDynamicSharedMemorySize, SM_ATTN);
    cudaFuncSetAttribute(k_proj, cudaFuncAttributeMaxDynamicSharedMemorySize, SM3);

    k_qkv <<<dim3(NSP/TN, BATCH, 3),      256, SM1>>>(x, Wq, Wk, Wv);
    k_attn<<<dim3(NSP/TQ, BATCH, KSPLIT), 256, SM_ATTN>>>();
    k_proj<<<dim3(NSP/TN, BATCH),         256, SM3>>>(x, Wo);
    k_norm<<<(BATCH*CH*NSP)/(4*256), 256>>>(gamma, beta, out);
}

// round 13
// speedup vs baseline: 4.5088x; 1.0175x over previous
#include <cuda_runtime.h>
#include <cuda_bf16.h>
#include <cuda_fp16.h>
#include <math_constants.h>
#include <cstdint>

#define BATCH 2
#define CH    128
#define NSP   4096
#define GROUPS 8
#define TN    64
#define EPSV  1e-5f

// attention tiling
#define TQ     128
#define TKK    64
#define KSPLIT 2
#define NT2    (NSP/KSPLIT/TKK)   // 32

// ---------------- scratch (static __device__, allocation-free) ----------------
__device__ uint32_t g_Qh[BATCH*NSP*64], g_Ql[BATCH*NSP*64];   // [b][n][cw] fp16x2 hi/lo
__device__ uint32_t g_K16[BATCH*NSP*64];                      // [b][m][cw] fp16x2
__device__ uint32_t g_V16[BATCH*NSP*64];                      // [b][m][cw] fp16x2 (row-major V)
__device__ float g_Op[KSPLIT*BATCH*NSP*CH];   // unnormalized O  [s][b][n][c]
__device__ float g_lp[KSPLIT*BATCH*NSP];      // exp-sums        [s][b][n]
__device__ float g_mx[KSPLIT*BATCH*NSP];      // row maxes       [s][b][n]
__device__ float g_Y [BATCH*CH*NSP];
__device__ float g_part [BATCH*64*GROUPS*2];

// ---------------- f32x2 helpers ----------------
__device__ __forceinline__ unsigned long long pk2(float x, float y){
    unsigned long long r; asm("mov.b64 %0, {%1,%2};" : "=l"(r) : "f"(x), "f"(y)); return r;
}
__device__ __forceinline__ void upk2(unsigned long long v, float& x, float& y){
    asm("mov.b64 {%0,%1}, %2;" : "=f"(x), "=f"(y) : "l"(v));
}
__device__ __forceinline__ void ffma2(unsigned long long& d, unsigned long long a, unsigned long long b){
    asm("fma.rn.f32x2 %0, %1, %2, %0;" : "+l"(d) : "l"(a), "l"(b));
}

// ---------------- smem / mma / ldmatrix / cp.async helpers ----------------
__device__ __forceinline__ uint32_t smem_u32(const void* p){
    uint32_t a;
    asm("{ .reg .u64 t; cvta.to.shared.u64 t, %1; cvt.u32.u64 %0, t; }" : "=r"(a) : "l"(p));
    return a;
}
__device__ __forceinline__ void cpa(uint32_t saddr, const void* g){
    asm volatile("cp.async.ca.shared.global [%0], [%1], 16;" :: "r"(saddr), "l"(g) : "memory");
}
#define CPA_COMMIT() asm volatile("cp.async.commit_group;" ::: "memory")
#define CPA_WAIT0()  asm volatile("cp.async.wait_group 0;" ::: "memory")
#define CPA_WAIT1()  asm volatile("cp.async.wait_group 1;" ::: "memory")

__device__ __forceinline__ void ldsm4(uint32_t a, uint32_t r[4]){
    asm volatile("ldmatrix.sync.aligned.m8n8.x4.shared.b16 {%0,%1,%2,%3}, [%4];"
      : "=r"(r[0]), "=r"(r[1]), "=r"(r[2]), "=r"(r[3]) : "r"(a));
}
__device__ __forceinline__ void ldsm4t(uint32_t a, uint32_t r[4]){
    asm volatile("ldmatrix.sync.aligned.m8n8.x4.trans.shared.b16 {%0,%1,%2,%3}, [%4];"
      : "=r"(r[0]), "=r"(r[1]), "=r"(r[2]), "=r"(r[3]) : "r"(a));
}
// fp16 mma
__device__ __forceinline__ void mmah(float c[4], const uint32_t a[4], const uint32_t b[2]){
    asm volatile("mma.sync.aligned.m16n8k16.row.col.f32.f16.f16.f32 "
      "{%0,%1,%2,%3}, {%4,%5,%6,%7}, {%8,%9}, {%0,%1,%2,%3};"
      : "+f"(c[0]), "+f"(c[1]), "+f"(c[2]), "+f"(c[3])
      : "r"(a[0]), "r"(a[1]), "r"(a[2]), "r"(a[3]), "r"(b[0]), "r"(b[1]));
}

// fp16 hi/lo split of a float pair
__device__ __forceinline__ void split2h(float a, float b, uint32_t& hw, uint32_t& lw){
    __half ah = __float2half_rn(a), bh = __float2half_rn(b);
    float ar = a - __half2float(ah), br = b - __half2float(bh);
    __half al = __float2half_rn(ar), bl = __float2half_rn(br);
    hw = ((uint32_t)__half_as_ushort(bh) << 16) | __half_as_ushort(ah);
    lw = ((uint32_t)__half_as_ushort(bl) << 16) | __half_as_ushort(al);
}
// single fp16 pack of a float pair
__device__ __forceinline__ uint32_t packh2(float a, float b){
    __half2 h = __floats2half2_rn(a, b);
    return *reinterpret_cast<uint32_t*>(&h);
}

// smem byte offsets for k_attn
// Q: 128 rows x 272B (hi, lo).  K bufs: 64 rows x 272B.  V bufs: 64 rows x 272B.
#define QHS  0
#define QLS  34816
#define KB0  69632
#define KBSZ 17408
#define VB0  104448
#define VBSZ 17408
#define SM_ATTN 139264

// ============================================================================
// K1: Q/K/V projections (fp32 scalar), direct register->global fp16 stores.
// Q -> fp16 hi/lo [b][n][c];  K -> fp16 [b][m][c];  V -> fp16 [b][m][c].
// ============================================================================
__global__ __launch_bounds__(256) void k_qkv(const float* __restrict__ x,
                                             const float* __restrict__ Wq,
                                             const float* __restrict__ Wk,
                                             const float* __restrict__ Wv)
{
    extern __shared__ float sm[];
    float* Wt = sm;               // [c][130]
    float* Xs = sm + 128*130;     // [c][64]

    const int n0  = blockIdx.x * TN;
    const int b   = blockIdx.y;
    const int z   = blockIdx.z;
    const float* W = (z == 0) ? Wq : ((z == 1) ? Wk : Wv);

    const int tid = threadIdx.x;
    const int tx  = tid & 15;
    const int ty  = tid >> 4;

    for (int idx = tid; idx < 128*64; idx += 256){
        int o  = idx >> 6;
        int cq = (idx & 63) << 1;
        float2 w = *(const float2*)(W + o*128 + cq);
        Wt[ cq   *130 + o] = w.x;
        Wt[(cq+1)*130 + o] = w.y;
    }
    const float* xb = x + (size_t)b*CH*NSP + n0;
    for (int idx = tid; idx < 128*16; idx += 256){
        int c = idx >> 4, u = (idx & 15) << 2;
        *(float4*)(Xs + c*64 + u) = *(const float4*)(xb + c*NSP + u);
    }
    __syncthreads();

    unsigned long long acc[4][4];
    #pragma unroll
    for (int i = 0; i < 4; i++)
        #pragma unroll
        for (int j = 0; j < 4; j++) acc[i][j] = 0ull;

    #pragma unroll 4
    for (int c = 0; c < 128; c++){
        unsigned long long wv[4]; float xn[4];
        #pragma unroll
        for (int j = 0; j < 4; j++)
            wv[j] = *(const unsigned long long*)(Wt + c*130 + 2*tx + 32*j);
        #pragma unroll
        for (int i = 0; i < 4; i++) xn[i] = Xs[c*64 + ty + 16*i];
        #pragma unroll
        for (int i = 0; i < 4; i++){
            unsigned long long xd = pk2(xn[i], xn[i]);
            #pragma unroll
            for (int j = 0; j < 4; j++) ffma2(acc[i][j], wv[j], xd);
        }
    }

    // direct stores: thread holds (o, o+1) pair = one fp16x2 word at [n][cw]
    if (z == 0){
        uint32_t* oh = g_Qh + ((size_t)b*NSP + n0)*64;
        uint32_t* ol = g_Ql + ((size_t)b*NSP + n0)*64;
        #pragma unroll
        for (int i = 0; i < 4; i++)
            #pragma unroll
            for (int j = 0; j < 4; j++){
                float a, bv; upk2(acc[i][j], a, bv);
                uint32_t hw, lw;
                split2h(a, bv, hw, lw);
                int n = ty + 16*i, cw = tx + 16*j;
                oh[n*64 + cw] = hw;
                ol[n*64 + cw] = lw;
            }
    } else {
        uint32_t* ok = (z == 1 ? g_K16 : g_V16) + ((size_t)b*NSP + n0)*64;
        #pragma unroll
        for (int i = 0; i < 4; i++)
            #pragma unroll
            for (int j = 0; j < 4; j++){
                float a, bv; upk2(acc[i][j], a, bv);
                int n = ty + 16*i, cw = tx + 16*j;
                ok[n*64 + cw] = packh2(a, bv);
            }
    }
}

// ============================================================================
// K2: HMMA flash attention, online softmax (per-row running max), split-K.
// QK^T: fp16 2-pass (Qh+Ql)*K16.  PV^T: fp16 1-pass P16*V16, V via ldsm.trans.
// TK=64 tiles, double-buffered K and V, one __syncthreads per tile.
// ============================================================================
__global__ __launch_bounds__(256) void k_attn()
{
    extern __shared__ char smc[];
    const uint32_t sb = smem_u32(smc);
    const int tid = threadIdx.x;
    const int wid = tid >> 5, lane = tid & 31;
    const int n0 = blockIdx.x * TQ;
    const int b  = blockIdx.y;
    const int sp = blockIdx.z;
    const int m_base = sp * (NSP/KSPLIT);

    const uint32_t* Qh  = g_Qh  + ((size_t)b*NSP + n0)*64;
    const uint32_t* Ql  = g_Ql  + ((size_t)b*NSP + n0)*64;
    const uint32_t* K16 = g_K16 + (size_t)b*NSP*64;
    const uint32_t* V16 = g_V16 + (size_t)b*NSP*64;

    // ---- prologue group 0: Q hi/lo + K(0) into K buf 0 ----
    for (int i = tid; i < 2048; i += 256){
        int r = i >> 4, q = i & 15;
        uint32_t so = (uint32_t)r*272 + q*16;
        cpa(sb + QHS + so, Qh + r*64 + q*4);
        cpa(sb + QLS + so, Ql + r*64 + q*4);
    }
    for (int i = tid; i < 1024; i += 256){
        int r = i >> 4, q = i & 15;
        uint32_t so = (uint32_t)r*272 + q*16;
        cpa(sb + KB0 + so, K16 + (size_t)(m_base + r)*64 + q*4);
    }
    CPA_COMMIT();
    // ---- prologue group 1: V(0) into V buf 0 ----
    for (int i = tid; i < 1024; i += 256){
        int r = i >> 4, q = i & 15;
        uint32_t so = (uint32_t)r*272 + q*16;
        cpa(sb + VB0 + so, V16 + (size_t)(m_base + r)*64 + q*4);
    }
    CPA_COMMIT();
    CPA_WAIT1();            // Q + K(0) ready (V(0) may still fly)
    __syncthreads();

    // fragment address bases (row stride 272B everywhere)
    const int arow = 16*wid + (lane & 7) + ((lane >> 3) & 1)*8;
    const uint32_t aoff = (uint32_t)arow*272 + ((lane >> 4) & 1)*16;
    // K (non-trans): rows = n-dim via bit4; byte window = k-dim via bit3
    const int brow = (lane & 7) + ((lane >> 4) & 1)*8;
    const uint32_t boff = ((lane >> 3) & 1)*16;
    // V (trans): rows = k-dim via bit3; byte window = n-dim via bit4
    const int vrow = (lane & 7) + ((lane >> 3) & 1)*8;
    const uint32_t voff = ((lane >> 4) & 1)*16;

    // ---- cache Q_hi A-fragments for the whole kernel ----
    uint32_t qfh[8][4];
    #pragma unroll
    for (int k = 0; k < 8; k++) ldsm4(sb + QHS + aoff + k*32, qfh[k]);

    float oacc[16][4];
    #pragma unroll
    for (int i = 0; i < 16; i++)
        #pragma unroll
        for (int j = 0; j < 4; j++) oacc[i][j] = 0.f;
    float lsum0 = 0.f, lsum1 = 0.f;
    float mrow0 = -CUDART_INF_F, mrow1 = -CUDART_INF_F;

    for (int t = 0; t < NT2; t++){
        const uint32_t kb = sb + KB0 + (uint32_t)(t & 1)*KBSZ;
        const uint32_t vb = sb + VB0 + (uint32_t)(t & 1)*VBSZ;

        // tile barrier; confirm K(t) landed (pending <= {V(t)})
        __syncthreads();
        CPA_WAIT1();

        // earliest possible K(t+1) prefetch (writes other K buf)
        if (t + 1 < NT2){
            const int m1 = m_base + (t + 1)*TKK;
            const uint32_t kn = sb + KB0 + (uint32_t)((t + 1) & 1)*KBSZ;
            for (int i = tid; i < 1024; i += 256){
                int r = i >> 4, q = i & 15;
                uint32_t so = (uint32_t)r*272 + q*16;
                cpa(kn + so, K16 + (size_t)(m1 + r)*64 + q*4);
            }
            CPA_COMMIT();
        }

        // ---- S = Q K^T : fp16, 2 passes (Qh*K + Ql*K), B loaded once ----
        float sacc[8][4];
        #pragma unroll
        for (int i = 0; i < 8; i++)
            #pragma unroll
            for (int j = 0; j < 4; j++) sacc[i][j] = 0.f;

        #pragma unroll
        for (int k = 0; k < 8; k++){
            uint32_t al[4];
            ldsm4(sb + QLS + aoff + k*32, al);
            #pragma unroll
            for (int jj = 0; jj < 4; jj++){
                uint32_t bh[4];
                uint32_t ro = (uint32_t)(16*jj + brow)*272 + boff + k*32;
                ldsm4(kb + ro, bh);
                mmah(sacc[2*jj],     qfh[k], bh);
                mmah(sacc[2*jj + 1], qfh[k], bh + 2);
                mmah(sacc[2*jj],     al,     bh);
                mmah(sacc[2*jj + 1], al,     bh + 2);
            }
        }

        // ---- online row max over this tile (rows g and g+8 of the quad) ----
        float tm0 = sacc[0][0], tm1 = sacc[0][2];
        #pragma unroll
        for (int j = 0; j < 8; j++){
            tm0 = fmaxf(tm0, fmaxf(sacc[j][0], sacc[j][1]));
            tm1 = fmaxf(tm1, fmaxf(sacc[j][2], sacc[j][3]));
        }
        #pragma unroll
        for (int d = 1; d < 4; d <<= 1){
            tm0 = fmaxf(tm0, __shfl_xor_sync(0xffffffffu, tm0, d));
            tm1 = fmaxf(tm1, __shfl_xor_sync(0xffffffffu, tm1, d));
        }
        float mn0 = fmaxf(mrow0, tm0), mn1 = fmaxf(mrow1, tm1);
        float sc0 = __expf(mrow0 - mn0), sc1 = __expf(mrow1 - mn1);
        mrow0 = mn0; mrow1 = mn1;
        if (!__all_sync(0xffffffffu, (sc0 == 1.0f) && (sc1 == 1.0f))){
            #pragma unroll
            for (int i = 0; i < 16; i++){
                oacc[i][0] *= sc0; oacc[i][1] *= sc0;
                oacc[i][2] *= sc1; oacc[i][3] *= sc1;
            }
            lsum0 *= sc0; lsum1 *= sc1;
        }

        // ---- P = exp(S - m_row); pack into SINGLE fp16 A-fragments ----
        uint32_t pf[4][4];
        #pragma unroll
        for (int j = 0; j < 8; j++){
            float p0 = __expf(sacc[j][0] - mn0);
            float p1 = __expf(sacc[j][1] - mn0);
            float p2 = __expf(sacc[j][2] - mn1);
            float p3 = __expf(sacc[j][3] - mn1);
            lsum0 += p0 + p1; lsum1 += p2 + p3;
            int jk = j >> 1, hv = (j & 1) << 1;
            pf[jk][hv]     = packh2(p0, p1);
            pf[jk][hv + 1] = packh2(p2, p3);
        }

        // V(t) ready?  pending: {V(t), K(t+1)} -> wait 1;  last tile: wait 0
        if (t + 1 < NT2) { CPA_WAIT1(); } else { CPA_WAIT0(); }

        // earliest possible V(t+1) prefetch
        if (t + 1 < NT2){
            const int m1 = m_base + (t + 1)*TKK;
            const uint32_t vn = sb + VB0 + (uint32_t)((t + 1) & 1)*VBSZ;
            for (int i = tid; i < 1024; i += 256){
                int r = i >> 4, q = i & 15;
                uint32_t so = (uint32_t)r*272 + q*16;
                cpa(vn + so, V16 + (size_t)(m1 + r)*64 + q*4);
            }
            CPA_COMMIT();
        }

        // ---- O += P V^T : fp16 1 pass, V [m][c] via ldsm.trans ----
        #pragma unroll
        for (int k = 0; k < 4; k++){
            #pragma unroll
            for (int jj = 0; jj < 8; jj++){
                uint32_t bh[4];
                uint32_t ro = (uint32_t)(16*k + vrow)*272 + voff + jj*32;
                ldsm4t(vb + ro, bh);
                mmah(oacc[2*jj],     pf[k], bh);
                mmah(oacc[2*jj + 1], pf[k], bh + 2);
            }
        }
    }

    // ---- epilogue: l and m per row, unnormalized (max-relative) O out ----
    #pragma unroll
    for (int d = 1; d < 4; d <<= 1){
        lsum0 += __shfl_xor_sync(0xffffffffu, lsum0, d);
        lsum1 += __shfl_xor_sync(0xffffffffu, lsum1, d);
    }
    const int g = lane >> 2, q = lane & 3;
    const int row = 16*wid + g;
    if (q == 0){
        size_t lb = ((size_t)sp*BATCH + b)*NSP + n0;
        g_lp[lb + row]     = lsum0;
        g_lp[lb + row + 8] = lsum1;
        g_mx[lb + row]     = mrow0;
        g_mx[lb + row + 8] = mrow1;
    }
    float* Ob = g_Op + (((size_t)sp*BATCH + b)*NSP + n0)*CH;
    #pragma unroll
    for (int tt = 0; tt < 16; tt++){
        int c = 8*tt + 2*q;
        *(float2*)(Ob + (size_t)row*CH + c)       = make_float2(oacc[tt][0], oacc[tt][1]);
        *(float2*)(Ob + (size_t)(row + 8)*CH + c) = make_float2(oacc[tt][2], oacc[tt][3]);
    }
}

// ============================================================================
// K3: combine splits (m/l merge), y = x + Wo @ h, per-(b,group) partials.
// ============================================================================
__global__ __launch_bounds__(256) void k_proj(const float* __restrict__ x,
                                              const float* __restrict__ Wo)
{
    extern __shared__ float sm[];
    __shared__ float w0S[64], w1S[64];
    float* Wt = sm;               // [c][130]
    float* HS = sm + 128*130;     // [n][129] compute; [o][65] staging

    const int n0 = blockIdx.x * TN;
    const int b  = blockIdx.y;
    const int tid = threadIdx.x;
    const int tx  = tid & 15;
    const int ty  = tid >> 4;

    if (tid < 64){
        size_t i0 = ((size_t)0*BATCH + b)*NSP + n0 + tid;
        size_t i1 = ((size_t)1*BATCH + b)*NSP + n0 + tid;
        float l0 = g_lp[i0], l1 = g_lp[i1];
        float m0 = g_mx[i0], m1 = g_mx[i1];
        float M  = fmaxf(m0, m1);
        float e0 = __expf(m0 - M), e1 = __expf(m1 - M);
        float rl = 1.0f / (l0*e0 + l1*e1);
        w0S[tid] = e0 * rl;
        w1S[tid] = e1 * rl;
    }
    for (int idx = tid; idx < 128*64; idx += 256){
        int o  = idx >> 6;
        int cq = (idx & 63) << 1;
        float2 w = *(const float2*)(Wo + o*128 + cq);
        Wt[ cq   *130 + o] = w.x;
        Wt[(cq+1)*130 + o] = w.y;
    }
    __syncthreads();

    const float* O0 = g_Op + (((size_t)0*BATCH + b)*NSP + n0)*CH;
    const float* O1 = g_Op + (((size_t)1*BATCH + b)*NSP + n0)*CH;
    for (int idx = tid; idx < 64*128; idx += 256){
        int n = idx >> 7, c = idx & 127;
        HS[n*129 + c] = O0[idx]*w0S[n] + O1[idx]*w1S[n];
    }
    __syncthreads();

    unsigned long long acc[4][4];
    #pragma unroll
    for (int i = 0; i < 4; i++)
        #pragma unroll
        for (int j = 0; j < 4; j++) acc[i][j] = 0ull;

    #pragma unroll 4
    for (int c = 0; c < 128; c++){
        unsigned long long wv[4]; float hv[4];
        #pragma unroll
        for (int j = 0; j < 4; j++)
            wv[j] = *(const unsigned long long*)(Wt + c*130 + 2*tx + 32*j);
        #pragma unroll
        for (int i = 0; i < 4; i++) hv[i] = HS[(ty + 16*i)*129 + c];
        #pragma unroll
        for (int i = 0; i < 4; i++){
            unsigned long long hd = pk2(hv[i], hv[i]);
            #pragma unroll
            for (int j = 0; j < 4; j++) ffma2(acc[i][j], wv[j], hd);
        }
    }
    __syncthreads();

    float* St = HS;  // [o][65]
    #pragma unroll
    for (int i = 0; i < 4; i++)
        #pragma unroll
        for (int j = 0; j < 4; j++){
            float a, bv; upk2(acc[i][j], a, bv);
            int o = 2*tx + 32*j, n = ty + 16*i;
            St[ o   *65 + n] = a;
            St[(o+1)*65 + n] = bv;
        }
    __syncthreads();

    const float* xb = x   + (size_t)b*CH*NSP + n0;
    float*       yb = g_Y + (size_t)b*CH*NSP + n0;
    const int w = tid >> 5, lane = tid & 31;
    float s1 = 0.f, s2 = 0.f;
    for (int k = 0; k < 32; k++){
        int e = w*1024 + k*32 + lane;
        int o = e >> 6, n = e & 63;
        float val = xb[o*NSP + n] + St[o*65 + n];
        yb[o*NSP + n] = val;
        s1 += val; s2 += val*val;
    }
    #pragma unroll
    for (int d = 16; d >= 1; d >>= 1){
        s1 += __shfl_xor_sync(0xffffffffu, s1, d);
        s2 += __shfl_xor_sync(0xffffffffu, s2, d);
    }
    if (lane == 0){
        float* p = g_part + ((size_t)(b*64 + blockIdx.x)*GROUPS + w)*2;
        p[0] = s1; p[1] = s2;
    }
}

// K4: GroupNorm + affine + SiLU, 2 float4 per thread, with fused (redundant,
// deterministic) per-block reduction of the 64 partial sums for its group.
__global__ __launch_bounds__(256) void k_norm(const float* __restrict__ gamma,
                                              const float* __restrict__ beta,
                                              float* __restrict__ out)
{
    __shared__ float sh_mean, sh_inv;
    const int tid = threadIdx.x;
    const int e0 = blockIdx.x << 11;        // 2048 elems per block
    const int b = e0 >> 19;
    const int c = (e0 >> 12) & 127;
    const int g = c >> 4;

    if (tid < 32){
        const float* p = g_part + ((size_t)(b*64)*GROUPS + g)*2;
        float s1 = p[(size_t)tid*GROUPS*2]     + p[(size_t)(tid+32)*GROUPS*2];
        float s2 = p[(size_t)tid*GROUPS*2 + 1] + p[(size_t)(tid+32)*GROUPS*2 + 1];
        #pragma unroll
        for (int d = 16; d >= 1; d >>= 1){
            s1 += __shfl_xor_sync(0xffffffffu, s1, d);
            s2 += __shfl_xor_sync(0xffffffffu, s2, d);
        }
        if (tid == 0){
            const float icnt = 1.0f / 65536.0f;
            float mean = s1 * icnt;
            float var  = s2 * icnt - mean*mean;
            sh_mean = mean;
            sh_inv  = rsqrtf(var + EPSV);
        }
    }
    __syncthreads();

    const float mean = sh_mean, inv = sh_inv;
    const float ga = gamma[c], be = beta[c];
    #pragma unroll
    for (int h = 0; h < 2; h++){
        const int e = e0 + tid*4 + h*1024;
        float4 y = *(const float4*)(g_Y + e);
        float4 r;
        float t = (y.x - mean)*inv*ga + be; r.x = t / (1.0f + __expf(-t));
        t = (y.y - mean)*inv*ga + be;       r.y = t / (1.0f + __expf(-t));
        t = (y.z - mean)*inv*ga + be;       r.z = t / (1.0f + __expf(-t));
        t = (y.w - mean)*inv*ga + be;       r.w = t / (1.0f + __expf(-t));
        *(float4*)(out + e) = r;
    }
}

// ============================================================================
extern "C" void kernel_launch(void* const* d_in, const int* in_sizes, int n_in,
                              void* d_out, int out_size)
{
    const float* x     = (const float*)d_in[0];
    const float* Wq    = (const float*)d_in[1];
    const float* Wk    = (const float*)d_in[2];
    const float* Wv    = (const float*)d_in[3];
    const float* Wo    = (const float*)d_in[4];
    const float* gamma = (const float*)d_in[5];
    const float* beta  = (const float*)d_in[6];
    float* out = (float*)d_out;

    const int SM1 = (128*130 + 128*64) * 4;
    const int SM3 = (128*130 + 128*65) * 4;

    cudaFuncSetAttribute(k_qkv,  cudaFuncAttributeMaxDynamicSharedMemorySize, SM1);
    cudaFuncSetAttribute(k_attn, cudaFuncAttributeMaxDynamicSharedMemorySize, SM_ATTN);
    cudaFuncSetAttribute(k_proj, cudaFuncAttributeMaxDynamicSharedMemorySize, SM3);

    k_qkv <<<dim3(NSP/TN, BATCH, 3),      256, SM1>>>(x, Wq, Wk, Wv);
    k_attn<<<dim3(NSP/TQ, BATCH, KSPLIT), 256, SM_ATTN>>>();
    k_proj<<<dim3(NSP/TN, BATCH),         256, SM3>>>(x, Wo);
    k_norm<<<(BATCH*CH*NSP)/(8*256), 256>>>(gamma, beta, out);
}

// round 14
// speedup vs baseline: 4.8819x; 1.0827x over previous
#include <cuda_runtime.h>
#include <cuda_bf16.h>
#include <cuda_fp16.h>
#include <math_constants.h>
#include <cstdint>

#define BATCH 2
#define CH    128
#define NSP   4096
#define GROUPS 8
#define TN    64
#define EPSV  1e-5f

// attention tiling
#define TQ     128
#define TKK    64
#define KSPLIT 2
#define NT2    (NSP/KSPLIT/TKK)   // 32

// ---------------- scratch (static __device__, allocation-free) ----------------
__device__ uint32_t g_Q16[BATCH*NSP*64];      // [b][n][cw] fp16x2
__device__ uint32_t g_K16[BATCH*NSP*64];      // [b][m][cw] fp16x2
__device__ uint32_t g_V16[BATCH*NSP*64];      // [b][m][cw] fp16x2 (row-major V)
__device__ float g_Op[KSPLIT*BATCH*NSP*CH];   // unnormalized O  [s][b][n][c]
__device__ float g_lp[KSPLIT*BATCH*NSP];      // exp-sums        [s][b][n]
__device__ float g_mx[KSPLIT*BATCH*NSP];      // row maxes       [s][b][n]
__device__ float g_Y [BATCH*CH*NSP];
__device__ float g_part [BATCH*64*GROUPS*2];

// ---------------- f32x2 helpers ----------------
__device__ __forceinline__ unsigned long long pk2(float x, float y){
    unsigned long long r; asm("mov.b64 %0, {%1,%2};" : "=l"(r) : "f"(x), "f"(y)); return r;
}
__device__ __forceinline__ void upk2(unsigned long long v, float& x, float& y){
    asm("mov.b64 {%0,%1}, %2;" : "=f"(x), "=f"(y) : "l"(v));
}
__device__ __forceinline__ void ffma2(unsigned long long& d, unsigned long long a, unsigned long long b){
    asm("fma.rn.f32x2 %0, %1, %2, %0;" : "+l"(d) : "l"(a), "l"(b));
}

// ---------------- smem / mma / ldmatrix / cp.async helpers ----------------
__device__ __forceinline__ uint32_t smem_u32(const void* p){
    uint32_t a;
    asm("{ .reg .u64 t; cvta.to.shared.u64 t, %1; cvt.u32.u64 %0, t; }" : "=r"(a) : "l"(p));
    return a;
}
__device__ __forceinline__ void cpa(uint32_t saddr, const void* g){
    asm volatile("cp.async.ca.shared.global [%0], [%1], 16;" :: "r"(saddr), "l"(g) : "memory");
}
#define CPA_COMMIT() asm volatile("cp.async.commit_group;" ::: "memory")
#define CPA_WAIT0()  asm volatile("cp.async.wait_group 0;" ::: "memory")
#define CPA_WAIT1()  asm volatile("cp.async.wait_group 1;" ::: "memory")

__device__ __forceinline__ void ldsm4(uint32_t a, uint32_t r[4]){
    asm volatile("ldmatrix.sync.aligned.m8n8.x4.shared.b16 {%0,%1,%2,%3}, [%4];"
      : "=r"(r[0]), "=r"(r[1]), "=r"(r[2]), "=r"(r[3]) : "r"(a));
}
__device__ __forceinline__ void ldsm4t(uint32_t a, uint32_t r[4]){
    asm volatile("ldmatrix.sync.aligned.m8n8.x4.trans.shared.b16 {%0,%1,%2,%3}, [%4];"
      : "=r"(r[0]), "=r"(r[1]), "=r"(r[2]), "=r"(r[3]) : "r"(a));
}
// fp16 mma
__device__ __forceinline__ void mmah(float c[4], const uint32_t a[4], const uint32_t b[2]){
    asm volatile("mma.sync.aligned.m16n8k16.row.col.f32.f16.f16.f32 "
      "{%0,%1,%2,%3}, {%4,%5,%6,%7}, {%8,%9}, {%0,%1,%2,%3};"
      : "+f"(c[0]), "+f"(c[1]), "+f"(c[2]), "+f"(c[3])
      : "r"(a[0]), "r"(a[1]), "r"(a[2]), "r"(a[3]), "r"(b[0]), "r"(b[1]));
}

// single fp16 pack of a float pair
__device__ __forceinline__ uint32_t packh2(float a, float b){
    __half2 h = __floats2half2_rn(a, b);
    return *reinterpret_cast<uint32_t*>(&h);
}

// smem byte offsets for k_attn (row stride 272B everywhere)
// Q: 128 rows.  K bufs: 64 rows x2.  V bufs: 64 rows x2.
#define QS   0
#define KB0  34816
#define KBSZ 17408
#define VB0  69632
#define VBSZ 17408
#define SM_ATTN 104448

// ============================================================================
// K1: Q/K/V projections (fp32 scalar), direct register->global fp16 stores.
// All three -> single fp16 [b][row][c].
// ============================================================================
__global__ __launch_bounds__(256) void k_qkv(const float* __restrict__ x,
                                             const float* __restrict__ Wq,
                                             const float* __restrict__ Wk,
                                             const float* __restrict__ Wv)
{
    extern __shared__ float sm[];
    float* Wt = sm;               // [c][130]
    float* Xs = sm + 128*130;     // [c][64]

    const int n0  = blockIdx.x * TN;
    const int b   = blockIdx.y;
    const int z   = blockIdx.z;
    const float* W = (z == 0) ? Wq : ((z == 1) ? Wk : Wv);

    const int tid = threadIdx.x;
    const int tx  = tid & 15;
    const int ty  = tid >> 4;

    for (int idx = tid; idx < 128*64; idx += 256){
        int o  = idx >> 6;
        int cq = (idx & 63) << 1;
        float2 w = *(const float2*)(W + o*128 + cq);
        Wt[ cq   *130 + o] = w.x;
        Wt[(cq+1)*130 + o] = w.y;
    }
    const float* xb = x + (size_t)b*CH*NSP + n0;
    for (int idx = tid; idx < 128*16; idx += 256){
        int c = idx >> 4, u = (idx & 15) << 2;
        *(float4*)(Xs + c*64 + u) = *(const float4*)(xb + c*NSP + u);
    }
    __syncthreads();

    unsigned long long acc[4][4];
    #pragma unroll
    for (int i = 0; i < 4; i++)
        #pragma unroll
        for (int j = 0; j < 4; j++) acc[i][j] = 0ull;

    #pragma unroll 4
    for (int c = 0; c < 128; c++){
        unsigned long long wv[4]; float xn[4];
        #pragma unroll
        for (int j = 0; j < 4; j++)
            wv[j] = *(const unsigned long long*)(Wt + c*130 + 2*tx + 32*j);
        #pragma unroll
        for (int i = 0; i < 4; i++) xn[i] = Xs[c*64 + ty + 16*i];
        #pragma unroll
        for (int i = 0; i < 4; i++){
            unsigned long long xd = pk2(xn[i], xn[i]);
            #pragma unroll
            for (int j = 0; j < 4; j++) ffma2(acc[i][j], wv[j], xd);
        }
    }

    // direct stores: thread holds (o, o+1) pair = one fp16x2 word at [n][cw]
    uint32_t* ok = (z == 0 ? g_Q16 : (z == 1 ? g_K16 : g_V16)) + ((size_t)b*NSP + n0)*64;
    #pragma unroll
    for (int i = 0; i < 4; i++)
        #pragma unroll
        for (int j = 0; j < 4; j++){
            float a, bv; upk2(acc[i][j], a, bv);
            int n = ty + 16*i, cw = tx + 16*j;
            ok[n*64 + cw] = packh2(a, bv);
        }
}

// ============================================================================
// K2: HMMA flash attention, online softmax (per-row running max), split-K.
// QK^T: fp16 1-pass Q16*K16.  PV^T: fp16 1-pass P16*V16 (V via ldsm.trans).
// TK=64 tiles, double-buffered K and V, one __syncthreads per tile.
// ============================================================================
__global__ __launch_bounds__(256) void k_attn()
{
    extern __shared__ char smc[];
    const uint32_t sb = smem_u32(smc);
    const int tid = threadIdx.x;
    const int wid = tid >> 5, lane = tid & 31;
    const int n0 = blockIdx.x * TQ;
    const int b  = blockIdx.y;
    const int sp = blockIdx.z;
    const int m_base = sp * (NSP/KSPLIT);

    const uint32_t* Q16 = g_Q16 + ((size_t)b*NSP + n0)*64;
    const uint32_t* K16 = g_K16 + (size_t)b*NSP*64;
    const uint32_t* V16 = g_V16 + (size_t)b*NSP*64;

    // ---- prologue group 0: Q + K(0) into K buf 0 ----
    for (int i = tid; i < 2048; i += 256){
        int r = i >> 4, q = i & 15;
        cpa(sb + QS + (uint32_t)r*272 + q*16, Q16 + r*64 + q*4);
    }
    for (int i = tid; i < 1024; i += 256){
        int r = i >> 4, q = i & 15;
        cpa(sb + KB0 + (uint32_t)r*272 + q*16, K16 + (size_t)(m_base + r)*64 + q*4);
    }
    CPA_COMMIT();
    // ---- prologue group 1: V(0) into V buf 0 ----
    for (int i = tid; i < 1024; i += 256){
        int r = i >> 4, q = i & 15;
        cpa(sb + VB0 + (uint32_t)r*272 + q*16, V16 + (size_t)(m_base + r)*64 + q*4);
    }
    CPA_COMMIT();
    CPA_WAIT1();            // Q + K(0) ready (V(0) may still fly)
    __syncthreads();

    // fragment address bases (row stride 272B everywhere)
    const int arow = 16*wid + (lane & 7) + ((lane >> 3) & 1)*8;
    const uint32_t aoff = (uint32_t)arow*272 + ((lane >> 4) & 1)*16;
    // K (non-trans): rows = n-dim via bit4; byte window = k-dim via bit3
    const int brow = (lane & 7) + ((lane >> 4) & 1)*8;
    const uint32_t boff = ((lane >> 3) & 1)*16;
    // V (trans): rows = k-dim via bit3; byte window = n-dim via bit4
    const int vrow = (lane & 7) + ((lane >> 3) & 1)*8;
    const uint32_t voff = ((lane >> 4) & 1)*16;

    // ---- cache Q A-fragments for the whole kernel ----
    uint32_t qf[8][4];
    #pragma unroll
    for (int k = 0; k < 8; k++) ldsm4(sb + QS + aoff + k*32, qf[k]);

    float oacc[16][4];
    #pragma unroll
    for (int i = 0; i < 16; i++)
        #pragma unroll
        for (int j = 0; j < 4; j++) oacc[i][j] = 0.f;
    float lsum0 = 0.f, lsum1 = 0.f;
    float mrow0 = -CUDART_INF_F, mrow1 = -CUDART_INF_F;

    for (int t = 0; t < NT2; t++){
        const uint32_t kb = sb + KB0 + (uint32_t)(t & 1)*KBSZ;
        const uint32_t vb = sb + VB0 + (uint32_t)(t & 1)*VBSZ;

        // tile barrier; confirm K(t) landed (pending <= {V(t)})
        __syncthreads();
        CPA_WAIT1();

        // earliest possible K(t+1) prefetch (writes other K buf)
        if (t + 1 < NT2){
            const int m1 = m_base + (t + 1)*TKK;
            const uint32_t kn = sb + KB0 + (uint32_t)((t + 1) & 1)*KBSZ;
            for (int i = tid; i < 1024; i += 256){
                int r = i >> 4, q = i & 15;
                cpa(kn + (uint32_t)r*272 + q*16, K16 + (size_t)(m1 + r)*64 + q*4);
            }
            CPA_COMMIT();
        }

        // ---- S = Q K^T : fp16, 1 pass, B loaded once per (k,jj) ----
        float sacc[8][4];
        #pragma unroll
        for (int i = 0; i < 8; i++)
            #pragma unroll
            for (int j = 0; j < 4; j++) sacc[i][j] = 0.f;

        #pragma unroll
        for (int k = 0; k < 8; k++){
            #pragma unroll
            for (int jj = 0; jj < 4; jj++){
                uint32_t bh[4];
                uint32_t ro = (uint32_t)(16*jj + brow)*272 + boff + k*32;
                ldsm4(kb + ro, bh);
                mmah(sacc[2*jj],     qf[k], bh);
                mmah(sacc[2*jj + 1], qf[k], bh + 2);
            }
        }

        // ---- online row max over this tile (rows g and g+8 of the quad) ----
        float tm0 = sacc[0][0], tm1 = sacc[0][2];
        #pragma unroll
        for (int j = 0; j < 8; j++){
            tm0 = fmaxf(tm0, fmaxf(sacc[j][0], sacc[j][1]));
            tm1 = fmaxf(tm1, fmaxf(sacc[j][2], sacc[j][3]));
        }
        #pragma unroll
        for (int d = 1; d < 4; d <<= 1){
            tm0 = fmaxf(tm0, __shfl_xor_sync(0xffffffffu, tm0, d));
            tm1 = fmaxf(tm1, __shfl_xor_sync(0xffffffffu, tm1, d));
        }
        float mn0 = fmaxf(mrow0, tm0), mn1 = fmaxf(mrow1, tm1);
        float sc0 = __expf(mrow0 - mn0), sc1 = __expf(mrow1 - mn1);
        mrow0 = mn0; mrow1 = mn1;
        if (!__all_sync(0xffffffffu, (sc0 == 1.0f) && (sc1 == 1.0f))){
            #pragma unroll
            for (int i = 0; i < 16; i++){
                oacc[i][0] *= sc0; oacc[i][1] *= sc0;
                oacc[i][2] *= sc1; oacc[i][3] *= sc1;
            }
            lsum0 *= sc0; lsum1 *= sc1;
        }

        // ---- P = exp(S - m_row); pack into SINGLE fp16 A-fragments ----
        uint32_t pf[4][4];
        #pragma unroll
        for (int j = 0; j < 8; j++){
            float p0 = __expf(sacc[j][0] - mn0);
            float p1 = __expf(sacc[j][1] - mn0);
            float p2 = __expf(sacc[j][2] - mn1);
            float p3 = __expf(sacc[j][3] - mn1);
            lsum0 += p0 + p1; lsum1 += p2 + p3;
            int jk = j >> 1, hv = (j & 1) << 1;
            pf[jk][hv]     = packh2(p0, p1);
            pf[jk][hv + 1] = packh2(p2, p3);
        }

        // V(t) ready?  pending: {V(t), K(t+1)} -> wait 1;  last tile: wait 0
        if (t + 1 < NT2) { CPA_WAIT1(); } else { CPA_WAIT0(); }

        // earliest possible V(t+1) prefetch
        if (t + 1 < NT2){
            const int m1 = m_base + (t + 1)*TKK;
            const uint32_t vn = sb + VB0 + (uint32_t)((t + 1) & 1)*VBSZ;
            for (int i = tid; i < 1024; i += 256){
                int r = i >> 4, q = i & 15;
                cpa(vn + (uint32_t)r*272 + q*16, V16 + (size_t)(m1 + r)*64 + q*4);
            }
            CPA_COMMIT();
        }

        // ---- O += P V^T : fp16 1 pass, V [m][c] via ldsm.trans ----
        #pragma unroll
        for (int k = 0; k < 4; k++){
            #pragma unroll
            for (int jj = 0; jj < 8; jj++){
                uint32_t bh[4];
                uint32_t ro = (uint32_t)(16*k + vrow)*272 + voff + jj*32;
                ldsm4t(vb + ro, bh);
                mmah(oacc[2*jj],     pf[k], bh);
                mmah(oacc[2*jj + 1], pf[k], bh + 2);
            }
        }
    }

    // ---- epilogue: l and m per row, unnormalized (max-relative) O out ----
    #pragma unroll
    for (int d = 1; d < 4; d <<= 1){
        lsum0 += __shfl_xor_sync(0xffffffffu, lsum0, d);
        lsum1 += __shfl_xor_sync(0xffffffffu, lsum1, d);
    }
    const int g = lane >> 2, q = lane & 3;
    const int row = 16*wid + g;
    if (q == 0){
        size_t lb = ((size_t)sp*BATCH + b)*NSP + n0;
        g_lp[lb + row]     = lsum0;
        g_lp[lb + row + 8] = lsum1;
        g_mx[lb + row]     = mrow0;
        g_mx[lb + row + 8] = mrow1;
    }
    float* Ob = g_Op + (((size_t)sp*BATCH + b)*NSP + n0)*CH;
    #pragma unroll
    for (int tt = 0; tt < 16; tt++){
        int c = 8*tt + 2*q;
        *(float2*)(Ob + (size_t)row*CH + c)       = make_float2(oacc[tt][0], oacc[tt][1]);
        *(float2*)(Ob + (size_t)(row + 8)*CH + c) = make_float2(oacc[tt][2], oacc[tt][3]);
    }
}

// ============================================================================
// K3: combine splits (m/l merge), y = x + Wo @ h, per-(b,group) partials.
// ============================================================================
__global__ __launch_bounds__(256) void k_proj(const float* __restrict__ x,
                                              const float* __restrict__ Wo)
{
    extern __shared__ float sm[];
    __shared__ float w0S[64], w1S[64];
    float* Wt = sm;               // [c][130]
    float* HS = sm + 128*130;     // [n][129] compute; [o][65] staging

    const int n0 = blockIdx.x * TN;
    const int b  = blockIdx.y;
    const int tid = threadIdx.x;
    const int tx  = tid & 15;
    const int ty  = tid >> 4;

    if (tid < 64){
        size_t i0 = ((size_t)0*BATCH + b)*NSP + n0 + tid;
        size_t i1 = ((size_t)1*BATCH + b)*NSP + n0 + tid;
        float l0 = g_lp[i0], l1 = g_lp[i1];
        float m0 = g_mx[i0], m1 = g_mx[i1];
        float M  = fmaxf(m0, m1);
        float e0 = __expf(m0 - M), e1 = __expf(m1 - M);
        float rl = 1.0f / (l0*e0 + l1*e1);
        w0S[tid] = e0 * rl;
        w1S[tid] = e1 * rl;
    }
    for (int idx = tid; idx < 128*64; idx += 256){
        int o  = idx >> 6;
        int cq = (idx & 63) << 1;
        float2 w = *(const float2*)(Wo + o*128 + cq);
        Wt[ cq   *130 + o] = w.x;
        Wt[(cq+1)*130 + o] = w.y;
    }
    __syncthreads();

    const float* O0 = g_Op + (((size_t)0*BATCH + b)*NSP + n0)*CH;
    const float* O1 = g_Op + (((size_t)1*BATCH + b)*NSP + n0)*CH;
    for (int idx = tid; idx < 64*128; idx += 256){
        int n = idx >> 7, c = idx & 127;
        HS[n*129 + c] = O0[idx]*w0S[n] + O1[idx]*w1S[n];
    }
    __syncthreads();

    unsigned long long acc[4][4];
    #pragma unroll
    for (int i = 0; i < 4; i++)
        #pragma unroll
        for (int j = 0; j < 4; j++) acc[i][j] = 0ull;

    #pragma unroll 4
    for (int c = 0; c < 128; c++){
        unsigned long long wv[4]; float hv[4];
        #pragma unroll
        for (int j = 0; j < 4; j++)
            wv[j] = *(const unsigned long long*)(Wt + c*130 + 2*tx + 32*j);
        #pragma unroll
        for (int i = 0; i < 4; i++) hv[i] = HS[(ty + 16*i)*129 + c];
        #pragma unroll
        for (int i = 0; i < 4; i++){
            unsigned long long hd = pk2(hv[i], hv[i]);
            #pragma unroll
            for (int j = 0; j < 4; j++) ffma2(acc[i][j], wv[j], hd);
        }
    }
    __syncthreads();

    float* St = HS;  // [o][65]
    #pragma unroll
    for (int i = 0; i < 4; i++)
        #pragma unroll
        for (int j = 0; j < 4; j++){
            float a, bv; upk2(acc[i][j], a, bv);
            int o = 2*tx + 32*j, n = ty + 16*i;
            St[ o   *65 + n] = a;
            St[(o+1)*65 + n] = bv;
        }
    __syncthreads();

    const float* xb = x   + (size_t)b*CH*NSP + n0;
    float*       yb = g_Y + (size_t)b*CH*NSP + n0;
    const int w = tid >> 5, lane = tid & 31;
    float s1 = 0.f, s2 = 0.f;
    for (int k = 0; k < 32; k++){
        int e = w*1024 + k*32 + lane;
        int o = e >> 6, n = e & 63;
        float val = xb[o*NSP + n] + St[o*65 + n];
        yb[o*NSP + n] = val;
        s1 += val; s2 += val*val;
    }
    #pragma unroll
    for (int d = 16; d >= 1; d >>= 1){
        s1 += __shfl_xor_sync(0xffffffffu, s1, d);
        s2 += __shfl_xor_sync(0xffffffffu, s2, d);
    }
    if (lane == 0){
        float* p = g_part + ((size_t)(b*64 + blockIdx.x)*GROUPS + w)*2;
        p[0] = s1; p[1] = s2;
    }
}

// K4: GroupNorm + affine + SiLU, with fused (redundant, deterministic)
// per-block reduction of the 64 partial sums for this block's group.
__global__ __launch_bounds__(256) void k_norm(const float* __restrict__ gamma,
                                              const float* __restrict__ beta,
                                              float* __restrict__ out)
{
    __shared__ float sh_mean, sh_inv;
    const int tid = threadIdx.x;
    const int e0 = blockIdx.x << 10;        // 1024 elems per block
    const int b = e0 >> 19;
    const int c = (e0 >> 12) & 127;
    const int g = c >> 4;

    if (tid < 32){
        const float* p = g_part + ((size_t)(b*64)*GROUPS + g)*2;
        float s1 = p[(size_t)tid*GROUPS*2]     + p[(size_t)(tid+32)*GROUPS*2];
        float s2 = p[(size_t)tid*GROUPS*2 + 1] + p[(size_t)(tid+32)*GROUPS*2 + 1];
        #pragma unroll
        for (int d = 16; d >= 1; d >>= 1){
            s1 += __shfl_xor_sync(0xffffffffu, s1, d);
            s2 += __shfl_xor_sync(0xffffffffu, s2, d);
        }
        if (tid == 0){
            const float icnt = 1.0f / 65536.0f;
            float mean = s1 * icnt;
            float var  = s2 * icnt - mean*mean;
            sh_mean = mean;
            sh_inv  = rsqrtf(var + EPSV);
        }
    }
    __syncthreads();

    const float mean = sh_mean, inv = sh_inv;
    const float ga = gamma[c], be = beta[c];
    const int e = e0 + tid*4;
    float4 y = *(const float4*)(g_Y + e);
    float4 r;
    float t = (y.x - mean)*inv*ga + be; r.x = t / (1.0f + __expf(-t));
    t = (y.y - mean)*inv*ga + be;       r.y = t / (1.0f + __expf(-t));
    t = (y.z - mean)*inv*ga + be;       r.z = t / (1.0f + __expf(-t));
    t = (y.w - mean)*inv*ga + be;       r.w = t / (1.0f + __expf(-t));
    *(float4*)(out + e) = r;
}

// ============================================================================
extern "C" void kernel_launch(void* const* d_in, const int* in_sizes, int n_in,
                              void* d_out, int out_size)
{
    const float* x     = (const float*)d_in[0];
    const float* Wq    = (const float*)d_in[1];
    const float* Wk    = (const float*)d_in[2];
    const float* Wv    = (const float*)d_in[3];
    const float* Wo    = (const float*)d_in[4];
    const float* gamma = (const float*)d_in[5];
    const float* beta  = (const float*)d_in[6];
    float* out = (float*)d_out;

    const int SM1 = (128*130 + 128*64) * 4;
    const int SM3 = (128*130 + 128*65) * 4;

    cudaFuncSetAttribute(k_qkv,  cudaFuncAttributeMaxDynamicSharedMemorySize, SM1);
    cudaFuncSetAttribute(k_attn, cudaFuncAttributeMaxDynamicSharedMemorySize, SM_ATTN);
    cudaFuncSetAttribute(k_proj, cudaFuncAttributeMaxDynamicSharedMemorySize, SM3);

    k_qkv <<<dim3(NSP/TN, BATCH, 3),      256, SM1>>>(x, Wq, Wk, Wv);
    k_attn<<<dim3(NSP/TQ, BATCH, KSPLIT), 256, SM_ATTN>>>();
    k_proj<<<dim3(NSP/TN, BATCH),         256, SM3>>>(x, Wo);
    k_norm<<<(BATCH*CH*NSP)/(4*256), 256>>>(gamma, beta, out);
}